// round 4
// baseline (speedup 1.0000x reference)
#include <cuda_runtime.h>
#include <cuda_bf16.h>
#include <math.h>
#include <cstdint>

#define Bb 4
#define Tn 1024
#define Cc 1024
#define Hh 16
#define Dd 64
#define NELEM ((size_t)Bb * Tn * Cc)   // 4M

// ---------------- scratch (device globals) ----------------
__device__ float g_att[(size_t)Bb * Hh * Tn * Tn];    // fp32 scores (causal blocks)
__device__ __nv_bfloat16 g_ah[(size_t)Bb * Hh * Tn * Tn];  // mixed att hi (zero-padded diag)
__device__ __nv_bfloat16 g_al[(size_t)Bb * Hh * Tn * Tn];  // mixed att lo

__device__ __nv_bfloat16 g_xs_h[NELEM];               // time-shifted input hi/lo
__device__ __nv_bfloat16 g_xs_l[NELEM];
__device__ __nv_bfloat16 g_y_h[NELEM];                // AV output [B,T,C] hi/lo
__device__ __nv_bfloat16 g_y_l[NELEM];
__device__ __nv_bfloat16 g_wh[4 * (size_t)Cc * Cc];   // weights q,k,v,p hi
__device__ __nv_bfloat16 g_wl[4 * (size_t)Cc * Cc];   // weights q,k,v,p lo

__device__ __nv_bfloat16 g_qh[(size_t)Bb * Hh * Tn * Dd];  // [bh][t][d]
__device__ __nv_bfloat16 g_ql[(size_t)Bb * Hh * Tn * Dd];
__device__ __nv_bfloat16 g_kh[(size_t)Bb * Hh * Tn * Dd];
__device__ __nv_bfloat16 g_kl[(size_t)Bb * Hh * Tn * Dd];
__device__ __nv_bfloat16 g_vh[(size_t)Bb * Hh * Tn * Dd];
__device__ __nv_bfloat16 g_vl[(size_t)Bb * Hh * Tn * Dd];

// ================= helpers =================
__device__ __forceinline__ uint32_t smem_to_u32(const void* p) {
    uint32_t a;
    asm("{ .reg .u64 t; cvta.to.shared.u64 t, %1; cvt.u32.u64 %0, t; }" : "=r"(a) : "l"(p));
    return a;
}
#define CP16(dst, src) \
    asm volatile("cp.async.cg.shared.global [%0], [%1], 16;" :: "r"(dst), "l"(src) : "memory")
#define CP_COMMIT() asm volatile("cp.async.commit_group;" ::: "memory")
#define CP_WAIT0() asm volatile("cp.async.wait_group 0;" ::: "memory")
#define CP_WAIT1() asm volatile("cp.async.wait_group 1;" ::: "memory")

__device__ __forceinline__ void ldsm4(uint32_t* r, uint32_t addr) {
    asm volatile("ldmatrix.sync.aligned.m8n8.x4.shared.b16 {%0,%1,%2,%3}, [%4];"
                 : "=r"(r[0]), "=r"(r[1]), "=r"(r[2]), "=r"(r[3]) : "r"(addr));
}
__device__ __forceinline__ void ldsm2(uint32_t* r, uint32_t addr) {
    asm volatile("ldmatrix.sync.aligned.m8n8.x2.shared.b16 {%0,%1}, [%2];"
                 : "=r"(r[0]), "=r"(r[1]) : "r"(addr));
}
__device__ __forceinline__ void ldsm2t(uint32_t* r, uint32_t addr) {
    asm volatile("ldmatrix.sync.aligned.m8n8.x2.trans.shared.b16 {%0,%1}, [%2];"
                 : "=r"(r[0]), "=r"(r[1]) : "r"(addr));
}
__device__ __forceinline__ void mma16816(float* c, const uint32_t* a, const uint32_t* b) {
    asm volatile("mma.sync.aligned.m16n8k16.row.col.f32.bf16.bf16.f32 "
                 "{%0,%1,%2,%3}, {%4,%5,%6,%7}, {%8,%9}, {%0,%1,%2,%3};"
                 : "+f"(c[0]), "+f"(c[1]), "+f"(c[2]), "+f"(c[3])
                 : "r"(a[0]), "r"(a[1]), "r"(a[2]), "r"(a[3]), "r"(b[0]), "r"(b[1]));
}
__device__ __forceinline__ void split_store(__nv_bfloat16* ph, __nv_bfloat16* pl, size_t idx, float v) {
    __nv_bfloat16 h = __float2bfloat16_rn(v);
    ph[idx] = h;
    pl[idx] = __float2bfloat16_rn(v - __bfloat162float(h));
}

// ---------------- 1) time shift -> bf16 hi/lo ----------------
__global__ __launch_bounds__(256) void timeshift_kernel(const float* __restrict__ x) {
    int idx = blockIdx.x * blockDim.x + threadIdx.x;
    int c = idx & (Cc - 1);
    int t = (idx >> 10) & (Tn - 1);
    int b = idx >> 20;
    float val;
    if (c < Cc / 2) {
        val = (t == 0) ? 0.f : x[((size_t)b * Tn + (t - 1)) * Cc + c];
    } else {
        val = x[((size_t)b * Tn + t) * Cc + c];
    }
    split_store(g_xs_h, g_xs_l, idx, val);
}

// ---------------- 1b) weight conversion -> bf16 hi/lo ----------------
__global__ __launch_bounds__(256) void convert_w_kernel(const float* __restrict__ Wq,
                                                        const float* __restrict__ Wk,
                                                        const float* __restrict__ Wv,
                                                        const float* __restrict__ Wp) {
    size_t idx = (size_t)blockIdx.x * blockDim.x + threadIdx.x;
    int which = (int)(idx >> 20);
    size_t off = idx & ((size_t)Cc * Cc - 1);
    const float* W = (which == 0) ? Wq : (which == 1) ? Wk : (which == 2) ? Wv : Wp;
    split_store(g_wh, g_wl, idx, W[off]);
}

// ================= 2/7) bf16-split mma.sync projection GEMM =================
#define STAGE_BYTES 32768
#define PROJ_SMEM (2 * STAGE_BYTES)

__global__ __launch_bounds__(256) void proj_gemm_mma(const float* __restrict__ bias,
                                                     float* __restrict__ outflat, int which) {
    extern __shared__ char smem[];
    uint32_t sbase = smem_to_u32(smem);
    const __nv_bfloat16* gAh = (which == 3) ? g_y_h : g_xs_h;
    const __nv_bfloat16* gAl = (which == 3) ? g_y_l : g_xs_l;
    const __nv_bfloat16* gWh = g_wh + (size_t)which * Cc * Cc;
    const __nv_bfloat16* gWl = g_wl + (size_t)which * Cc * Cc;

    int tid = threadIdx.x, lane = tid & 31, wid = tid >> 5;
    int warp_m = wid & 1, warp_n = wid >> 1;
    int m0 = blockIdx.y * 128, n0 = blockIdx.x * 128;

    int rtid = tid >> 2;
    int ctid = tid & 3;

    int a_row_off = (lane & 7) + ((lane >> 3) & 1) * 8;
    int a_chunk = lane >> 4;
    int b_row_off = lane & 7;
    int b_chunk = (lane >> 3) & 1;

    uint32_t aBase[4], aSw[4], bBase[4], bSw[4];
#pragma unroll
    for (int mi = 0; mi < 4; mi++) {
        int r = warp_m * 64 + mi * 16 + a_row_off;
        aBase[mi] = (uint32_t)(r * 64);
        aSw[mi] = (uint32_t)((r >> 1) & 3);
    }
#pragma unroll
    for (int ni = 0; ni < 4; ni++) {
        int r = warp_n * 32 + ni * 8 + b_row_off;
        bBase[ni] = (uint32_t)(r * 64);
        bSw[ni] = (uint32_t)((r >> 1) & 3);
    }

    float acc[4][4][4];
#pragma unroll
    for (int mi = 0; mi < 4; mi++)
#pragma unroll
        for (int ni = 0; ni < 4; ni++)
#pragma unroll
            for (int j = 0; j < 4; j++) acc[mi][ni][j] = 0.f;

    auto issue = [&](int chunk, int stage) {
        int k0 = chunk * 32;
        uint32_t sb = sbase + (uint32_t)stage * STAGE_BYTES;
#pragma unroll
        for (int j = 0; j < 2; j++) {
            int row = rtid + j * 64;
            uint32_t dof = (uint32_t)(row * 64 + ((ctid ^ ((row >> 1) & 3)) << 4));
            size_t ga = (size_t)(m0 + row) * Cc + k0 + ctid * 8;
            size_t gw = (size_t)(n0 + row) * Cc + k0 + ctid * 8;
            CP16(sb + dof,         gAh + ga);
            CP16(sb + 8192 + dof,  gAl + ga);
            CP16(sb + 16384 + dof, gWh + gw);
            CP16(sb + 24576 + dof, gWl + gw);
        }
    };

    auto compute = [&](int stage) {
        uint32_t sb = sbase + (uint32_t)stage * STAGE_BYTES;
#pragma unroll
        for (int ks = 0; ks < 2; ks++) {
            uint32_t aH[4][4], aL[4][4], bH[4][2], bL[4][2];
#pragma unroll
            for (int mi = 0; mi < 4; mi++) {
                uint32_t off = aBase[mi] + ((((uint32_t)(ks * 2) + a_chunk) ^ aSw[mi]) << 4);
                ldsm4(aH[mi], sb + off);
                ldsm4(aL[mi], sb + 8192 + off);
            }
#pragma unroll
            for (int ni = 0; ni < 4; ni++) {
                uint32_t off = bBase[ni] + ((((uint32_t)(ks * 2) + b_chunk) ^ bSw[ni]) << 4);
                ldsm2(bH[ni], sb + 16384 + off);
                ldsm2(bL[ni], sb + 24576 + off);
            }
#pragma unroll
            for (int mi = 0; mi < 4; mi++)
#pragma unroll
                for (int ni = 0; ni < 4; ni++) {
                    mma16816(acc[mi][ni], aH[mi], bH[ni]);
                    mma16816(acc[mi][ni], aH[mi], bL[ni]);
                    mma16816(acc[mi][ni], aL[mi], bH[ni]);
                }
        }
    };

    const int NCH = Cc / 32;
    issue(0, 0);
    CP_COMMIT();
#pragma unroll 1
    for (int c = 0; c < NCH; c++) {
        if (c + 1 < NCH) {
            issue(c + 1, (c + 1) & 1);
            CP_COMMIT();
            CP_WAIT1();
        } else {
            CP_WAIT0();
        }
        __syncthreads();
        compute(c & 1);
        __syncthreads();
    }

    // epilogue
    int r4 = lane >> 2;
    int cp2 = (lane & 3) * 2;
    __nv_bfloat16* ph = (which == 0) ? g_qh : (which == 1) ? g_kh : g_vh;
    __nv_bfloat16* pl = (which == 0) ? g_ql : (which == 1) ? g_kl : g_vl;
#pragma unroll
    for (int ni = 0; ni < 4; ni++) {
        int n = n0 + warp_n * 32 + ni * 8 + cp2;
        float b0 = bias[n], b1 = bias[n + 1];
#pragma unroll
        for (int mi = 0; mi < 4; mi++) {
            int mA = m0 + warp_m * 64 + mi * 16 + r4;
            float v00 = acc[mi][ni][0] + b0, v01 = acc[mi][ni][1] + b1;
            float v10 = acc[mi][ni][2] + b0, v11 = acc[mi][ni][3] + b1;
            if (which == 3) {
                *reinterpret_cast<float2*>(&outflat[(size_t)mA * Cc + n]) = make_float2(v00, v01);
                *reinterpret_cast<float2*>(&outflat[(size_t)(mA + 8) * Cc + n]) = make_float2(v10, v11);
            } else {
                int h = n >> 6, d = n & 63;
                int b_ = mA >> 10, t = mA & 1023;
                size_t i0 = (((size_t)(b_ * Hh + h)) * Tn + t) * Dd + d;
                split_store(ph, pl, i0,     v00);
                split_store(ph, pl, i0 + 1, v01);
                int m2 = mA + 8;
                int b2 = m2 >> 10, t2 = m2 & 1023;
                size_t i1 = (((size_t)(b2 * Hh + h)) * Tn + t2) * Dd + d;
                split_store(ph, pl, i1,     v10);
                split_store(ph, pl, i1 + 1, v11);
            }
        }
    }
}

// ================= 3) scores via bf16-split MMA: S = QK^T / 8 =================
// CTA: 128 thr (4 warps, 2x2 warp grid, warp tile 32x32), tile 64x64, K=64.
__global__ __launch_bounds__(128) void scores_mma() {
    int sblk = blockIdx.x, tblk = blockIdx.y, bh = blockIdx.z;
    if (sblk > tblk) return;
    __shared__ char smem[4 * 8192];   // Qh Ql Kh Kl (64 rows x 128B each)
    uint32_t sb = smem_to_u32(smem);

    int tid = threadIdx.x, lane = tid & 31, wid = tid >> 5;
    int warp_m = wid & 1, warp_n = wid >> 1;
    int t0 = tblk * 64, s0 = sblk * 64;

    const __nv_bfloat16* srcs[4] = {
        g_qh + ((size_t)bh * Tn + t0) * Dd,
        g_ql + ((size_t)bh * Tn + t0) * Dd,
        g_kh + ((size_t)bh * Tn + s0) * Dd,
        g_kl + ((size_t)bh * Tn + s0) * Dd };
#pragma unroll
    for (int a = 0; a < 4; a++) {
        const __nv_bfloat16* s = srcs[a];
        for (int i = tid; i < 512; i += 128) {
            int row = i >> 3, ch = i & 7;
            uint32_t off = (uint32_t)(row * 128 + ((ch ^ (row & 7)) << 4));
            *reinterpret_cast<uint4*>(smem + a * 8192 + off) =
                *reinterpret_cast<const uint4*>(s + row * 64 + ch * 8);
        }
    }
    __syncthreads();

    int a_row = warp_m * 32 + ((lane >> 3) & 1) * 8 + (lane & 7);
    int a_ch  = lane >> 4;
    int b_row = warp_n * 32 + (lane & 7);
    int b_ch  = (lane >> 3) & 1;

    float acc[2][4][4];
#pragma unroll
    for (int mi = 0; mi < 2; mi++)
#pragma unroll
        for (int ni = 0; ni < 4; ni++)
#pragma unroll
            for (int j = 0; j < 4; j++) acc[mi][ni][j] = 0.f;

#pragma unroll
    for (int ks = 0; ks < 4; ks++) {
        uint32_t aH[2][4], aL[2][4], bH[4][2], bL[4][2];
#pragma unroll
        for (int mi = 0; mi < 2; mi++) {
            int r = a_row + mi * 16;
            uint32_t off = (uint32_t)(r * 128 + (((ks * 2 + a_ch) ^ (r & 7)) << 4));
            ldsm4(aH[mi], sb + off);
            ldsm4(aL[mi], sb + 8192 + off);
        }
#pragma unroll
        for (int ni = 0; ni < 4; ni++) {
            int r = b_row + ni * 8;
            uint32_t off = (uint32_t)(r * 128 + (((ks * 2 + b_ch) ^ (r & 7)) << 4));
            ldsm2(bH[ni], sb + 16384 + off);
            ldsm2(bL[ni], sb + 24576 + off);
        }
#pragma unroll
        for (int mi = 0; mi < 2; mi++)
#pragma unroll
            for (int ni = 0; ni < 4; ni++) {
                mma16816(acc[mi][ni], aH[mi], bH[ni]);
                mma16816(acc[mi][ni], aH[mi], bL[ni]);
                mma16816(acc[mi][ni], aL[mi], bH[ni]);
            }
    }

    float* S = g_att + (size_t)bh * Tn * Tn;
    int r4 = lane >> 2, cp2 = (lane & 3) * 2;
#pragma unroll
    for (int mi = 0; mi < 2; mi++) {
        int t = t0 + warp_m * 32 + mi * 16 + r4;
#pragma unroll
        for (int ni = 0; ni < 4; ni++) {
            int s = s0 + warp_n * 32 + ni * 8 + cp2;
            *reinterpret_cast<float2*>(&S[(size_t)t * Tn + s]) =
                make_float2(acc[mi][ni][0] * 0.125f, acc[mi][ni][1] * 0.125f);
            *reinterpret_cast<float2*>(&S[(size_t)(t + 8) * Tn + s]) =
                make_float2(acc[mi][ni][2] * 0.125f, acc[mi][ni][3] * 0.125f);
        }
    }
}

// ================= 4+5) fused softmax * tw + head mix -> bf16 hi/lo =================
// CTA per (t, b): stages 16 head-rows in smem, writes mixed att (zero-padded to 64).
#define FUSED_SMEM (16 * 1024 * 4)
__global__ __launch_bounds__(256) void softmax_mix_kernel(const float* __restrict__ tw,
                                                          const float* __restrict__ Mx) {
    int t = blockIdx.x, b = blockIdx.y;
    extern __shared__ float smf[];   // [16][1024]
    __shared__ float red[8];
    __shared__ float Ms[256];
    int tid = threadIdx.x, lane = tid & 31, wid = tid >> 5;
    int L = t + 1;
    int L64 = (t + 64) & ~63;

    if (tid < 256) Ms[tid] = Mx[tid];

    for (int h = 0; h < Hh; h++) {
        const float* row = g_att + (((size_t)(b * Hh + h)) * Tn + t) * Tn;
        float* shr = smf + h * 1024;
        float m = -1e30f;
        for (int i = tid; i < L; i += 256) { float v = row[i]; shr[i] = v; m = fmaxf(m, v); }
#pragma unroll
        for (int o = 16; o; o >>= 1) m = fmaxf(m, __shfl_xor_sync(0xffffffffu, m, o));
        if (lane == 0) red[wid] = m;
        __syncthreads();
        m = red[0];
#pragma unroll
        for (int i = 1; i < 8; i++) m = fmaxf(m, red[i]);
        __syncthreads();

        float s = 0.f;
        for (int i = tid; i < L; i += 256) { float e = __expf(shr[i] - m); shr[i] = e; s += e; }
#pragma unroll
        for (int o = 16; o; o >>= 1) s += __shfl_xor_sync(0xffffffffu, s, o);
        if (lane == 0) red[wid] = s;
        __syncthreads();
        float ss = 0.f;
#pragma unroll
        for (int i = 0; i < 8; i++) ss += red[i];
        float inv = 1.0f / ss;
        __syncthreads();

        const float* twr = tw + (((size_t)h * Tn) + t) * Tn;
        for (int i = tid; i < L; i += 256) shr[i] = shr[i] * inv * twr[i];
        for (int i = L + tid - (L & 255) + (tid < (L & 255) ? 256 : 0); false;) {}  // (unused)
        for (int i = L + tid; i < L64; i += 256) shr[i] = 0.f;
    }
    __syncthreads();

    for (int i = tid; i < L64; i += 256) {
        float vals[16];
#pragma unroll
        for (int h = 0; h < Hh; h++) vals[h] = smf[h * 1024 + i];
#pragma unroll
        for (int o = 0; o < Hh; o++) {
            float a = 0.f;
#pragma unroll
            for (int h = 0; h < Hh; h++) a = fmaf(Ms[o * 16 + h], vals[h], a);
            size_t idx = (((size_t)(b * Hh + o)) * Tn + t) * Tn + i;
            __nv_bfloat16 hi = __float2bfloat16_rn(a);
            g_ah[idx] = hi;
            g_al[idx] = __float2bfloat16_rn(a - __bfloat162float(hi));
        }
    }
}

// ================= 6) AV via bf16-split MMA: y = attm @ V =================
// CTA: 128 thr, out tile 64(t) x 64(d), loop s in 64-chunks.
__global__ __launch_bounds__(128) void av_mma() {
    int tblk = blockIdx.x, bo = blockIdx.y;
    int b = bo >> 4, o = bo & 15;
    int t0 = tblk * 64;
    __shared__ char smem[4 * 8192];   // Ah Al Vh Vl
    uint32_t sb = smem_to_u32(smem);

    int tid = threadIdx.x, lane = tid & 31, wid = tid >> 5;
    int warp_m = wid & 1, warp_n = wid >> 1;

    int a_row = warp_m * 32 + ((lane >> 3) & 1) * 8 + (lane & 7);
    int a_ch  = lane >> 4;
    int v_lrow = ((lane >> 3) & 1) * 8 + (lane & 7);   // k-row within 16 (lanes 0..15)

    float acc[2][4][4];
#pragma unroll
    for (int mi = 0; mi < 2; mi++)
#pragma unroll
        for (int ni = 0; ni < 4; ni++)
#pragma unroll
            for (int j = 0; j < 4; j++) acc[mi][ni][j] = 0.f;

    const __nv_bfloat16* Ah = g_ah + ((size_t)bo * Tn + t0) * Tn;
    const __nv_bfloat16* Al = g_al + ((size_t)bo * Tn + t0) * Tn;
    const __nv_bfloat16* Vh = g_vh + (size_t)bo * Tn * Dd;
    const __nv_bfloat16* Vl = g_vl + (size_t)bo * Tn * Dd;

    int nStages = tblk + 1;
    for (int st = 0; st < nStages; st++) {
        int s0 = st * 64;
        __syncthreads();
        for (int i = tid; i < 512; i += 128) {
            int row = i >> 3, ch = i & 7;
            uint32_t off = (uint32_t)(row * 128 + ((ch ^ (row & 7)) << 4));
            *reinterpret_cast<uint4*>(smem + off) =
                *reinterpret_cast<const uint4*>(Ah + (size_t)row * Tn + s0 + ch * 8);
            *reinterpret_cast<uint4*>(smem + 8192 + off) =
                *reinterpret_cast<const uint4*>(Al + (size_t)row * Tn + s0 + ch * 8);
            *reinterpret_cast<uint4*>(smem + 16384 + off) =
                *reinterpret_cast<const uint4*>(Vh + (size_t)(s0 + row) * Dd + ch * 8);
            *reinterpret_cast<uint4*>(smem + 24576 + off) =
                *reinterpret_cast<const uint4*>(Vl + (size_t)(s0 + row) * Dd + ch * 8);
        }
        __syncthreads();

#pragma unroll
        for (int ks = 0; ks < 4; ks++) {
            uint32_t aH[2][4], aL[2][4], bH[4][2], bL[4][2];
#pragma unroll
            for (int mi = 0; mi < 2; mi++) {
                int r = a_row + mi * 16;
                uint32_t off = (uint32_t)(r * 128 + (((ks * 2 + a_ch) ^ (r & 7)) << 4));
                ldsm4(aH[mi], sb + off);
                ldsm4(aL[mi], sb + 8192 + off);
            }
            int vrow = ks * 16 + v_lrow;   // s-row within 64 (lanes 0..15 meaningful)
#pragma unroll
            for (int ni = 0; ni < 4; ni++) {
                int dch = warp_n * 4 + ni;   // 16B chunk along d
                uint32_t off = (uint32_t)(vrow * 128 + ((dch ^ (vrow & 7)) << 4));
                ldsm2t(bH[ni], sb + 16384 + off);
                ldsm2t(bL[ni], sb + 24576 + off);
            }
#pragma unroll
            for (int mi = 0; mi < 2; mi++)
#pragma unroll
                for (int ni = 0; ni < 4; ni++) {
                    mma16816(acc[mi][ni], aH[mi], bH[ni]);
                    mma16816(acc[mi][ni], aL[mi], bH[ni]);
                    mma16816(acc[mi][ni], aH[mi], bL[ni]);
                }
        }
    }

    int r4 = lane >> 2, cp2 = (lane & 3) * 2;
#pragma unroll
    for (int mi = 0; mi < 2; mi++) {
        int t = t0 + warp_m * 32 + mi * 16 + r4;
#pragma unroll
        for (int ni = 0; ni < 4; ni++) {
            int d = warp_n * 32 + ni * 8 + cp2;
            size_t i0 = ((size_t)(b * Tn + t)) * Cc + o * 64 + d;
            split_store(g_y_h, g_y_l, i0,     acc[mi][ni][0]);
            split_store(g_y_h, g_y_l, i0 + 1, acc[mi][ni][1]);
            size_t i1 = ((size_t)(b * Tn + t + 8)) * Cc + o * 64 + d;
            split_store(g_y_h, g_y_l, i1,     acc[mi][ni][2]);
            split_store(g_y_h, g_y_l, i1 + 1, acc[mi][ni][3]);
        }
    }
}

// ---------------- host launch ----------------
extern "C" void kernel_launch(void* const* d_in, const int* in_sizes, int n_in,
                              void* d_out, int out_size) {
    const float* x  = (const float*)d_in[0];
    const float* Wq = (const float*)d_in[1];
    const float* bq = (const float*)d_in[2];
    const float* Wk = (const float*)d_in[3];
    const float* bk = (const float*)d_in[4];
    const float* Wv = (const float*)d_in[5];
    const float* bv = (const float*)d_in[6];
    const float* tw = (const float*)d_in[7];
    const float* hm = (const float*)d_in[8];
    const float* Wp = (const float*)d_in[9];
    const float* bp = (const float*)d_in[10];
    float* out = (float*)d_out;

    static int smem_set = 0;
    if (!smem_set) {
        cudaFuncSetAttribute(proj_gemm_mma, cudaFuncAttributeMaxDynamicSharedMemorySize, PROJ_SMEM);
        cudaFuncSetAttribute(softmax_mix_kernel, cudaFuncAttributeMaxDynamicSharedMemorySize, FUSED_SMEM);
        smem_set = 1;
    }

    timeshift_kernel<<<(Bb * Tn * Cc) / 256, 256>>>(x);
    convert_w_kernel<<<(4 * Cc * Cc) / 256, 256>>>(Wq, Wk, Wv, Wp);

    dim3 gproj(Cc / 128, (Bb * Tn) / 128);
    proj_gemm_mma<<<gproj, 256, PROJ_SMEM>>>(bq, nullptr, 0);
    proj_gemm_mma<<<gproj, 256, PROJ_SMEM>>>(bk, nullptr, 1);
    proj_gemm_mma<<<gproj, 256, PROJ_SMEM>>>(bv, nullptr, 2);

    dim3 gs(Tn / 64, Tn / 64, Bb * Hh);
    scores_mma<<<gs, 128>>>();

    dim3 gsm(Tn, Bb);
    softmax_mix_kernel<<<gsm, 256, FUSED_SMEM>>>(tw, hm);

    dim3 gav(Tn / 64, Bb * Hh);
    av_mma<<<gav, 128>>>();

    proj_gemm_mma<<<gproj, 256, PROJ_SMEM>>>(bp, out, 3);
}

// round 5
// speedup vs baseline: 2.4149x; 2.4149x over previous
#include <cuda_runtime.h>
#include <cuda_bf16.h>
#include <math.h>
#include <cstdint>

#define Bb 4
#define Tn 1024
#define Cc 1024
#define Hh 16
#define Dd 64
#define NELEM ((size_t)Bb * Tn * Cc)   // 4M

// ---------------- scratch (device globals) ----------------
__device__ float g_att[(size_t)Bb * Hh * Tn * Tn];         // fp32 scores -> softmax (in place)
__device__ __nv_bfloat16 g_ah[(size_t)Bb * Hh * Tn * Tn];  // mixed att hi (causal-zeroed)
__device__ __nv_bfloat16 g_al[(size_t)Bb * Hh * Tn * Tn];  // mixed att lo

__device__ __nv_bfloat16 g_xs_h[NELEM];               // time-shifted input hi/lo
__device__ __nv_bfloat16 g_xs_l[NELEM];
__device__ __nv_bfloat16 g_y_h[NELEM];                // AV output [B,T,C] hi/lo
__device__ __nv_bfloat16 g_y_l[NELEM];
__device__ __nv_bfloat16 g_wh[4 * (size_t)Cc * Cc];   // weights q,k,v,p hi
__device__ __nv_bfloat16 g_wl[4 * (size_t)Cc * Cc];   // weights q,k,v,p lo

__device__ __nv_bfloat16 g_qh[(size_t)Bb * Hh * Tn * Dd];  // [bh][t][d]
__device__ __nv_bfloat16 g_ql[(size_t)Bb * Hh * Tn * Dd];
__device__ __nv_bfloat16 g_kh[(size_t)Bb * Hh * Tn * Dd];
__device__ __nv_bfloat16 g_kl[(size_t)Bb * Hh * Tn * Dd];
__device__ __nv_bfloat16 g_vh[(size_t)Bb * Hh * Tn * Dd];
__device__ __nv_bfloat16 g_vl[(size_t)Bb * Hh * Tn * Dd];

// ================= helpers =================
__device__ __forceinline__ uint32_t smem_to_u32(const void* p) {
    uint32_t a;
    asm("{ .reg .u64 t; cvta.to.shared.u64 t, %1; cvt.u32.u64 %0, t; }" : "=r"(a) : "l"(p));
    return a;
}
#define CP16(dst, src) \
    asm volatile("cp.async.cg.shared.global [%0], [%1], 16;" :: "r"(dst), "l"(src) : "memory")
#define CP_COMMIT() asm volatile("cp.async.commit_group;" ::: "memory")
#define CP_WAIT0() asm volatile("cp.async.wait_group 0;" ::: "memory")
#define CP_WAIT1() asm volatile("cp.async.wait_group 1;" ::: "memory")

__device__ __forceinline__ void ldsm4(uint32_t* r, uint32_t addr) {
    asm volatile("ldmatrix.sync.aligned.m8n8.x4.shared.b16 {%0,%1,%2,%3}, [%4];"
                 : "=r"(r[0]), "=r"(r[1]), "=r"(r[2]), "=r"(r[3]) : "r"(addr));
}
__device__ __forceinline__ void ldsm2(uint32_t* r, uint32_t addr) {
    asm volatile("ldmatrix.sync.aligned.m8n8.x2.shared.b16 {%0,%1}, [%2];"
                 : "=r"(r[0]), "=r"(r[1]) : "r"(addr));
}
__device__ __forceinline__ void ldsm2t(uint32_t* r, uint32_t addr) {
    asm volatile("ldmatrix.sync.aligned.m8n8.x2.trans.shared.b16 {%0,%1}, [%2];"
                 : "=r"(r[0]), "=r"(r[1]) : "r"(addr));
}
__device__ __forceinline__ void mma16816(float* c, const uint32_t* a, const uint32_t* b) {
    asm volatile("mma.sync.aligned.m16n8k16.row.col.f32.bf16.bf16.f32 "
                 "{%0,%1,%2,%3}, {%4,%5,%6,%7}, {%8,%9}, {%0,%1,%2,%3};"
                 : "+f"(c[0]), "+f"(c[1]), "+f"(c[2]), "+f"(c[3])
                 : "r"(a[0]), "r"(a[1]), "r"(a[2]), "r"(a[3]), "r"(b[0]), "r"(b[1]));
}
__device__ __forceinline__ void split_store(__nv_bfloat16* ph, __nv_bfloat16* pl, size_t idx, float v) {
    __nv_bfloat16 h = __float2bfloat16_rn(v);
    ph[idx] = h;
    pl[idx] = __float2bfloat16_rn(v - __bfloat162float(h));
}

// ---------------- 1) time shift -> bf16 hi/lo ----------------
__global__ __launch_bounds__(256) void timeshift_kernel(const float* __restrict__ x) {
    int idx = blockIdx.x * blockDim.x + threadIdx.x;
    int c = idx & (Cc - 1);
    int t = (idx >> 10) & (Tn - 1);
    int b = idx >> 20;
    float val;
    if (c < Cc / 2) {
        val = (t == 0) ? 0.f : x[((size_t)b * Tn + (t - 1)) * Cc + c];
    } else {
        val = x[((size_t)b * Tn + t) * Cc + c];
    }
    split_store(g_xs_h, g_xs_l, idx, val);
}

// ---------------- 1b) weight conversion -> bf16 hi/lo ----------------
__global__ __launch_bounds__(256) void convert_w_kernel(const float* __restrict__ Wq,
                                                        const float* __restrict__ Wk,
                                                        const float* __restrict__ Wv,
                                                        const float* __restrict__ Wp) {
    size_t idx = (size_t)blockIdx.x * blockDim.x + threadIdx.x;
    int which = (int)(idx >> 20);
    size_t off = idx & ((size_t)Cc * Cc - 1);
    const float* W = (which == 0) ? Wq : (which == 1) ? Wk : (which == 2) ? Wv : Wp;
    split_store(g_wh, g_wl, idx, W[off]);
}

// ================= 2/7) bf16-split mma.sync projection GEMM =================
#define STAGE_BYTES 32768
#define PROJ_SMEM (2 * STAGE_BYTES)

__global__ __launch_bounds__(256) void proj_gemm_mma(const float* __restrict__ bias,
                                                     float* __restrict__ outflat, int which) {
    extern __shared__ char smem[];
    uint32_t sbase = smem_to_u32(smem);
    const __nv_bfloat16* gAh = (which == 3) ? g_y_h : g_xs_h;
    const __nv_bfloat16* gAl = (which == 3) ? g_y_l : g_xs_l;
    const __nv_bfloat16* gWh = g_wh + (size_t)which * Cc * Cc;
    const __nv_bfloat16* gWl = g_wl + (size_t)which * Cc * Cc;

    int tid = threadIdx.x, lane = tid & 31, wid = tid >> 5;
    int warp_m = wid & 1, warp_n = wid >> 1;
    int m0 = blockIdx.y * 128, n0 = blockIdx.x * 128;

    int rtid = tid >> 2;
    int ctid = tid & 3;

    int a_row_off = (lane & 7) + ((lane >> 3) & 1) * 8;
    int a_chunk = lane >> 4;
    int b_row_off = lane & 7;
    int b_chunk = (lane >> 3) & 1;

    uint32_t aBase[4], aSw[4], bBase[4], bSw[4];
#pragma unroll
    for (int mi = 0; mi < 4; mi++) {
        int r = warp_m * 64 + mi * 16 + a_row_off;
        aBase[mi] = (uint32_t)(r * 64);
        aSw[mi] = (uint32_t)((r >> 1) & 3);
    }
#pragma unroll
    for (int ni = 0; ni < 4; ni++) {
        int r = warp_n * 32 + ni * 8 + b_row_off;
        bBase[ni] = (uint32_t)(r * 64);
        bSw[ni] = (uint32_t)((r >> 1) & 3);
    }

    float acc[4][4][4];
#pragma unroll
    for (int mi = 0; mi < 4; mi++)
#pragma unroll
        for (int ni = 0; ni < 4; ni++)
#pragma unroll
            for (int j = 0; j < 4; j++) acc[mi][ni][j] = 0.f;

    auto issue = [&](int chunk, int stage) {
        int k0 = chunk * 32;
        uint32_t sb = sbase + (uint32_t)stage * STAGE_BYTES;
#pragma unroll
        for (int j = 0; j < 2; j++) {
            int row = rtid + j * 64;
            uint32_t dof = (uint32_t)(row * 64 + ((ctid ^ ((row >> 1) & 3)) << 4));
            size_t ga = (size_t)(m0 + row) * Cc + k0 + ctid * 8;
            size_t gw = (size_t)(n0 + row) * Cc + k0 + ctid * 8;
            CP16(sb + dof,         gAh + ga);
            CP16(sb + 8192 + dof,  gAl + ga);
            CP16(sb + 16384 + dof, gWh + gw);
            CP16(sb + 24576 + dof, gWl + gw);
        }
    };

    auto compute = [&](int stage) {
        uint32_t sb = sbase + (uint32_t)stage * STAGE_BYTES;
#pragma unroll
        for (int ks = 0; ks < 2; ks++) {
            uint32_t aH[4][4], aL[4][4], bH[4][2], bL[4][2];
#pragma unroll
            for (int mi = 0; mi < 4; mi++) {
                uint32_t off = aBase[mi] + ((((uint32_t)(ks * 2) + a_chunk) ^ aSw[mi]) << 4);
                ldsm4(aH[mi], sb + off);
                ldsm4(aL[mi], sb + 8192 + off);
            }
#pragma unroll
            for (int ni = 0; ni < 4; ni++) {
                uint32_t off = bBase[ni] + ((((uint32_t)(ks * 2) + b_chunk) ^ bSw[ni]) << 4);
                ldsm2(bH[ni], sb + 16384 + off);
                ldsm2(bL[ni], sb + 24576 + off);
            }
#pragma unroll
            for (int mi = 0; mi < 4; mi++)
#pragma unroll
                for (int ni = 0; ni < 4; ni++) {
                    mma16816(acc[mi][ni], aH[mi], bH[ni]);
                    mma16816(acc[mi][ni], aH[mi], bL[ni]);
                    mma16816(acc[mi][ni], aL[mi], bH[ni]);
                }
        }
    };

    const int NCH = Cc / 32;
    issue(0, 0);
    CP_COMMIT();
#pragma unroll 1
    for (int c = 0; c < NCH; c++) {
        if (c + 1 < NCH) {
            issue(c + 1, (c + 1) & 1);
            CP_COMMIT();
            CP_WAIT1();
        } else {
            CP_WAIT0();
        }
        __syncthreads();
        compute(c & 1);
        __syncthreads();
    }

    // epilogue
    int r4 = lane >> 2;
    int cp2 = (lane & 3) * 2;
    __nv_bfloat16* ph = (which == 0) ? g_qh : (which == 1) ? g_kh : g_vh;
    __nv_bfloat16* pl = (which == 0) ? g_ql : (which == 1) ? g_kl : g_vl;
#pragma unroll
    for (int ni = 0; ni < 4; ni++) {
        int n = n0 + warp_n * 32 + ni * 8 + cp2;
        float b0 = bias[n], b1 = bias[n + 1];
#pragma unroll
        for (int mi = 0; mi < 4; mi++) {
            int mA = m0 + warp_m * 64 + mi * 16 + r4;
            float v00 = acc[mi][ni][0] + b0, v01 = acc[mi][ni][1] + b1;
            float v10 = acc[mi][ni][2] + b0, v11 = acc[mi][ni][3] + b1;
            if (which == 3) {
                *reinterpret_cast<float2*>(&outflat[(size_t)mA * Cc + n]) = make_float2(v00, v01);
                *reinterpret_cast<float2*>(&outflat[(size_t)(mA + 8) * Cc + n]) = make_float2(v10, v11);
            } else {
                int h = n >> 6, d = n & 63;
                int b_ = mA >> 10, t = mA & 1023;
                size_t i0 = (((size_t)(b_ * Hh + h)) * Tn + t) * Dd + d;
                split_store(ph, pl, i0,     v00);
                split_store(ph, pl, i0 + 1, v01);
                int m2 = mA + 8;
                int b2 = m2 >> 10, t2 = m2 & 1023;
                size_t i1 = (((size_t)(b2 * Hh + h)) * Tn + t2) * Dd + d;
                split_store(ph, pl, i1,     v10);
                split_store(ph, pl, i1 + 1, v11);
            }
        }
    }
}

// ================= 3) scores via bf16-split MMA: S = QK^T / 8 =================
__global__ __launch_bounds__(128) void scores_mma() {
    int sblk = blockIdx.x, tblk = blockIdx.y, bh = blockIdx.z;
    if (sblk > tblk) return;
    __shared__ char smem[4 * 8192];   // Qh Ql Kh Kl (64 rows x 128B each)
    uint32_t sb = smem_to_u32(smem);

    int tid = threadIdx.x, lane = tid & 31, wid = tid >> 5;
    int warp_m = wid & 1, warp_n = wid >> 1;
    int t0 = tblk * 64, s0 = sblk * 64;

    const __nv_bfloat16* srcs[4] = {
        g_qh + ((size_t)bh * Tn + t0) * Dd,
        g_ql + ((size_t)bh * Tn + t0) * Dd,
        g_kh + ((size_t)bh * Tn + s0) * Dd,
        g_kl + ((size_t)bh * Tn + s0) * Dd };
#pragma unroll
    for (int a = 0; a < 4; a++) {
        const __nv_bfloat16* s = srcs[a];
        for (int i = tid; i < 512; i += 128) {
            int row = i >> 3, ch = i & 7;
            uint32_t off = (uint32_t)(row * 128 + ((ch ^ (row & 7)) << 4));
            *reinterpret_cast<uint4*>(smem + a * 8192 + off) =
                *reinterpret_cast<const uint4*>(s + row * 64 + ch * 8);
        }
    }
    __syncthreads();

    int a_row = warp_m * 32 + ((lane >> 3) & 1) * 8 + (lane & 7);
    int a_ch  = lane >> 4;
    int b_row = warp_n * 32 + (lane & 7);
    int b_ch  = (lane >> 3) & 1;

    float acc[2][4][4];
#pragma unroll
    for (int mi = 0; mi < 2; mi++)
#pragma unroll
        for (int ni = 0; ni < 4; ni++)
#pragma unroll
            for (int j = 0; j < 4; j++) acc[mi][ni][j] = 0.f;

#pragma unroll
    for (int ks = 0; ks < 4; ks++) {
        uint32_t aH[2][4], aL[2][4], bH[4][2], bL[4][2];
#pragma unroll
        for (int mi = 0; mi < 2; mi++) {
            int r = a_row + mi * 16;
            uint32_t off = (uint32_t)(r * 128 + (((ks * 2 + a_ch) ^ (r & 7)) << 4));
            ldsm4(aH[mi], sb + off);
            ldsm4(aL[mi], sb + 8192 + off);
        }
#pragma unroll
        for (int ni = 0; ni < 4; ni++) {
            int r = b_row + ni * 8;
            uint32_t off = (uint32_t)(r * 128 + (((ks * 2 + b_ch) ^ (r & 7)) << 4));
            ldsm2(bH[ni], sb + 16384 + off);
            ldsm2(bL[ni], sb + 24576 + off);
        }
#pragma unroll
        for (int mi = 0; mi < 2; mi++)
#pragma unroll
            for (int ni = 0; ni < 4; ni++) {
                mma16816(acc[mi][ni], aH[mi], bH[ni]);
                mma16816(acc[mi][ni], aH[mi], bL[ni]);
                mma16816(acc[mi][ni], aL[mi], bH[ni]);
            }
    }

    float* S = g_att + (size_t)bh * Tn * Tn;
    int r4 = lane >> 2, cp2 = (lane & 3) * 2;
#pragma unroll
    for (int mi = 0; mi < 2; mi++) {
        int t = t0 + warp_m * 32 + mi * 16 + r4;
#pragma unroll
        for (int ni = 0; ni < 4; ni++) {
            int s = s0 + warp_n * 32 + ni * 8 + cp2;
            *reinterpret_cast<float2*>(&S[(size_t)t * Tn + s]) =
                make_float2(acc[mi][ni][0] * 0.125f, acc[mi][ni][1] * 0.125f);
            *reinterpret_cast<float2*>(&S[(size_t)(t + 8) * Tn + s]) =
                make_float2(acc[mi][ni][2] * 0.125f, acc[mi][ni][3] * 0.125f);
        }
    }
}

// ---------------- 4) row softmax over s<=t, then * time_weighting (in place, fp32) ----------------
__global__ __launch_bounds__(256) void softmax_tw_kernel(const float* __restrict__ tw) {
    int t = blockIdx.x;
    int bh = blockIdx.y;
    int h = bh & (Hh - 1);
    float* row = g_att + ((size_t)bh * Tn + t) * Tn;
    const float* twr = tw + ((size_t)h * Tn + t) * Tn;
    int n = t + 1;
    int tid = threadIdx.x;
    __shared__ float red[8];

    float m = -1e30f;
    for (int i = tid; i < n; i += 256) m = fmaxf(m, row[i]);
#pragma unroll
    for (int o = 16; o; o >>= 1) m = fmaxf(m, __shfl_xor_sync(0xffffffffu, m, o));
    if ((tid & 31) == 0) red[tid >> 5] = m;
    __syncthreads();
    float mm = red[0];
#pragma unroll
    for (int i = 1; i < 8; i++) mm = fmaxf(mm, red[i]);
    m = mm;
    __syncthreads();

    float s = 0.f;
    for (int i = tid; i < n; i += 256) {
        float e = __expf(row[i] - m);
        row[i] = e;
        s += e;
    }
#pragma unroll
    for (int o = 16; o; o >>= 1) s += __shfl_xor_sync(0xffffffffu, s, o);
    if ((tid & 31) == 0) red[tid >> 5] = s;
    __syncthreads();
    float ss = 0.f;
#pragma unroll
    for (int i = 0; i < 8; i++) ss += red[i];
    float inv = 1.0f / ss;

    for (int i = tid; i < n; i += 256) row[i] = row[i] * inv * twr[i];
}

// ---------------- 5) head mix -> bf16 hi/lo, causal-zeroed ----------------
__global__ __launch_bounds__(256) void headmix_kernel(const float* __restrict__ Mx) {
    int chunk = blockIdx.x;
    int t = blockIdx.y;
    int b = blockIdx.z;
    int s0 = chunk * 256;
    if (s0 > t) return;            // beyond causal: g_ah/g_al stay 0 (BSS init, never written)
    __shared__ float sm[16][256];
    __shared__ float Ms[256];
    int tid = threadIdx.x;
    Ms[tid] = Mx[tid];
#pragma unroll
    for (int h = 0; h < Hh; h++)
        sm[h][tid] = g_att[(((size_t)(b * Hh + h)) * Tn + t) * Tn + s0 + tid];
    __syncthreads();
    bool valid = (s0 + tid) <= t;
    float vals[16];
#pragma unroll
    for (int h = 0; h < Hh; h++) vals[h] = valid ? sm[h][tid] : 0.f;
#pragma unroll
    for (int o = 0; o < Hh; o++) {
        float acc = 0.f;
#pragma unroll
        for (int h = 0; h < Hh; h++) acc = fmaf(Ms[o * 16 + h], vals[h], acc);
        size_t idx = (((size_t)(b * Hh + o)) * Tn + t) * Tn + s0 + tid;
        __nv_bfloat16 hi = __float2bfloat16_rn(acc);
        g_ah[idx] = hi;
        g_al[idx] = __float2bfloat16_rn(acc - __bfloat162float(hi));
    }
}

// ================= 6) AV via bf16-split MMA, 256 thr + cp.async double buffer =================
#define AV_STAGE 32768
#define AV_SMEM (2 * AV_STAGE)
__global__ __launch_bounds__(256) void av_mma() {
    int tblk = blockIdx.x, bo = blockIdx.y;
    int b = bo >> 4, o = bo & 15;
    int t0 = tblk * 64;
    extern __shared__ char smem[];
    uint32_t sbase = smem_to_u32(smem);

    int tid = threadIdx.x, lane = tid & 31, wid = tid >> 5;
    int warp_m = wid & 3, warp_n = wid >> 2;   // 4 x 2 warp grid, warp tile 16(t) x 32(d)

    int a_row = warp_m * 16 + ((lane >> 3) & 1) * 8 + (lane & 7);
    int a_ch  = lane >> 4;
    int v_lrow = ((lane >> 3) & 1) * 8 + (lane & 7);

    float acc[4][4];
#pragma unroll
    for (int ni = 0; ni < 4; ni++)
#pragma unroll
        for (int j = 0; j < 4; j++) acc[ni][j] = 0.f;

    const __nv_bfloat16* Ah = g_ah + ((size_t)bo * Tn + t0) * Tn;
    const __nv_bfloat16* Al = g_al + ((size_t)bo * Tn + t0) * Tn;
    const __nv_bfloat16* Vh = g_vh + (size_t)bo * Tn * Dd;
    const __nv_bfloat16* Vl = g_vl + (size_t)bo * Tn * Dd;

    auto issue = [&](int st, int stage) {
        int s0 = st * 64;
        uint32_t sb = sbase + (uint32_t)stage * AV_STAGE;
#pragma unroll
        for (int j = 0; j < 2; j++) {
            int i = tid + j * 256;
            int row = i >> 3, ch = i & 7;
            uint32_t off = (uint32_t)(row * 128 + ((ch ^ (row & 7)) << 4));
            CP16(sb + off,         Ah + (size_t)row * Tn + s0 + ch * 8);
            CP16(sb + 8192 + off,  Al + (size_t)row * Tn + s0 + ch * 8);
            CP16(sb + 16384 + off, Vh + (size_t)(s0 + row) * Dd + ch * 8);
            CP16(sb + 24576 + off, Vl + (size_t)(s0 + row) * Dd + ch * 8);
        }
    };

    auto compute = [&](int stage) {
        uint32_t sb = sbase + (uint32_t)stage * AV_STAGE;
#pragma unroll
        for (int ks = 0; ks < 4; ks++) {
            uint32_t aH[4], aL[4], bH[4][2], bL[4][2];
            {
                int r = a_row;
                uint32_t off = (uint32_t)(r * 128 + (((ks * 2 + a_ch) ^ (r & 7)) << 4));
                ldsm4(aH, sb + off);
                ldsm4(aL, sb + 8192 + off);
            }
            int vrow = ks * 16 + v_lrow;
#pragma unroll
            for (int ni = 0; ni < 4; ni++) {
                int dch = warp_n * 4 + ni;
                uint32_t off = (uint32_t)(vrow * 128 + ((dch ^ (vrow & 7)) << 4));
                ldsm2t(bH[ni], sb + 16384 + off);
                ldsm2t(bL[ni], sb + 24576 + off);
            }
#pragma unroll
            for (int ni = 0; ni < 4; ni++) {
                mma16816(acc[ni], aH, bH[ni]);
                mma16816(acc[ni], aL, bH[ni]);
                mma16816(acc[ni], aH, bL[ni]);
            }
        }
    };

    int nStages = tblk + 1;
    issue(0, 0);
    CP_COMMIT();
#pragma unroll 1
    for (int st = 0; st < nStages; st++) {
        if (st + 1 < nStages) {
            issue(st + 1, (st + 1) & 1);
            CP_COMMIT();
            CP_WAIT1();
        } else {
            CP_WAIT0();
        }
        __syncthreads();
        compute(st & 1);
        __syncthreads();
    }

    int r4 = lane >> 2, cp2 = (lane & 3) * 2;
#pragma unroll
    for (int ni = 0; ni < 4; ni++) {
        int d = warp_n * 32 + ni * 8 + cp2;
        int t = t0 + warp_m * 16 + r4;
        size_t i0 = ((size_t)(b * Tn + t)) * Cc + o * 64 + d;
        split_store(g_y_h, g_y_l, i0,     acc[ni][0]);
        split_store(g_y_h, g_y_l, i0 + 1, acc[ni][1]);
        size_t i1 = ((size_t)(b * Tn + t + 8)) * Cc + o * 64 + d;
        split_store(g_y_h, g_y_l, i1,     acc[ni][2]);
        split_store(g_y_h, g_y_l, i1 + 1, acc[ni][3]);
    }
}

// ---------------- host launch ----------------
extern "C" void kernel_launch(void* const* d_in, const int* in_sizes, int n_in,
                              void* d_out, int out_size) {
    const float* x  = (const float*)d_in[0];
    const float* Wq = (const float*)d_in[1];
    const float* bq = (const float*)d_in[2];
    const float* Wk = (const float*)d_in[3];
    const float* bk = (const float*)d_in[4];
    const float* Wv = (const float*)d_in[5];
    const float* bv = (const float*)d_in[6];
    const float* tw = (const float*)d_in[7];
    const float* hm = (const float*)d_in[8];
    const float* Wp = (const float*)d_in[9];
    const float* bp = (const float*)d_in[10];
    float* out = (float*)d_out;

    static int smem_set = 0;
    if (!smem_set) {
        cudaFuncSetAttribute(proj_gemm_mma, cudaFuncAttributeMaxDynamicSharedMemorySize, PROJ_SMEM);
        cudaFuncSetAttribute(av_mma, cudaFuncAttributeMaxDynamicSharedMemorySize, AV_SMEM);
        smem_set = 1;
    }

    timeshift_kernel<<<(Bb * Tn * Cc) / 256, 256>>>(x);
    convert_w_kernel<<<(4 * Cc * Cc) / 256, 256>>>(Wq, Wk, Wv, Wp);

    dim3 gproj(Cc / 128, (Bb * Tn) / 128);
    proj_gemm_mma<<<gproj, 256, PROJ_SMEM>>>(bq, nullptr, 0);
    proj_gemm_mma<<<gproj, 256, PROJ_SMEM>>>(bk, nullptr, 1);
    proj_gemm_mma<<<gproj, 256, PROJ_SMEM>>>(bv, nullptr, 2);

    dim3 gs(Tn / 64, Tn / 64, Bb * Hh);
    scores_mma<<<gs, 128>>>();

    dim3 gsm(Tn, Bb * Hh);
    softmax_tw_kernel<<<gsm, 256>>>(tw);

    dim3 ghm(Tn / 256, Tn, Bb);
    headmix_kernel<<<ghm, 256>>>(hm);

    dim3 gav(Tn / 64, Bb * Hh);
    av_mma<<<gav, 256, AV_SMEM>>>();

    proj_gemm_mma<<<gproj, 256, PROJ_SMEM>>>(bp, out, 3);
}

// round 7
// speedup vs baseline: 2.6520x; 1.0982x over previous
#include <cuda_runtime.h>
#include <cuda_bf16.h>
#include <math.h>
#include <cstdint>

#define Bb 4
#define Tn 1024
#define Cc 1024
#define Hh 16
#define Dd 64
#define NELEM ((size_t)Bb * Tn * Cc)   // 4M

// ---------------- scratch (device globals) ----------------
__device__ float g_att[(size_t)Bb * Hh * Tn * Tn];         // fp32 raw scores (causal blocks)
__device__ float2 g_stat[(size_t)Bb * Hh * Tn];            // per-row (max, 1/sum)
__device__ __nv_bfloat16 g_ah[(size_t)Bb * Hh * Tn * Tn];  // mixed att hi (causal-zeroed)
__device__ __nv_bfloat16 g_al[(size_t)Bb * Hh * Tn * Tn];  // mixed att lo

__device__ __nv_bfloat16 g_xs_h[NELEM];               // time-shifted input hi/lo
__device__ __nv_bfloat16 g_xs_l[NELEM];
__device__ __nv_bfloat16 g_y_h[NELEM];                // AV output [B,T,C] hi/lo
__device__ __nv_bfloat16 g_y_l[NELEM];
__device__ __nv_bfloat16 g_wh[4 * (size_t)Cc * Cc];   // weights q,k,v,p hi
__device__ __nv_bfloat16 g_wl[4 * (size_t)Cc * Cc];   // weights q,k,v,p lo

__device__ __nv_bfloat16 g_qh[(size_t)Bb * Hh * Tn * Dd];  // [bh][t][d]
__device__ __nv_bfloat16 g_ql[(size_t)Bb * Hh * Tn * Dd];
__device__ __nv_bfloat16 g_kh[(size_t)Bb * Hh * Tn * Dd];
__device__ __nv_bfloat16 g_kl[(size_t)Bb * Hh * Tn * Dd];
__device__ __nv_bfloat16 g_vh[(size_t)Bb * Hh * Tn * Dd];
__device__ __nv_bfloat16 g_vl[(size_t)Bb * Hh * Tn * Dd];

// ================= helpers =================
__device__ __forceinline__ uint32_t smem_to_u32(const void* p) {
    uint32_t a;
    asm("{ .reg .u64 t; cvta.to.shared.u64 t, %1; cvt.u32.u64 %0, t; }" : "=r"(a) : "l"(p));
    return a;
}
#define CP16(dst, src) \
    asm volatile("cp.async.cg.shared.global [%0], [%1], 16;" :: "r"(dst), "l"(src) : "memory")
#define CP_COMMIT() asm volatile("cp.async.commit_group;" ::: "memory")
#define CP_WAIT1() asm volatile("cp.async.wait_group 1;" ::: "memory")

__device__ __forceinline__ void ldsm4(uint32_t* r, uint32_t addr) {
    asm volatile("ldmatrix.sync.aligned.m8n8.x4.shared.b16 {%0,%1,%2,%3}, [%4];"
                 : "=r"(r[0]), "=r"(r[1]), "=r"(r[2]), "=r"(r[3]) : "r"(addr));
}
__device__ __forceinline__ void ldsm2(uint32_t* r, uint32_t addr) {
    asm volatile("ldmatrix.sync.aligned.m8n8.x2.shared.b16 {%0,%1}, [%2];"
                 : "=r"(r[0]), "=r"(r[1]) : "r"(addr));
}
__device__ __forceinline__ void ldsm2t(uint32_t* r, uint32_t addr) {
    asm volatile("ldmatrix.sync.aligned.m8n8.x2.trans.shared.b16 {%0,%1}, [%2];"
                 : "=r"(r[0]), "=r"(r[1]) : "r"(addr));
}
__device__ __forceinline__ void mma16816(float* c, const uint32_t* a, const uint32_t* b) {
    asm volatile("mma.sync.aligned.m16n8k16.row.col.f32.bf16.bf16.f32 "
                 "{%0,%1,%2,%3}, {%4,%5,%6,%7}, {%8,%9}, {%0,%1,%2,%3};"
                 : "+f"(c[0]), "+f"(c[1]), "+f"(c[2]), "+f"(c[3])
                 : "r"(a[0]), "r"(a[1]), "r"(a[2]), "r"(a[3]), "r"(b[0]), "r"(b[1]));
}
__device__ __forceinline__ void split_store(__nv_bfloat16* ph, __nv_bfloat16* pl, size_t idx, float v) {
    __nv_bfloat16 h = __float2bfloat16_rn(v);
    ph[idx] = h;
    pl[idx] = __float2bfloat16_rn(v - __bfloat162float(h));
}

// ---------------- 1) time shift -> bf16 hi/lo ----------------
__global__ __launch_bounds__(256) void timeshift_kernel(const float* __restrict__ x) {
    int idx = blockIdx.x * blockDim.x + threadIdx.x;
    int c = idx & (Cc - 1);
    int t = (idx >> 10) & (Tn - 1);
    int b = idx >> 20;
    float val;
    if (c < Cc / 2) {
        val = (t == 0) ? 0.f : x[((size_t)b * Tn + (t - 1)) * Cc + c];
    } else {
        val = x[((size_t)b * Tn + t) * Cc + c];
    }
    split_store(g_xs_h, g_xs_l, idx, val);
}

// ---------------- 1b) weight conversion -> bf16 hi/lo ----------------
__global__ __launch_bounds__(256) void convert_w_kernel(const float* __restrict__ Wq,
                                                        const float* __restrict__ Wk,
                                                        const float* __restrict__ Wv,
                                                        const float* __restrict__ Wp) {
    size_t idx = (size_t)blockIdx.x * blockDim.x + threadIdx.x;
    int which = (int)(idx >> 20);
    size_t off = idx & ((size_t)Cc * Cc - 1);
    const float* W = (which == 0) ? Wq : (which == 1) ? Wk : (which == 2) ? Wv : Wp;
    split_store(g_wh, g_wl, idx, W[off]);
}

// ================= 2/7) bf16-split mma.sync projection GEMM, 3-stage pipeline =================
#define STAGE_BYTES 32768
#define PROJ_SMEM (3 * STAGE_BYTES)

__global__ __launch_bounds__(256) void proj_gemm_mma(const float* __restrict__ bias,
                                                     float* __restrict__ outflat, int which) {
    extern __shared__ char smem[];
    uint32_t sbase = smem_to_u32(smem);
    const __nv_bfloat16* gAh = (which == 3) ? g_y_h : g_xs_h;
    const __nv_bfloat16* gAl = (which == 3) ? g_y_l : g_xs_l;
    const __nv_bfloat16* gWh = g_wh + (size_t)which * Cc * Cc;
    const __nv_bfloat16* gWl = g_wl + (size_t)which * Cc * Cc;

    int tid = threadIdx.x, lane = tid & 31, wid = tid >> 5;
    int warp_m = wid & 1, warp_n = wid >> 1;
    int m0 = blockIdx.y * 128, n0 = blockIdx.x * 128;

    int rtid = tid >> 2;
    int ctid = tid & 3;

    int a_row_off = (lane & 7) + ((lane >> 3) & 1) * 8;
    int a_chunk = lane >> 4;
    int b_row_off = lane & 7;
    int b_chunk = (lane >> 3) & 1;

    uint32_t aBase[4], aSw[4], bBase[4], bSw[4];
#pragma unroll
    for (int mi = 0; mi < 4; mi++) {
        int r = warp_m * 64 + mi * 16 + a_row_off;
        aBase[mi] = (uint32_t)(r * 64);
        aSw[mi] = (uint32_t)((r >> 1) & 3);
    }
#pragma unroll
    for (int ni = 0; ni < 4; ni++) {
        int r = warp_n * 32 + ni * 8 + b_row_off;
        bBase[ni] = (uint32_t)(r * 64);
        bSw[ni] = (uint32_t)((r >> 1) & 3);
    }

    float acc[4][4][4];
#pragma unroll
    for (int mi = 0; mi < 4; mi++)
#pragma unroll
        for (int ni = 0; ni < 4; ni++)
#pragma unroll
            for (int j = 0; j < 4; j++) acc[mi][ni][j] = 0.f;

    auto issue = [&](int chunk, int stage) {
        int k0 = chunk * 32;
        uint32_t sb = sbase + (uint32_t)stage * STAGE_BYTES;
#pragma unroll
        for (int j = 0; j < 2; j++) {
            int row = rtid + j * 64;
            uint32_t dof = (uint32_t)(row * 64 + ((ctid ^ ((row >> 1) & 3)) << 4));
            size_t ga = (size_t)(m0 + row) * Cc + k0 + ctid * 8;
            size_t gw = (size_t)(n0 + row) * Cc + k0 + ctid * 8;
            CP16(sb + dof,         gAh + ga);
            CP16(sb + 8192 + dof,  gAl + ga);
            CP16(sb + 16384 + dof, gWh + gw);
            CP16(sb + 24576 + dof, gWl + gw);
        }
    };

    auto compute = [&](int stage) {
        uint32_t sb = sbase + (uint32_t)stage * STAGE_BYTES;
#pragma unroll
        for (int ks = 0; ks < 2; ks++) {
            uint32_t aH[4][4], aL[4][4], bH[4][2], bL[4][2];
#pragma unroll
            for (int mi = 0; mi < 4; mi++) {
                uint32_t off = aBase[mi] + ((((uint32_t)(ks * 2) + a_chunk) ^ aSw[mi]) << 4);
                ldsm4(aH[mi], sb + off);
                ldsm4(aL[mi], sb + 8192 + off);
            }
#pragma unroll
            for (int ni = 0; ni < 4; ni++) {
                uint32_t off = bBase[ni] + ((((uint32_t)(ks * 2) + b_chunk) ^ bSw[ni]) << 4);
                ldsm2(bH[ni], sb + 16384 + off);
                ldsm2(bL[ni], sb + 24576 + off);
            }
#pragma unroll
            for (int mi = 0; mi < 4; mi++)
#pragma unroll
                for (int ni = 0; ni < 4; ni++) {
                    mma16816(acc[mi][ni], aH[mi], bH[ni]);
                    mma16816(acc[mi][ni], aH[mi], bL[ni]);
                    mma16816(acc[mi][ni], aL[mi], bH[ni]);
                }
        }
    };

    const int NCH = Cc / 32;
    issue(0, 0);
    CP_COMMIT();
    issue(1, 1);
    CP_COMMIT();
#pragma unroll 1
    for (int c = 0; c < NCH; c++) {
        CP_WAIT1();                 // all but newest group done -> stage c ready
        __syncthreads();
        compute(c % 3);
        if (c + 2 < NCH) issue(c + 2, (c + 2) % 3);
        CP_COMMIT();                // unconditional: keeps group indexing positional
    }

    // epilogue
    int r4 = lane >> 2;
    int cp2 = (lane & 3) * 2;
    __nv_bfloat16* ph = (which == 0) ? g_qh : (which == 1) ? g_kh : g_vh;
    __nv_bfloat16* pl = (which == 0) ? g_ql : (which == 1) ? g_kl : g_vl;
#pragma unroll
    for (int ni = 0; ni < 4; ni++) {
        int n = n0 + warp_n * 32 + ni * 8 + cp2;
        float b0 = bias[n], b1 = bias[n + 1];
#pragma unroll
        for (int mi = 0; mi < 4; mi++) {
            int mA = m0 + warp_m * 64 + mi * 16 + r4;
            float v00 = acc[mi][ni][0] + b0, v01 = acc[mi][ni][1] + b1;
            float v10 = acc[mi][ni][2] + b0, v11 = acc[mi][ni][3] + b1;
            if (which == 3) {
                *reinterpret_cast<float2*>(&outflat[(size_t)mA * Cc + n]) = make_float2(v00, v01);
                *reinterpret_cast<float2*>(&outflat[(size_t)(mA + 8) * Cc + n]) = make_float2(v10, v11);
            } else {
                int h = n >> 6, d = n & 63;
                int b_ = mA >> 10, t = mA & 1023;
                size_t i0 = (((size_t)(b_ * Hh + h)) * Tn + t) * Dd + d;
                split_store(ph, pl, i0,     v00);
                split_store(ph, pl, i0 + 1, v01);
                int m2 = mA + 8;
                int b2 = m2 >> 10, t2 = m2 & 1023;
                size_t i1 = (((size_t)(b2 * Hh + h)) * Tn + t2) * Dd + d;
                split_store(ph, pl, i1,     v10);
                split_store(ph, pl, i1 + 1, v11);
            }
        }
    }
}

// ================= 3) scores via bf16-split MMA: S = QK^T / 8 =================
__global__ __launch_bounds__(128) void scores_mma() {
    int sblk = blockIdx.x, tblk = blockIdx.y, bh = blockIdx.z;
    if (sblk > tblk) return;
    __shared__ char smem[4 * 8192];   // Qh Ql Kh Kl (64 rows x 128B each)
    uint32_t sb = smem_to_u32(smem);

    int tid = threadIdx.x, lane = tid & 31, wid = tid >> 5;
    int warp_m = wid & 1, warp_n = wid >> 1;
    int t0 = tblk * 64, s0 = sblk * 64;

    const __nv_bfloat16* srcs[4] = {
        g_qh + ((size_t)bh * Tn + t0) * Dd,
        g_ql + ((size_t)bh * Tn + t0) * Dd,
        g_kh + ((size_t)bh * Tn + s0) * Dd,
        g_kl + ((size_t)bh * Tn + s0) * Dd };
#pragma unroll
    for (int a = 0; a < 4; a++) {
        const __nv_bfloat16* s = srcs[a];
        for (int i = tid; i < 512; i += 128) {
            int row = i >> 3, ch = i & 7;
            uint32_t off = (uint32_t)(row * 128 + ((ch ^ (row & 7)) << 4));
            *reinterpret_cast<uint4*>(smem + a * 8192 + off) =
                *reinterpret_cast<const uint4*>(s + row * 64 + ch * 8);
        }
    }
    __syncthreads();

    int a_row = warp_m * 32 + ((lane >> 3) & 1) * 8 + (lane & 7);
    int a_ch  = lane >> 4;
    int b_row = warp_n * 32 + (lane & 7);
    int b_ch  = (lane >> 3) & 1;

    float acc[2][4][4];
#pragma unroll
    for (int mi = 0; mi < 2; mi++)
#pragma unroll
        for (int ni = 0; ni < 4; ni++)
#pragma unroll
            for (int j = 0; j < 4; j++) acc[mi][ni][j] = 0.f;

#pragma unroll
    for (int ks = 0; ks < 4; ks++) {
        uint32_t aH[2][4], aL[2][4], bH[4][2], bL[4][2];
#pragma unroll
        for (int mi = 0; mi < 2; mi++) {
            int r = a_row + mi * 16;
            uint32_t off = (uint32_t)(r * 128 + (((ks * 2 + a_ch) ^ (r & 7)) << 4));
            ldsm4(aH[mi], sb + off);
            ldsm4(aL[mi], sb + 8192 + off);
        }
#pragma unroll
        for (int ni = 0; ni < 4; ni++) {
            int r = b_row + ni * 8;
            uint32_t off = (uint32_t)(r * 128 + (((ks * 2 + b_ch) ^ (r & 7)) << 4));
            ldsm2(bH[ni], sb + 16384 + off);
            ldsm2(bL[ni], sb + 24576 + off);
        }
#pragma unroll
        for (int mi = 0; mi < 2; mi++)
#pragma unroll
            for (int ni = 0; ni < 4; ni++) {
                mma16816(acc[mi][ni], aH[mi], bH[ni]);
                mma16816(acc[mi][ni], aH[mi], bL[ni]);
                mma16816(acc[mi][ni], aL[mi], bH[ni]);
            }
    }

    float* S = g_att + (size_t)bh * Tn * Tn;
    int r4 = lane >> 2, cp2 = (lane & 3) * 2;
#pragma unroll
    for (int mi = 0; mi < 2; mi++) {
        int t = t0 + warp_m * 32 + mi * 16 + r4;
#pragma unroll
        for (int ni = 0; ni < 4; ni++) {
            int s = s0 + warp_n * 32 + ni * 8 + cp2;
            *reinterpret_cast<float2*>(&S[(size_t)t * Tn + s]) =
                make_float2(acc[mi][ni][0] * 0.125f, acc[mi][ni][1] * 0.125f);
            *reinterpret_cast<float2*>(&S[(size_t)(t + 8) * Tn + s]) =
                make_float2(acc[mi][ni][2] * 0.125f, acc[mi][ni][3] * 0.125f);
        }
    }
}

// ---------------- 4) row stats: single-pass online (max, 1/sum) ----------------
__global__ __launch_bounds__(128) void rowstat_kernel() {
    int t = blockIdx.x, bh = blockIdx.y;
    const float* row = g_att + ((size_t)bh * Tn + t) * Tn;
    int L = t + 1;
    int tid = threadIdx.x, lane = tid & 31, wid = tid >> 5;

    float m = -1e30f, s = 0.f;
    for (int i = tid; i < L; i += 128) {
        float x = row[i];
        if (x > m) { s *= __expf(m - x); m = x; }
        s += __expf(x - m);
    }
#pragma unroll
    for (int o = 16; o; o >>= 1) {
        float mo = __shfl_xor_sync(0xffffffffu, m, o);
        float so = __shfl_xor_sync(0xffffffffu, s, o);
        float M = fmaxf(m, mo);
        s = s * __expf(m - M) + so * __expf(mo - M);
        m = M;
    }
    __shared__ float2 red[4];
    if (lane == 0) red[wid] = make_float2(m, s);
    __syncthreads();
    if (tid == 0) {
        float M = red[0].x;
#pragma unroll
        for (int i = 1; i < 4; i++) M = fmaxf(M, red[i].x);
        float S = 0.f;
#pragma unroll
        for (int i = 0; i < 4; i++) S += red[i].y * __expf(red[i].x - M);
        g_stat[(size_t)bh * Tn + t] = make_float2(M, 1.0f / S);
    }
}

// ---------------- 5) apply exp*inv*tw + head mix -> bf16 hi/lo, causal-zeroed ----------------
__global__ __launch_bounds__(256) void mixapply_kernel(const float* __restrict__ tw,
                                                       const float* __restrict__ Mx) {
    int chunk = blockIdx.x, t = blockIdx.y, b = blockIdx.z;
    int s0 = chunk * 256;
    if (s0 > t) return;            // beyond causal: g_ah/g_al stay 0 (never written)
    __shared__ float Ms[256];
    __shared__ float2 st[16];
    int tid = threadIdx.x;
    Ms[tid] = Mx[tid];
    if (tid < 16) st[tid] = g_stat[((size_t)(b * Hh + tid)) * Tn + t];
    __syncthreads();

    int s = s0 + tid;
    bool valid = s <= t;
    float vals[16];
#pragma unroll
    for (int h = 0; h < Hh; h++) {
        float x = g_att[(((size_t)(b * Hh + h)) * Tn + t) * Tn + s];
        float w = tw[(((size_t)h * Tn) + t) * Tn + s];
        vals[h] = valid ? __expf(x - st[h].x) * st[h].y * w : 0.f;
    }
#pragma unroll
    for (int o = 0; o < Hh; o++) {
        float a = 0.f;
#pragma unroll
        for (int h = 0; h < Hh; h++) a = fmaf(Ms[o * 16 + h], vals[h], a);
        size_t idx = (((size_t)(b * Hh + o)) * Tn + t) * Tn + s;
        __nv_bfloat16 hi = __float2bfloat16_rn(a);
        g_ah[idx] = hi;
        g_al[idx] = __float2bfloat16_rn(a - __bfloat162float(hi));
    }
}

// ================= 6) AV via bf16-split MMA, 256 thr + 3-stage cp.async =================
#define AV_STAGE 32768
#define AV_SMEM (3 * AV_STAGE)
__global__ __launch_bounds__(256) void av_mma() {
    int tblk = blockIdx.x, bo = blockIdx.y;
    int b = bo >> 4, o = bo & 15;
    int t0 = tblk * 64;
    extern __shared__ char smem[];
    uint32_t sbase = smem_to_u32(smem);

    int tid = threadIdx.x, lane = tid & 31, wid = tid >> 5;
    int warp_m = wid & 3, warp_n = wid >> 2;   // 4 x 2 warp grid, warp tile 16(t) x 32(d)

    int a_row = warp_m * 16 + ((lane >> 3) & 1) * 8 + (lane & 7);
    int a_ch  = lane >> 4;
    int v_lrow = ((lane >> 3) & 1) * 8 + (lane & 7);

    float acc[4][4];
#pragma unroll
    for (int ni = 0; ni < 4; ni++)
#pragma unroll
        for (int j = 0; j < 4; j++) acc[ni][j] = 0.f;

    const __nv_bfloat16* Ah = g_ah + ((size_t)bo * Tn + t0) * Tn;
    const __nv_bfloat16* Al = g_al + ((size_t)bo * Tn + t0) * Tn;
    const __nv_bfloat16* Vh = g_vh + (size_t)bo * Tn * Dd;
    const __nv_bfloat16* Vl = g_vl + (size_t)bo * Tn * Dd;

    auto issue = [&](int st, int stage) {
        int s0 = st * 64;
        uint32_t sb = sbase + (uint32_t)stage * AV_STAGE;
#pragma unroll
        for (int j = 0; j < 2; j++) {
            int i = tid + j * 256;
            int row = i >> 3, ch = i & 7;
            uint32_t off = (uint32_t)(row * 128 + ((ch ^ (row & 7)) << 4));
            CP16(sb + off,         Ah + (size_t)row * Tn + s0 + ch * 8);
            CP16(sb + 8192 + off,  Al + (size_t)row * Tn + s0 + ch * 8);
            CP16(sb + 16384 + off, Vh + (size_t)(s0 + row) * Dd + ch * 8);
            CP16(sb + 24576 + off, Vl + (size_t)(s0 + row) * Dd + ch * 8);
        }
    };

    auto compute = [&](int stage) {
        uint32_t sb = sbase + (uint32_t)stage * AV_STAGE;
#pragma unroll
        for (int ks = 0; ks < 4; ks++) {
            uint32_t aH[4], aL[4], bH[4][2], bL[4][2];
            {
                int r = a_row;
                uint32_t off = (uint32_t)(r * 128 + (((ks * 2 + a_ch) ^ (r & 7)) << 4));
                ldsm4(aH, sb + off);
                ldsm4(aL, sb + 8192 + off);
            }
            int vrow = ks * 16 + v_lrow;
#pragma unroll
            for (int ni = 0; ni < 4; ni++) {
                int dch = warp_n * 4 + ni;
                uint32_t off = (uint32_t)(vrow * 128 + ((dch ^ (vrow & 7)) << 4));
                ldsm2t(bH[ni], sb + 16384 + off);
                ldsm2t(bL[ni], sb + 24576 + off);
            }
#pragma unroll
            for (int ni = 0; ni < 4; ni++) {
                mma16816(acc[ni], aH, bH[ni]);
                mma16816(acc[ni], aL, bH[ni]);
                mma16816(acc[ni], aH, bL[ni]);
            }
        }
    };

    int nStages = tblk + 1;
    issue(0, 0);
    CP_COMMIT();
    if (nStages > 1) issue(1, 1);
    CP_COMMIT();
#pragma unroll 1
    for (int st = 0; st < nStages; st++) {
        CP_WAIT1();
        __syncthreads();
        compute(st % 3);
        if (st + 2 < nStages) issue(st + 2, (st + 2) % 3);
        CP_COMMIT();
    }

    int r4 = lane >> 2, cp2 = (lane & 3) * 2;
#pragma unroll
    for (int ni = 0; ni < 4; ni++) {
        int d = warp_n * 32 + ni * 8 + cp2;
        int t = t0 + warp_m * 16 + r4;
        size_t i0 = ((size_t)(b * Tn + t)) * Cc + o * 64 + d;
        split_store(g_y_h, g_y_l, i0,     acc[ni][0]);
        split_store(g_y_h, g_y_l, i0 + 1, acc[ni][1]);
        size_t i1 = ((size_t)(b * Tn + t + 8)) * Cc + o * 64 + d;
        split_store(g_y_h, g_y_l, i1,     acc[ni][2]);
        split_store(g_y_h, g_y_l, i1 + 1, acc[ni][3]);
    }
}

// ---------------- host launch ----------------
extern "C" void kernel_launch(void* const* d_in, const int* in_sizes, int n_in,
                              void* d_out, int out_size) {
    const float* x  = (const float*)d_in[0];
    const float* Wq = (const float*)d_in[1];
    const float* bq = (const float*)d_in[2];
    const float* Wk = (const float*)d_in[3];
    const float* bk = (const float*)d_in[4];
    const float* Wv = (const float*)d_in[5];
    const float* bv = (const float*)d_in[6];
    const float* tw = (const float*)d_in[7];
    const float* hm = (const float*)d_in[8];
    const float* Wp = (const float*)d_in[9];
    const float* bp = (const float*)d_in[10];
    float* out = (float*)d_out;

    static int smem_set = 0;
    if (!smem_set) {
        cudaFuncSetAttribute(proj_gemm_mma, cudaFuncAttributeMaxDynamicSharedMemorySize, PROJ_SMEM);
        cudaFuncSetAttribute(av_mma, cudaFuncAttributeMaxDynamicSharedMemorySize, AV_SMEM);
        smem_set = 1;
    }

    timeshift_kernel<<<(Bb * Tn * Cc) / 256, 256>>>(x);
    convert_w_kernel<<<(4 * Cc * Cc) / 256, 256>>>(Wq, Wk, Wv, Wp);

    dim3 gproj(Cc / 128, (Bb * Tn) / 128);
    proj_gemm_mma<<<gproj, 256, PROJ_SMEM>>>(bq, nullptr, 0);
    proj_gemm_mma<<<gproj, 256, PROJ_SMEM>>>(bk, nullptr, 1);
    proj_gemm_mma<<<gproj, 256, PROJ_SMEM>>>(bv, nullptr, 2);

    dim3 gs(Tn / 64, Tn / 64, Bb * Hh);
    scores_mma<<<gs, 128>>>();

    dim3 grs(Tn, Bb * Hh);
    rowstat_kernel<<<grs, 128>>>();

    dim3 gmx(Tn / 256, Tn, Bb);
    mixapply_kernel<<<gmx, 256>>>(tw, hm);

    dim3 gav(Tn / 64, Bb * Hh);
    av_mma<<<gav, 256, AV_SMEM>>>();

    proj_gemm_mma<<<gproj, 256, PROJ_SMEM>>>(bp, out, 3);
}

// round 8
// speedup vs baseline: 2.9603x; 1.1163x over previous
#include <cuda_runtime.h>
#include <cuda_bf16.h>
#include <math.h>
#include <cstdint>

#define Bb 4
#define Tn 1024
#define Cc 1024
#define Hh 16
#define Dd 64
#define NELEM ((size_t)Bb * Tn * Cc)   // 4M

// ---------------- scratch (device globals) ----------------
__device__ float g_att[(size_t)Bb * Hh * Tn * Tn];         // fp32 raw scores (causal blocks)
__device__ float g_psum[(size_t)Bb * Hh * Tn * 16];        // per-(row, sblk) exp partial sums
__device__ float g_inv[(size_t)Bb * Hh * Tn];              // per-row 1/sum
__device__ __nv_bfloat16 g_ah[(size_t)Bb * Hh * Tn * Tn];  // mixed att hi (causal-zeroed)
__device__ __nv_bfloat16 g_al[(size_t)Bb * Hh * Tn * Tn];  // mixed att lo

__device__ __nv_bfloat16 g_xs_h[NELEM];               // time-shifted input hi/lo
__device__ __nv_bfloat16 g_xs_l[NELEM];
__device__ __nv_bfloat16 g_y_h[NELEM];                // AV output [B,T,C] hi/lo
__device__ __nv_bfloat16 g_y_l[NELEM];
__device__ __nv_bfloat16 g_wh[4 * (size_t)Cc * Cc];   // weights q,k,v,p hi
__device__ __nv_bfloat16 g_wl[4 * (size_t)Cc * Cc];   // weights q,k,v,p lo

__device__ __nv_bfloat16 g_qh[(size_t)Bb * Hh * Tn * Dd];  // [bh][t][d]
__device__ __nv_bfloat16 g_ql[(size_t)Bb * Hh * Tn * Dd];
__device__ __nv_bfloat16 g_kh[(size_t)Bb * Hh * Tn * Dd];
__device__ __nv_bfloat16 g_kl[(size_t)Bb * Hh * Tn * Dd];
__device__ __nv_bfloat16 g_vh[(size_t)Bb * Hh * Tn * Dd];
__device__ __nv_bfloat16 g_vl[(size_t)Bb * Hh * Tn * Dd];

// ================= helpers =================
__device__ __forceinline__ uint32_t smem_to_u32(const void* p) {
    uint32_t a;
    asm("{ .reg .u64 t; cvta.to.shared.u64 t, %1; cvt.u32.u64 %0, t; }" : "=r"(a) : "l"(p));
    return a;
}
#define CP16(dst, src) \
    asm volatile("cp.async.cg.shared.global [%0], [%1], 16;" :: "r"(dst), "l"(src) : "memory")
#define CP_COMMIT() asm volatile("cp.async.commit_group;" ::: "memory")
#define CP_WAIT0() asm volatile("cp.async.wait_group 0;" ::: "memory")
#define CP_WAIT1() asm volatile("cp.async.wait_group 1;" ::: "memory")

__device__ __forceinline__ void ldsm4(uint32_t* r, uint32_t addr) {
    asm volatile("ldmatrix.sync.aligned.m8n8.x4.shared.b16 {%0,%1,%2,%3}, [%4];"
                 : "=r"(r[0]), "=r"(r[1]), "=r"(r[2]), "=r"(r[3]) : "r"(addr));
}
__device__ __forceinline__ void ldsm2(uint32_t* r, uint32_t addr) {
    asm volatile("ldmatrix.sync.aligned.m8n8.x2.shared.b16 {%0,%1}, [%2];"
                 : "=r"(r[0]), "=r"(r[1]) : "r"(addr));
}
__device__ __forceinline__ void ldsm2t(uint32_t* r, uint32_t addr) {
    asm volatile("ldmatrix.sync.aligned.m8n8.x2.trans.shared.b16 {%0,%1}, [%2];"
                 : "=r"(r[0]), "=r"(r[1]) : "r"(addr));
}
__device__ __forceinline__ void mma16816(float* c, const uint32_t* a, const uint32_t* b) {
    asm volatile("mma.sync.aligned.m16n8k16.row.col.f32.bf16.bf16.f32 "
                 "{%0,%1,%2,%3}, {%4,%5,%6,%7}, {%8,%9}, {%0,%1,%2,%3};"
                 : "+f"(c[0]), "+f"(c[1]), "+f"(c[2]), "+f"(c[3])
                 : "r"(a[0]), "r"(a[1]), "r"(a[2]), "r"(a[3]), "r"(b[0]), "r"(b[1]));
}
__device__ __forceinline__ void split_store(__nv_bfloat16* ph, __nv_bfloat16* pl, size_t idx, float v) {
    __nv_bfloat16 h = __float2bfloat16_rn(v);
    ph[idx] = h;
    pl[idx] = __float2bfloat16_rn(v - __bfloat162float(h));
}

// ---------------- 1) time shift -> bf16 hi/lo ----------------
__global__ __launch_bounds__(256) void timeshift_kernel(const float* __restrict__ x) {
    int idx = blockIdx.x * blockDim.x + threadIdx.x;
    int c = idx & (Cc - 1);
    int t = (idx >> 10) & (Tn - 1);
    int b = idx >> 20;
    float val;
    if (c < Cc / 2) {
        val = (t == 0) ? 0.f : x[((size_t)b * Tn + (t - 1)) * Cc + c];
    } else {
        val = x[((size_t)b * Tn + t) * Cc + c];
    }
    split_store(g_xs_h, g_xs_l, idx, val);
}

// ---------------- 1b) weight conversion -> bf16 hi/lo ----------------
__global__ __launch_bounds__(256) void convert_w_kernel(const float* __restrict__ Wq,
                                                        const float* __restrict__ Wk,
                                                        const float* __restrict__ Wv,
                                                        const float* __restrict__ Wp) {
    size_t idx = (size_t)blockIdx.x * blockDim.x + threadIdx.x;
    int which = (int)(idx >> 20);
    size_t off = idx & ((size_t)Cc * Cc - 1);
    const float* W = (which == 0) ? Wq : (which == 1) ? Wk : (which == 2) ? Wv : Wp;
    split_store(g_wh, g_wl, idx, W[off]);
}

// ================= 2/7) bf16-split mma.sync projection GEMM, 2-stage pipeline =================
#define STAGE_BYTES 32768
#define PROJ_SMEM (2 * STAGE_BYTES)

__global__ __launch_bounds__(256) void proj_gemm_mma(const float* __restrict__ bias,
                                                     float* __restrict__ outflat, int which) {
    extern __shared__ char smem[];
    uint32_t sbase = smem_to_u32(smem);
    const __nv_bfloat16* gAh = (which == 3) ? g_y_h : g_xs_h;
    const __nv_bfloat16* gAl = (which == 3) ? g_y_l : g_xs_l;
    const __nv_bfloat16* gWh = g_wh + (size_t)which * Cc * Cc;
    const __nv_bfloat16* gWl = g_wl + (size_t)which * Cc * Cc;

    int tid = threadIdx.x, lane = tid & 31, wid = tid >> 5;
    int warp_m = wid & 1, warp_n = wid >> 1;
    int m0 = blockIdx.y * 128, n0 = blockIdx.x * 128;

    int rtid = tid >> 2;
    int ctid = tid & 3;

    int a_row_off = (lane & 7) + ((lane >> 3) & 1) * 8;
    int a_chunk = lane >> 4;
    int b_row_off = lane & 7;
    int b_chunk = (lane >> 3) & 1;

    uint32_t aBase[4], aSw[4], bBase[4], bSw[4];
#pragma unroll
    for (int mi = 0; mi < 4; mi++) {
        int r = warp_m * 64 + mi * 16 + a_row_off;
        aBase[mi] = (uint32_t)(r * 64);
        aSw[mi] = (uint32_t)((r >> 1) & 3);
    }
#pragma unroll
    for (int ni = 0; ni < 4; ni++) {
        int r = warp_n * 32 + ni * 8 + b_row_off;
        bBase[ni] = (uint32_t)(r * 64);
        bSw[ni] = (uint32_t)((r >> 1) & 3);
    }

    float acc[4][4][4];
#pragma unroll
    for (int mi = 0; mi < 4; mi++)
#pragma unroll
        for (int ni = 0; ni < 4; ni++)
#pragma unroll
            for (int j = 0; j < 4; j++) acc[mi][ni][j] = 0.f;

    auto issue = [&](int chunk, int stage) {
        int k0 = chunk * 32;
        uint32_t sb = sbase + (uint32_t)stage * STAGE_BYTES;
#pragma unroll
        for (int j = 0; j < 2; j++) {
            int row = rtid + j * 64;
            uint32_t dof = (uint32_t)(row * 64 + ((ctid ^ ((row >> 1) & 3)) << 4));
            size_t ga = (size_t)(m0 + row) * Cc + k0 + ctid * 8;
            size_t gw = (size_t)(n0 + row) * Cc + k0 + ctid * 8;
            CP16(sb + dof,         gAh + ga);
            CP16(sb + 8192 + dof,  gAl + ga);
            CP16(sb + 16384 + dof, gWh + gw);
            CP16(sb + 24576 + dof, gWl + gw);
        }
    };

    auto compute = [&](int stage) {
        uint32_t sb = sbase + (uint32_t)stage * STAGE_BYTES;
#pragma unroll
        for (int ks = 0; ks < 2; ks++) {
            uint32_t aH[4][4], aL[4][4], bH[4][2], bL[4][2];
#pragma unroll
            for (int mi = 0; mi < 4; mi++) {
                uint32_t off = aBase[mi] + ((((uint32_t)(ks * 2) + a_chunk) ^ aSw[mi]) << 4);
                ldsm4(aH[mi], sb + off);
                ldsm4(aL[mi], sb + 8192 + off);
            }
#pragma unroll
            for (int ni = 0; ni < 4; ni++) {
                uint32_t off = bBase[ni] + ((((uint32_t)(ks * 2) + b_chunk) ^ bSw[ni]) << 4);
                ldsm2(bH[ni], sb + 16384 + off);
                ldsm2(bL[ni], sb + 24576 + off);
            }
#pragma unroll
            for (int mi = 0; mi < 4; mi++)
#pragma unroll
                for (int ni = 0; ni < 4; ni++) {
                    mma16816(acc[mi][ni], aH[mi], bH[ni]);
                    mma16816(acc[mi][ni], aH[mi], bL[ni]);
                    mma16816(acc[mi][ni], aL[mi], bH[ni]);
                }
        }
    };

    const int NCH = Cc / 32;
    issue(0, 0);
    CP_COMMIT();
#pragma unroll 1
    for (int c = 0; c < NCH; c++) {
        if (c + 1 < NCH) {
            issue(c + 1, (c + 1) & 1);
            CP_COMMIT();
            CP_WAIT1();
        } else {
            CP_WAIT0();
        }
        __syncthreads();
        compute(c & 1);
        __syncthreads();
    }

    // epilogue
    int r4 = lane >> 2;
    int cp2 = (lane & 3) * 2;
    __nv_bfloat16* ph = (which == 0) ? g_qh : (which == 1) ? g_kh : g_vh;
    __nv_bfloat16* pl = (which == 0) ? g_ql : (which == 1) ? g_kl : g_vl;
#pragma unroll
    for (int ni = 0; ni < 4; ni++) {
        int n = n0 + warp_n * 32 + ni * 8 + cp2;
        float b0 = bias[n], b1 = bias[n + 1];
#pragma unroll
        for (int mi = 0; mi < 4; mi++) {
            int mA = m0 + warp_m * 64 + mi * 16 + r4;
            float v00 = acc[mi][ni][0] + b0, v01 = acc[mi][ni][1] + b1;
            float v10 = acc[mi][ni][2] + b0, v11 = acc[mi][ni][3] + b1;
            if (which == 3) {
                *reinterpret_cast<float2*>(&outflat[(size_t)mA * Cc + n]) = make_float2(v00, v01);
                *reinterpret_cast<float2*>(&outflat[(size_t)(mA + 8) * Cc + n]) = make_float2(v10, v11);
            } else {
                int h = n >> 6, d = n & 63;
                int b_ = mA >> 10, t = mA & 1023;
                size_t i0 = (((size_t)(b_ * Hh + h)) * Tn + t) * Dd + d;
                split_store(ph, pl, i0,     v00);
                split_store(ph, pl, i0 + 1, v01);
                int m2 = mA + 8;
                int b2 = m2 >> 10, t2 = m2 & 1023;
                size_t i1 = (((size_t)(b2 * Hh + h)) * Tn + t2) * Dd + d;
                split_store(ph, pl, i1,     v10);
                split_store(ph, pl, i1 + 1, v11);
            }
        }
    }
}

// ================= 3) scores via bf16-split MMA: S = QK^T / 8, + masked exp partial sums =================
__global__ __launch_bounds__(128) void scores_mma() {
    int sblk = blockIdx.x, tblk = blockIdx.y, bh = blockIdx.z;
    if (sblk > tblk) return;
    __shared__ char smem[4 * 8192];   // Qh Ql Kh Kl (64 rows x 128B each)
    __shared__ float rowsum[64][2];
    uint32_t sb = smem_to_u32(smem);

    int tid = threadIdx.x, lane = tid & 31, wid = tid >> 5;
    int warp_m = wid & 1, warp_n = wid >> 1;
    int t0 = tblk * 64, s0 = sblk * 64;

    const __nv_bfloat16* srcs[4] = {
        g_qh + ((size_t)bh * Tn + t0) * Dd,
        g_ql + ((size_t)bh * Tn + t0) * Dd,
        g_kh + ((size_t)bh * Tn + s0) * Dd,
        g_kl + ((size_t)bh * Tn + s0) * Dd };
#pragma unroll
    for (int a = 0; a < 4; a++) {
        const __nv_bfloat16* s = srcs[a];
        for (int i = tid; i < 512; i += 128) {
            int row = i >> 3, ch = i & 7;
            uint32_t off = (uint32_t)(row * 128 + ((ch ^ (row & 7)) << 4));
            *reinterpret_cast<uint4*>(smem + a * 8192 + off) =
                *reinterpret_cast<const uint4*>(s + row * 64 + ch * 8);
        }
    }
    __syncthreads();

    int a_row = warp_m * 32 + ((lane >> 3) & 1) * 8 + (lane & 7);
    int a_ch  = lane >> 4;
    int b_row = warp_n * 32 + (lane & 7);
    int b_ch  = (lane >> 3) & 1;

    float acc[2][4][4];
#pragma unroll
    for (int mi = 0; mi < 2; mi++)
#pragma unroll
        for (int ni = 0; ni < 4; ni++)
#pragma unroll
            for (int j = 0; j < 4; j++) acc[mi][ni][j] = 0.f;

#pragma unroll
    for (int ks = 0; ks < 4; ks++) {
        uint32_t aH[2][4], aL[2][4], bH[4][2], bL[4][2];
#pragma unroll
        for (int mi = 0; mi < 2; mi++) {
            int r = a_row + mi * 16;
            uint32_t off = (uint32_t)(r * 128 + (((ks * 2 + a_ch) ^ (r & 7)) << 4));
            ldsm4(aH[mi], sb + off);
            ldsm4(aL[mi], sb + 8192 + off);
        }
#pragma unroll
        for (int ni = 0; ni < 4; ni++) {
            int r = b_row + ni * 8;
            uint32_t off = (uint32_t)(r * 128 + (((ks * 2 + b_ch) ^ (r & 7)) << 4));
            ldsm2(bH[ni], sb + 16384 + off);
            ldsm2(bL[ni], sb + 24576 + off);
        }
#pragma unroll
        for (int mi = 0; mi < 2; mi++)
#pragma unroll
            for (int ni = 0; ni < 4; ni++) {
                mma16816(acc[mi][ni], aH[mi], bH[ni]);
                mma16816(acc[mi][ni], aH[mi], bL[ni]);
                mma16816(acc[mi][ni], aL[mi], bH[ni]);
            }
    }

    float* S = g_att + (size_t)bh * Tn * Tn;
    int r4 = lane >> 2, cp2 = (lane & 3) * 2;
    float esum[2][2] = {};   // [mi][row half (r4 / r4+8)]
#pragma unroll
    for (int mi = 0; mi < 2; mi++) {
        int t = t0 + warp_m * 32 + mi * 16 + r4;
#pragma unroll
        for (int ni = 0; ni < 4; ni++) {
            int s = s0 + warp_n * 32 + ni * 8 + cp2;
            float v0 = acc[mi][ni][0] * 0.125f, v1 = acc[mi][ni][1] * 0.125f;
            float v2 = acc[mi][ni][2] * 0.125f, v3 = acc[mi][ni][3] * 0.125f;
            *reinterpret_cast<float2*>(&S[(size_t)t * Tn + s]) = make_float2(v0, v1);
            *reinterpret_cast<float2*>(&S[(size_t)(t + 8) * Tn + s]) = make_float2(v2, v3);
            esum[mi][0] += (s     <= t    ? __expf(v0) : 0.f) + (s + 1 <= t     ? __expf(v1) : 0.f);
            esum[mi][1] += (s     <= t + 8 ? __expf(v2) : 0.f) + (s + 1 <= t + 8 ? __expf(v3) : 0.f);
        }
    }
    // reduce across the 4 lanes sharing a row (lane & 3)
#pragma unroll
    for (int mi = 0; mi < 2; mi++)
#pragma unroll
        for (int hf = 0; hf < 2; hf++) {
            float v = esum[mi][hf];
            v += __shfl_xor_sync(0xffffffffu, v, 1);
            v += __shfl_xor_sync(0xffffffffu, v, 2);
            esum[mi][hf] = v;
        }
    if ((lane & 3) == 0) {
#pragma unroll
        for (int mi = 0; mi < 2; mi++)
#pragma unroll
            for (int hf = 0; hf < 2; hf++)
                rowsum[warp_m * 32 + mi * 16 + hf * 8 + r4][warp_n] = esum[mi][hf];
    }
    __syncthreads();
    if (tid < 64)
        g_psum[(((size_t)bh * Tn) + t0 + tid) * 16 + sblk] = rowsum[tid][0] + rowsum[tid][1];
}

// ---------------- 4) reduce partials -> 1/sum per row ----------------
__global__ __launch_bounds__(256) void reduce_inv_kernel() {
    int idx = blockIdx.x * blockDim.x + threadIdx.x;   // bh*Tn + t
    int t = idx & (Tn - 1);
    int nblk = (t >> 6) + 1;
    const float* p = g_psum + (size_t)idx * 16;
    float S = 0.f;
    for (int i = 0; i < nblk; i++) S += p[i];
    g_inv[idx] = 1.0f / S;
}

// ---------------- 5) apply exp*inv*tw + head mix -> bf16 hi/lo, causal-zeroed ----------------
__global__ __launch_bounds__(256) void mixapply_kernel(const float* __restrict__ tw,
                                                       const float* __restrict__ Mx) {
    int chunk = blockIdx.x, t = blockIdx.y, b = blockIdx.z;
    int s0 = chunk * 256;
    if (s0 > t) return;            // beyond causal: g_ah/g_al stay 0 (never written)
    __shared__ float Ms[256];
    __shared__ float st[16];
    int tid = threadIdx.x;
    Ms[tid] = Mx[tid];
    if (tid < 16) st[tid] = g_inv[((size_t)(b * Hh + tid)) * Tn + t];
    __syncthreads();

    int s = s0 + tid;
    bool valid = s <= t;
    float vals[16];
#pragma unroll
    for (int h = 0; h < Hh; h++) {
        float x = g_att[(((size_t)(b * Hh + h)) * Tn + t) * Tn + s];
        float w = tw[(((size_t)h * Tn) + t) * Tn + s];
        vals[h] = valid ? __expf(x) * st[h] * w : 0.f;
    }
#pragma unroll
    for (int o = 0; o < Hh; o++) {
        float a = 0.f;
#pragma unroll
        for (int h = 0; h < Hh; h++) a = fmaf(Ms[o * 16 + h], vals[h], a);
        size_t idx = (((size_t)(b * Hh + o)) * Tn + t) * Tn + s;
        __nv_bfloat16 hi = __float2bfloat16_rn(a);
        g_ah[idx] = hi;
        g_al[idx] = __float2bfloat16_rn(a - __bfloat162float(hi));
    }
}

// ================= 6) AV via bf16-split MMA, 256 thr + 3-stage cp.async =================
#define AV_STAGE 32768
#define AV_SMEM (3 * AV_STAGE)
__global__ __launch_bounds__(256) void av_mma() {
    int tblk = blockIdx.x, bo = blockIdx.y;
    int b = bo >> 4, o = bo & 15;
    int t0 = tblk * 64;
    extern __shared__ char smem[];
    uint32_t sbase = smem_to_u32(smem);

    int tid = threadIdx.x, lane = tid & 31, wid = tid >> 5;
    int warp_m = wid & 3, warp_n = wid >> 2;   // 4 x 2 warp grid, warp tile 16(t) x 32(d)

    int a_row = warp_m * 16 + ((lane >> 3) & 1) * 8 + (lane & 7);
    int a_ch  = lane >> 4;
    int v_lrow = ((lane >> 3) & 1) * 8 + (lane & 7);

    float acc[4][4];
#pragma unroll
    for (int ni = 0; ni < 4; ni++)
#pragma unroll
        for (int j = 0; j < 4; j++) acc[ni][j] = 0.f;

    const __nv_bfloat16* Ah = g_ah + ((size_t)bo * Tn + t0) * Tn;
    const __nv_bfloat16* Al = g_al + ((size_t)bo * Tn + t0) * Tn;
    const __nv_bfloat16* Vh = g_vh + (size_t)bo * Tn * Dd;
    const __nv_bfloat16* Vl = g_vl + (size_t)bo * Tn * Dd;

    auto issue = [&](int st, int stage) {
        int s0 = st * 64;
        uint32_t sb = sbase + (uint32_t)stage * AV_STAGE;
#pragma unroll
        for (int j = 0; j < 2; j++) {
            int i = tid + j * 256;
            int row = i >> 3, ch = i & 7;
            uint32_t off = (uint32_t)(row * 128 + ((ch ^ (row & 7)) << 4));
            CP16(sb + off,         Ah + (size_t)row * Tn + s0 + ch * 8);
            CP16(sb + 8192 + off,  Al + (size_t)row * Tn + s0 + ch * 8);
            CP16(sb + 16384 + off, Vh + (size_t)(s0 + row) * Dd + ch * 8);
            CP16(sb + 24576 + off, Vl + (size_t)(s0 + row) * Dd + ch * 8);
        }
    };

    auto compute = [&](int stage) {
        uint32_t sb = sbase + (uint32_t)stage * AV_STAGE;
#pragma unroll
        for (int ks = 0; ks < 4; ks++) {
            uint32_t aH[4], aL[4], bH[4][2], bL[4][2];
            {
                int r = a_row;
                uint32_t off = (uint32_t)(r * 128 + (((ks * 2 + a_ch) ^ (r & 7)) << 4));
                ldsm4(aH, sb + off);
                ldsm4(aL, sb + 8192 + off);
            }
            int vrow = ks * 16 + v_lrow;
#pragma unroll
            for (int ni = 0; ni < 4; ni++) {
                int dch = warp_n * 4 + ni;
                uint32_t off = (uint32_t)(vrow * 128 + ((dch ^ (vrow & 7)) << 4));
                ldsm2t(bH[ni], sb + 16384 + off);
                ldsm2t(bL[ni], sb + 24576 + off);
            }
#pragma unroll
            for (int ni = 0; ni < 4; ni++) {
                mma16816(acc[ni], aH, bH[ni]);
                mma16816(acc[ni], aL, bH[ni]);
                mma16816(acc[ni], aH, bL[ni]);
            }
        }
    };

    int nStages = tblk + 1;
    issue(0, 0);
    CP_COMMIT();
    if (nStages > 1) issue(1, 1);
    CP_COMMIT();
#pragma unroll 1
    for (int st = 0; st < nStages; st++) {
        CP_WAIT1();
        __syncthreads();
        compute(st % 3);
        if (st + 2 < nStages) issue(st + 2, (st + 2) % 3);
        CP_COMMIT();
    }

    int r4 = lane >> 2, cp2 = (lane & 3) * 2;
#pragma unroll
    for (int ni = 0; ni < 4; ni++) {
        int d = warp_n * 32 + ni * 8 + cp2;
        int t = t0 + warp_m * 16 + r4;
        size_t i0 = ((size_t)(b * Tn + t)) * Cc + o * 64 + d;
        split_store(g_y_h, g_y_l, i0,     acc[ni][0]);
        split_store(g_y_h, g_y_l, i0 + 1, acc[ni][1]);
        size_t i1 = ((size_t)(b * Tn + t + 8)) * Cc + o * 64 + d;
        split_store(g_y_h, g_y_l, i1,     acc[ni][2]);
        split_store(g_y_h, g_y_l, i1 + 1, acc[ni][3]);
    }
}

// ---------------- host launch ----------------
extern "C" void kernel_launch(void* const* d_in, const int* in_sizes, int n_in,
                              void* d_out, int out_size) {
    const float* x  = (const float*)d_in[0];
    const float* Wq = (const float*)d_in[1];
    const float* bq = (const float*)d_in[2];
    const float* Wk = (const float*)d_in[3];
    const float* bk = (const float*)d_in[4];
    const float* Wv = (const float*)d_in[5];
    const float* bv = (const float*)d_in[6];
    const float* tw = (const float*)d_in[7];
    const float* hm = (const float*)d_in[8];
    const float* Wp = (const float*)d_in[9];
    const float* bp = (const float*)d_in[10];
    float* out = (float*)d_out;

    static cudaStream_t s2 = nullptr;
    static cudaEvent_t evA = nullptr, evB = nullptr;
    if (!s2) {
        cudaFuncSetAttribute(proj_gemm_mma, cudaFuncAttributeMaxDynamicSharedMemorySize, PROJ_SMEM);
        cudaFuncSetAttribute(av_mma, cudaFuncAttributeMaxDynamicSharedMemorySize, AV_SMEM);
        cudaStreamCreateWithFlags(&s2, cudaStreamNonBlocking);
        cudaEventCreateWithFlags(&evA, cudaEventDisableTiming);
        cudaEventCreateWithFlags(&evB, cudaEventDisableTiming);
    }

    timeshift_kernel<<<(Bb * Tn * Cc) / 256, 256>>>(x);
    convert_w_kernel<<<(4 * Cc * Cc) / 256, 256>>>(Wq, Wk, Wv, Wp);
    cudaEventRecord(evA, 0);

    // branch: v projection on s2, concurrent with q/k proj + scores chain
    cudaStreamWaitEvent(s2, evA, 0);
    dim3 gproj(Cc / 128, (Bb * Tn) / 128);
    proj_gemm_mma<<<gproj, 256, PROJ_SMEM, s2>>>(bv, nullptr, 2);
    cudaEventRecord(evB, s2);

    proj_gemm_mma<<<gproj, 256, PROJ_SMEM>>>(bq, nullptr, 0);
    proj_gemm_mma<<<gproj, 256, PROJ_SMEM>>>(bk, nullptr, 1);

    dim3 gs(Tn / 64, Tn / 64, Bb * Hh);
    scores_mma<<<gs, 128>>>();

    reduce_inv_kernel<<<(Bb * Hh * Tn) / 256, 256>>>();

    dim3 gmx(Tn / 256, Tn, Bb);
    mixapply_kernel<<<gmx, 256>>>(tw, hm);

    cudaStreamWaitEvent(0, evB, 0);
    dim3 gav(Tn / 64, Bb * Hh);
    av_mma<<<gav, 256, AV_SMEM>>>();

    proj_gemm_mma<<<gproj, 256, PROJ_SMEM>>>(bp, out, 3);
}

// round 9
// speedup vs baseline: 3.0648x; 1.0353x over previous
#include <cuda_runtime.h>
#include <cuda_bf16.h>
#include <cuda_fp16.h>
#include <math.h>
#include <cstdint>

#define Bb 4
#define Tn 1024
#define Cc 1024
#define Hh 16
#define Dd 64
#define NELEM ((size_t)Bb * Tn * Cc)   // 4M

// ---------------- scratch (device globals) ----------------
__device__ float g_att[(size_t)Bb * Hh * Tn * Tn];   // fp32 raw scores (causal blocks)
__device__ float g_psum[(size_t)Bb * Hh * Tn * 16];  // per-(row, sblk) exp partial sums
__device__ float g_inv[(size_t)Bb * Hh * Tn];        // per-row 1/sum
__device__ __half g_am[(size_t)Bb * Hh * Tn * Tn];   // mixed att fp16 (causal-zeroed)

__device__ __nv_bfloat16 g_xs_h[NELEM];              // time-shifted input hi/lo
__device__ __nv_bfloat16 g_xs_l[NELEM];
__device__ __nv_bfloat16 g_y_h[NELEM];               // AV output [B,T,C] hi/lo
__device__ __nv_bfloat16 g_y_l[NELEM];
__device__ __nv_bfloat16 g_wh[4 * (size_t)Cc * Cc];  // weights q,k,v,p hi
__device__ __nv_bfloat16 g_wl[4 * (size_t)Cc * Cc];  // weights q,k,v,p lo

__device__ __nv_bfloat16 g_qh[(size_t)Bb * Hh * Tn * Dd];  // [bh][t][d]
__device__ __nv_bfloat16 g_ql[(size_t)Bb * Hh * Tn * Dd];
__device__ __nv_bfloat16 g_kh[(size_t)Bb * Hh * Tn * Dd];
__device__ __nv_bfloat16 g_kl[(size_t)Bb * Hh * Tn * Dd];
__device__ __half g_vh[(size_t)Bb * Hh * Tn * Dd];         // V fp16 hi/lo
__device__ __half g_vl[(size_t)Bb * Hh * Tn * Dd];

// ================= helpers =================
__device__ __forceinline__ uint32_t smem_to_u32(const void* p) {
    uint32_t a;
    asm("{ .reg .u64 t; cvta.to.shared.u64 t, %1; cvt.u32.u64 %0, t; }" : "=r"(a) : "l"(p));
    return a;
}
#define CP16(dst, src) \
    asm volatile("cp.async.cg.shared.global [%0], [%1], 16;" :: "r"(dst), "l"(src) : "memory")
#define CP_COMMIT() asm volatile("cp.async.commit_group;" ::: "memory")
#define CP_WAIT0() asm volatile("cp.async.wait_group 0;" ::: "memory")
#define CP_WAIT1() asm volatile("cp.async.wait_group 1;" ::: "memory")

__device__ __forceinline__ void ldsm4(uint32_t* r, uint32_t addr) {
    asm volatile("ldmatrix.sync.aligned.m8n8.x4.shared.b16 {%0,%1,%2,%3}, [%4];"
                 : "=r"(r[0]), "=r"(r[1]), "=r"(r[2]), "=r"(r[3]) : "r"(addr));
}
__device__ __forceinline__ void ldsm2(uint32_t* r, uint32_t addr) {
    asm volatile("ldmatrix.sync.aligned.m8n8.x2.shared.b16 {%0,%1}, [%2];"
                 : "=r"(r[0]), "=r"(r[1]) : "r"(addr));
}
__device__ __forceinline__ void ldsm2t(uint32_t* r, uint32_t addr) {
    asm volatile("ldmatrix.sync.aligned.m8n8.x2.trans.shared.b16 {%0,%1}, [%2];"
                 : "=r"(r[0]), "=r"(r[1]) : "r"(addr));
}
__device__ __forceinline__ void mma16816(float* c, const uint32_t* a, const uint32_t* b) {
    asm volatile("mma.sync.aligned.m16n8k16.row.col.f32.bf16.bf16.f32 "
                 "{%0,%1,%2,%3}, {%4,%5,%6,%7}, {%8,%9}, {%0,%1,%2,%3};"
                 : "+f"(c[0]), "+f"(c[1]), "+f"(c[2]), "+f"(c[3])
                 : "r"(a[0]), "r"(a[1]), "r"(a[2]), "r"(a[3]), "r"(b[0]), "r"(b[1]));
}
__device__ __forceinline__ void mma16816h(float* c, const uint32_t* a, const uint32_t* b) {
    asm volatile("mma.sync.aligned.m16n8k16.row.col.f32.f16.f16.f32 "
                 "{%0,%1,%2,%3}, {%4,%5,%6,%7}, {%8,%9}, {%0,%1,%2,%3};"
                 : "+f"(c[0]), "+f"(c[1]), "+f"(c[2]), "+f"(c[3])
                 : "r"(a[0]), "r"(a[1]), "r"(a[2]), "r"(a[3]), "r"(b[0]), "r"(b[1]));
}
__device__ __forceinline__ void split_store(__nv_bfloat16* ph, __nv_bfloat16* pl, size_t idx, float v) {
    __nv_bfloat16 h = __float2bfloat16_rn(v);
    ph[idx] = h;
    pl[idx] = __float2bfloat16_rn(v - __bfloat162float(h));
}
__device__ __forceinline__ void split_store_h(__half* ph, __half* pl, size_t idx, float v) {
    __half h = __float2half_rn(v);
    ph[idx] = h;
    pl[idx] = __float2half_rn(v - __half2float(h));
}

// ---------------- 1) time shift -> bf16 hi/lo ----------------
__global__ __launch_bounds__(256) void timeshift_kernel(const float* __restrict__ x) {
    int idx = blockIdx.x * blockDim.x + threadIdx.x;
    int c = idx & (Cc - 1);
    int t = (idx >> 10) & (Tn - 1);
    int b = idx >> 20;
    float val;
    if (c < Cc / 2) {
        val = (t == 0) ? 0.f : x[((size_t)b * Tn + (t - 1)) * Cc + c];
    } else {
        val = x[((size_t)b * Tn + t) * Cc + c];
    }
    split_store(g_xs_h, g_xs_l, idx, val);
}

// ---------------- 1b) weight conversion -> bf16 hi/lo ----------------
__global__ __launch_bounds__(256) void convert_w_kernel(const float* __restrict__ Wq,
                                                        const float* __restrict__ Wk,
                                                        const float* __restrict__ Wv,
                                                        const float* __restrict__ Wp) {
    size_t idx = (size_t)blockIdx.x * blockDim.x + threadIdx.x;
    int which = (int)(idx >> 20);
    size_t off = idx & ((size_t)Cc * Cc - 1);
    const float* W = (which == 0) ? Wq : (which == 1) ? Wk : (which == 2) ? Wv : Wp;
    split_store(g_wh, g_wl, idx, W[off]);
}

// ================= 2/7) bf16-split mma.sync projection GEMM, 2-stage pipeline =================
#define STAGE_BYTES 32768
#define PROJ_SMEM (2 * STAGE_BYTES)

__global__ __launch_bounds__(256) void proj_gemm_mma(const float* __restrict__ bias,
                                                     float* __restrict__ outflat, int which) {
    extern __shared__ char smem[];
    uint32_t sbase = smem_to_u32(smem);
    const __nv_bfloat16* gAh = (which == 3) ? g_y_h : g_xs_h;
    const __nv_bfloat16* gAl = (which == 3) ? g_y_l : g_xs_l;
    const __nv_bfloat16* gWh = g_wh + (size_t)which * Cc * Cc;
    const __nv_bfloat16* gWl = g_wl + (size_t)which * Cc * Cc;

    int tid = threadIdx.x, lane = tid & 31, wid = tid >> 5;
    int warp_m = wid & 1, warp_n = wid >> 1;
    int m0 = blockIdx.y * 128, n0 = blockIdx.x * 128;

    int rtid = tid >> 2;
    int ctid = tid & 3;

    int a_row_off = (lane & 7) + ((lane >> 3) & 1) * 8;
    int a_chunk = lane >> 4;
    int b_row_off = lane & 7;
    int b_chunk = (lane >> 3) & 1;

    uint32_t aBase[4], aSw[4], bBase[4], bSw[4];
#pragma unroll
    for (int mi = 0; mi < 4; mi++) {
        int r = warp_m * 64 + mi * 16 + a_row_off;
        aBase[mi] = (uint32_t)(r * 64);
        aSw[mi] = (uint32_t)((r >> 1) & 3);
    }
#pragma unroll
    for (int ni = 0; ni < 4; ni++) {
        int r = warp_n * 32 + ni * 8 + b_row_off;
        bBase[ni] = (uint32_t)(r * 64);
        bSw[ni] = (uint32_t)((r >> 1) & 3);
    }

    float acc[4][4][4];
#pragma unroll
    for (int mi = 0; mi < 4; mi++)
#pragma unroll
        for (int ni = 0; ni < 4; ni++)
#pragma unroll
            for (int j = 0; j < 4; j++) acc[mi][ni][j] = 0.f;

    auto issue = [&](int chunk, int stage) {
        int k0 = chunk * 32;
        uint32_t sb = sbase + (uint32_t)stage * STAGE_BYTES;
#pragma unroll
        for (int j = 0; j < 2; j++) {
            int row = rtid + j * 64;
            uint32_t dof = (uint32_t)(row * 64 + ((ctid ^ ((row >> 1) & 3)) << 4));
            size_t ga = (size_t)(m0 + row) * Cc + k0 + ctid * 8;
            size_t gw = (size_t)(n0 + row) * Cc + k0 + ctid * 8;
            CP16(sb + dof,         gAh + ga);
            CP16(sb + 8192 + dof,  gAl + ga);
            CP16(sb + 16384 + dof, gWh + gw);
            CP16(sb + 24576 + dof, gWl + gw);
        }
    };

    auto compute = [&](int stage) {
        uint32_t sb = sbase + (uint32_t)stage * STAGE_BYTES;
#pragma unroll
        for (int ks = 0; ks < 2; ks++) {
            uint32_t aH[4][4], aL[4][4], bH[4][2], bL[4][2];
#pragma unroll
            for (int mi = 0; mi < 4; mi++) {
                uint32_t off = aBase[mi] + ((((uint32_t)(ks * 2) + a_chunk) ^ aSw[mi]) << 4);
                ldsm4(aH[mi], sb + off);
                ldsm4(aL[mi], sb + 8192 + off);
            }
#pragma unroll
            for (int ni = 0; ni < 4; ni++) {
                uint32_t off = bBase[ni] + ((((uint32_t)(ks * 2) + b_chunk) ^ bSw[ni]) << 4);
                ldsm2(bH[ni], sb + 16384 + off);
                ldsm2(bL[ni], sb + 24576 + off);
            }
#pragma unroll
            for (int mi = 0; mi < 4; mi++)
#pragma unroll
                for (int ni = 0; ni < 4; ni++) {
                    mma16816(acc[mi][ni], aH[mi], bH[ni]);
                    mma16816(acc[mi][ni], aH[mi], bL[ni]);
                    mma16816(acc[mi][ni], aL[mi], bH[ni]);
                }
        }
    };

    const int NCH = Cc / 32;
    issue(0, 0);
    CP_COMMIT();
#pragma unroll 1
    for (int c = 0; c < NCH; c++) {
        if (c + 1 < NCH) {
            issue(c + 1, (c + 1) & 1);
            CP_COMMIT();
            CP_WAIT1();
        } else {
            CP_WAIT0();
        }
        __syncthreads();
        compute(c & 1);
        __syncthreads();
    }

    // epilogue
    int r4 = lane >> 2;
    int cp2 = (lane & 3) * 2;
#pragma unroll
    for (int ni = 0; ni < 4; ni++) {
        int n = n0 + warp_n * 32 + ni * 8 + cp2;
        float b0 = bias[n], b1 = bias[n + 1];
#pragma unroll
        for (int mi = 0; mi < 4; mi++) {
            int mA = m0 + warp_m * 64 + mi * 16 + r4;
            float v00 = acc[mi][ni][0] + b0, v01 = acc[mi][ni][1] + b1;
            float v10 = acc[mi][ni][2] + b0, v11 = acc[mi][ni][3] + b1;
            if (which == 3) {
                *reinterpret_cast<float2*>(&outflat[(size_t)mA * Cc + n]) = make_float2(v00, v01);
                *reinterpret_cast<float2*>(&outflat[(size_t)(mA + 8) * Cc + n]) = make_float2(v10, v11);
            } else {
                int h = n >> 6, d = n & 63;
                int b_ = mA >> 10, t = mA & 1023;
                size_t i0 = (((size_t)(b_ * Hh + h)) * Tn + t) * Dd + d;
                int m2 = mA + 8;
                int b2 = m2 >> 10, t2 = m2 & 1023;
                size_t i1 = (((size_t)(b2 * Hh + h)) * Tn + t2) * Dd + d;
                if (which == 2) {
                    split_store_h(g_vh, g_vl, i0,     v00);
                    split_store_h(g_vh, g_vl, i0 + 1, v01);
                    split_store_h(g_vh, g_vl, i1,     v10);
                    split_store_h(g_vh, g_vl, i1 + 1, v11);
                } else {
                    __nv_bfloat16* ph = (which == 0) ? g_qh : g_kh;
                    __nv_bfloat16* pl = (which == 0) ? g_ql : g_kl;
                    split_store(ph, pl, i0,     v00);
                    split_store(ph, pl, i0 + 1, v01);
                    split_store(ph, pl, i1,     v10);
                    split_store(ph, pl, i1 + 1, v11);
                }
            }
        }
    }
}

// ================= 3) scores via bf16-split MMA: S = QK^T / 8, + masked exp partial sums =================
__global__ __launch_bounds__(128) void scores_mma() {
    int sblk = blockIdx.x, tblk = blockIdx.y, bh = blockIdx.z;
    if (sblk > tblk) return;
    __shared__ char smem[4 * 8192];   // Qh Ql Kh Kl (64 rows x 128B each)
    __shared__ float rowsum[64][2];
    uint32_t sb = smem_to_u32(smem);

    int tid = threadIdx.x, lane = tid & 31, wid = tid >> 5;
    int warp_m = wid & 1, warp_n = wid >> 1;
    int t0 = tblk * 64, s0 = sblk * 64;

    const __nv_bfloat16* srcs[4] = {
        g_qh + ((size_t)bh * Tn + t0) * Dd,
        g_ql + ((size_t)bh * Tn + t0) * Dd,
        g_kh + ((size_t)bh * Tn + s0) * Dd,
        g_kl + ((size_t)bh * Tn + s0) * Dd };
#pragma unroll
    for (int a = 0; a < 4; a++) {
        const __nv_bfloat16* s = srcs[a];
        for (int i = tid; i < 512; i += 128) {
            int row = i >> 3, ch = i & 7;
            uint32_t off = (uint32_t)(row * 128 + ((ch ^ (row & 7)) << 4));
            *reinterpret_cast<uint4*>(smem + a * 8192 + off) =
                *reinterpret_cast<const uint4*>(s + row * 64 + ch * 8);
        }
    }
    __syncthreads();

    int a_row = warp_m * 32 + ((lane >> 3) & 1) * 8 + (lane & 7);
    int a_ch  = lane >> 4;
    int b_row = warp_n * 32 + (lane & 7);
    int b_ch  = (lane >> 3) & 1;

    float acc[2][4][4];
#pragma unroll
    for (int mi = 0; mi < 2; mi++)
#pragma unroll
        for (int ni = 0; ni < 4; ni++)
#pragma unroll
            for (int j = 0; j < 4; j++) acc[mi][ni][j] = 0.f;

#pragma unroll
    for (int ks = 0; ks < 4; ks++) {
        uint32_t aH[2][4], aL[2][4], bH[4][2], bL[4][2];
#pragma unroll
        for (int mi = 0; mi < 2; mi++) {
            int r = a_row + mi * 16;
            uint32_t off = (uint32_t)(r * 128 + (((ks * 2 + a_ch) ^ (r & 7)) << 4));
            ldsm4(aH[mi], sb + off);
            ldsm4(aL[mi], sb + 8192 + off);
        }
#pragma unroll
        for (int ni = 0; ni < 4; ni++) {
            int r = b_row + ni * 8;
            uint32_t off = (uint32_t)(r * 128 + (((ks * 2 + b_ch) ^ (r & 7)) << 4));
            ldsm2(bH[ni], sb + 16384 + off);
            ldsm2(bL[ni], sb + 24576 + off);
        }
#pragma unroll
        for (int mi = 0; mi < 2; mi++)
#pragma unroll
            for (int ni = 0; ni < 4; ni++) {
                mma16816(acc[mi][ni], aH[mi], bH[ni]);
                mma16816(acc[mi][ni], aH[mi], bL[ni]);
                mma16816(acc[mi][ni], aL[mi], bH[ni]);
            }
    }

    float* S = g_att + (size_t)bh * Tn * Tn;
    int r4 = lane >> 2, cp2 = (lane & 3) * 2;
    float esum[2][2] = {};
#pragma unroll
    for (int mi = 0; mi < 2; mi++) {
        int t = t0 + warp_m * 32 + mi * 16 + r4;
#pragma unroll
        for (int ni = 0; ni < 4; ni++) {
            int s = s0 + warp_n * 32 + ni * 8 + cp2;
            float v0 = acc[mi][ni][0] * 0.125f, v1 = acc[mi][ni][1] * 0.125f;
            float v2 = acc[mi][ni][2] * 0.125f, v3 = acc[mi][ni][3] * 0.125f;
            *reinterpret_cast<float2*>(&S[(size_t)t * Tn + s]) = make_float2(v0, v1);
            *reinterpret_cast<float2*>(&S[(size_t)(t + 8) * Tn + s]) = make_float2(v2, v3);
            esum[mi][0] += (s     <= t    ? __expf(v0) : 0.f) + (s + 1 <= t     ? __expf(v1) : 0.f);
            esum[mi][1] += (s     <= t + 8 ? __expf(v2) : 0.f) + (s + 1 <= t + 8 ? __expf(v3) : 0.f);
        }
    }
#pragma unroll
    for (int mi = 0; mi < 2; mi++)
#pragma unroll
        for (int hf = 0; hf < 2; hf++) {
            float v = esum[mi][hf];
            v += __shfl_xor_sync(0xffffffffu, v, 1);
            v += __shfl_xor_sync(0xffffffffu, v, 2);
            esum[mi][hf] = v;
        }
    if ((lane & 3) == 0) {
#pragma unroll
        for (int mi = 0; mi < 2; mi++)
#pragma unroll
            for (int hf = 0; hf < 2; hf++)
                rowsum[warp_m * 32 + mi * 16 + hf * 8 + r4][warp_n] = esum[mi][hf];
    }
    __syncthreads();
    if (tid < 64)
        g_psum[(((size_t)bh * Tn) + t0 + tid) * 16 + sblk] = rowsum[tid][0] + rowsum[tid][1];
}

// ---------------- 4) reduce partials -> 1/sum per row ----------------
__global__ __launch_bounds__(256) void reduce_inv_kernel() {
    int idx = blockIdx.x * blockDim.x + threadIdx.x;   // bh*Tn + t
    int t = idx & (Tn - 1);
    int nblk = (t >> 6) + 1;
    const float* p = g_psum + (size_t)idx * 16;
    float S = 0.f;
    for (int i = 0; i < nblk; i++) S += p[i];
    g_inv[idx] = 1.0f / S;
}

// ---------------- 5) apply exp*inv*tw + head mix -> fp16, causal-zeroed ----------------
__global__ __launch_bounds__(256) void mixapply_kernel(const float* __restrict__ tw,
                                                       const float* __restrict__ Mx) {
    int chunk = blockIdx.x, t = blockIdx.y, b = blockIdx.z;
    int s0 = chunk * 256;
    if (s0 > t) return;            // beyond causal: g_am stays 0 (never written)
    __shared__ float Ms[256];
    __shared__ float st[16];
    int tid = threadIdx.x;
    Ms[tid] = Mx[tid];
    if (tid < 16) st[tid] = g_inv[((size_t)(b * Hh + tid)) * Tn + t];
    __syncthreads();

    int s = s0 + tid;
    bool valid = s <= t;
    float vals[16];
#pragma unroll
    for (int h = 0; h < Hh; h++) {
        float x = g_att[(((size_t)(b * Hh + h)) * Tn + t) * Tn + s];
        float w = tw[(((size_t)h * Tn) + t) * Tn + s];
        vals[h] = valid ? __expf(x) * st[h] * w : 0.f;
    }
#pragma unroll
    for (int o = 0; o < Hh; o++) {
        float a = 0.f;
#pragma unroll
        for (int h = 0; h < Hh; h++) a = fmaf(Ms[o * 16 + h], vals[h], a);
        g_am[(((size_t)(b * Hh + o)) * Tn + t) * Tn + s] = __float2half_rn(a);
    }
}

// ================= 6) AV via fp16 MMA (att single, V hi/lo), 3-stage cp.async =================
#define AV_STAGE 24576
#define AV_SMEM (3 * AV_STAGE)
__global__ __launch_bounds__(256) void av_mma() {
    int tblk = blockIdx.x, bo = blockIdx.y;
    int b = bo >> 4, o = bo & 15;
    int t0 = tblk * 64;
    extern __shared__ char smem[];
    uint32_t sbase = smem_to_u32(smem);

    int tid = threadIdx.x, lane = tid & 31, wid = tid >> 5;
    int warp_m = wid & 3, warp_n = wid >> 2;   // 4 x 2 warp grid, warp tile 16(t) x 32(d)

    int a_row = warp_m * 16 + ((lane >> 3) & 1) * 8 + (lane & 7);
    int a_ch  = lane >> 4;
    int v_lrow = ((lane >> 3) & 1) * 8 + (lane & 7);

    float acc[4][4];
#pragma unroll
    for (int ni = 0; ni < 4; ni++)
#pragma unroll
        for (int j = 0; j < 4; j++) acc[ni][j] = 0.f;

    const __half* Am = g_am + ((size_t)bo * Tn + t0) * Tn;
    const __half* Vh = g_vh + (size_t)bo * Tn * Dd;
    const __half* Vl = g_vl + (size_t)bo * Tn * Dd;

    auto issue = [&](int st, int stage) {
        int s0 = st * 64;
        uint32_t sb = sbase + (uint32_t)stage * AV_STAGE;
#pragma unroll
        for (int j = 0; j < 2; j++) {
            int i = tid + j * 256;
            int row = i >> 3, ch = i & 7;
            uint32_t off = (uint32_t)(row * 128 + ((ch ^ (row & 7)) << 4));
            CP16(sb + off,         Am + (size_t)row * Tn + s0 + ch * 8);
            CP16(sb + 8192 + off,  Vh + (size_t)(s0 + row) * Dd + ch * 8);
            CP16(sb + 16384 + off, Vl + (size_t)(s0 + row) * Dd + ch * 8);
        }
    };

    auto compute = [&](int stage) {
        uint32_t sb = sbase + (uint32_t)stage * AV_STAGE;
#pragma unroll
        for (int ks = 0; ks < 4; ks++) {
            uint32_t aF[4], bH[4][2], bL[4][2];
            {
                int r = a_row;
                uint32_t off = (uint32_t)(r * 128 + (((ks * 2 + a_ch) ^ (r & 7)) << 4));
                ldsm4(aF, sb + off);
            }
            int vrow = ks * 16 + v_lrow;
#pragma unroll
            for (int ni = 0; ni < 4; ni++) {
                int dch = warp_n * 4 + ni;
                uint32_t off = (uint32_t)(vrow * 128 + ((dch ^ (vrow & 7)) << 4));
                ldsm2t(bH[ni], sb + 8192 + off);
                ldsm2t(bL[ni], sb + 16384 + off);
            }
#pragma unroll
            for (int ni = 0; ni < 4; ni++) {
                mma16816h(acc[ni], aF, bH[ni]);
                mma16816h(acc[ni], aF, bL[ni]);
            }
        }
    };

    int nStages = tblk + 1;
    issue(0, 0);
    CP_COMMIT();
    if (nStages > 1) issue(1, 1);
    CP_COMMIT();
#pragma unroll 1
    for (int st = 0; st < nStages; st++) {
        CP_WAIT1();
        __syncthreads();
        compute(st % 3);
        if (st + 2 < nStages) issue(st + 2, (st + 2) % 3);
        CP_COMMIT();
    }

    int r4 = lane >> 2, cp2 = (lane & 3) * 2;
#pragma unroll
    for (int ni = 0; ni < 4; ni++) {
        int d = warp_n * 32 + ni * 8 + cp2;
        int t = t0 + warp_m * 16 + r4;
        size_t i0 = ((size_t)(b * Tn + t)) * Cc + o * 64 + d;
        split_store(g_y_h, g_y_l, i0,     acc[ni][0]);
        split_store(g_y_h, g_y_l, i0 + 1, acc[ni][1]);
        size_t i1 = ((size_t)(b * Tn + t + 8)) * Cc + o * 64 + d;
        split_store(g_y_h, g_y_l, i1,     acc[ni][2]);
        split_store(g_y_h, g_y_l, i1 + 1, acc[ni][3]);
    }
}

// ---------------- host launch ----------------
extern "C" void kernel_launch(void* const* d_in, const int* in_sizes, int n_in,
                              void* d_out, int out_size) {
    const float* x  = (const float*)d_in[0];
    const float* Wq = (const float*)d_in[1];
    const float* bq = (const float*)d_in[2];
    const float* Wk = (const float*)d_in[3];
    const float* bk = (const float*)d_in[4];
    const float* Wv = (const float*)d_in[5];
    const float* bv = (const float*)d_in[6];
    const float* tw = (const float*)d_in[7];
    const float* hm = (const float*)d_in[8];
    const float* Wp = (const float*)d_in[9];
    const float* bp = (const float*)d_in[10];
    float* out = (float*)d_out;

    static cudaStream_t s2 = nullptr;
    static cudaEvent_t evA = nullptr, evB = nullptr;
    if (!s2) {
        cudaFuncSetAttribute(proj_gemm_mma, cudaFuncAttributeMaxDynamicSharedMemorySize, PROJ_SMEM);
        cudaFuncSetAttribute(av_mma, cudaFuncAttributeMaxDynamicSharedMemorySize, AV_SMEM);
        cudaStreamCreateWithFlags(&s2, cudaStreamNonBlocking);
        cudaEventCreateWithFlags(&evA, cudaEventDisableTiming);
        cudaEventCreateWithFlags(&evB, cudaEventDisableTiming);
    }

    timeshift_kernel<<<(Bb * Tn * Cc) / 256, 256>>>(x);
    convert_w_kernel<<<(4 * Cc * Cc) / 256, 256>>>(Wq, Wk, Wv, Wp);
    cudaEventRecord(evA, 0);

    // branch: v projection on s2, concurrent with q/k proj + scores chain
    cudaStreamWaitEvent(s2, evA, 0);
    dim3 gproj(Cc / 128, (Bb * Tn) / 128);
    proj_gemm_mma<<<gproj, 256, PROJ_SMEM, s2>>>(bv, nullptr, 2);
    cudaEventRecord(evB, s2);

    proj_gemm_mma<<<gproj, 256, PROJ_SMEM>>>(bq, nullptr, 0);
    proj_gemm_mma<<<gproj, 256, PROJ_SMEM>>>(bk, nullptr, 1);

    dim3 gs(Tn / 64, Tn / 64, Bb * Hh);
    scores_mma<<<gs, 128>>>();

    reduce_inv_kernel<<<(Bb * Hh * Tn) / 256, 256>>>();

    dim3 gmx(Tn / 256, Tn, Bb);
    mixapply_kernel<<<gmx, 256>>>(tw, hm);

    cudaStreamWaitEvent(0, evB, 0);
    dim3 gav(Tn / 64, Bb * Hh);
    av_mma<<<gav, 256, AV_SMEM>>>();

    proj_gemm_mma<<<gproj, 256, PROJ_SMEM>>>(bp, out, 3);
}

// round 14
// speedup vs baseline: 3.0875x; 1.0074x over previous
#include <cuda_runtime.h>
#include <cuda_bf16.h>
#include <cuda_fp16.h>
#include <math.h>
#include <cstdint>

#define Bb 4
#define Tn 1024
#define Cc 1024
#define Hh 16
#define Dd 64
#define NELEM ((size_t)Bb * Tn * Cc)   // 4M

// ---------------- scratch (device globals) ----------------
__device__ float g_att[(size_t)Bb * Hh * Tn * Tn];   // fp32 raw scores (causal blocks)
__device__ float g_psum[(size_t)Bb * Hh * Tn * 16];  // per-(row, sblk) exp partial sums
__device__ float g_inv[(size_t)Bb * Hh * Tn];        // per-row 1/sum
__device__ __half g_am[(size_t)Bb * Hh * Tn * Tn];   // mixed att fp16 (causal-zeroed)

__device__ __nv_bfloat16 g_xs_h[NELEM];              // time-shifted input hi/lo
__device__ __nv_bfloat16 g_xs_l[NELEM];
__device__ __nv_bfloat16 g_y_h[NELEM];               // AV output [B,T,C] hi/lo
__device__ __nv_bfloat16 g_y_l[NELEM];
__device__ __nv_bfloat16 g_wh[4 * (size_t)Cc * Cc];  // weights q,k,v,p hi
__device__ __nv_bfloat16 g_wl[4 * (size_t)Cc * Cc];  // weights q,k,v,p lo

__device__ __nv_bfloat16 g_qh[(size_t)Bb * Hh * Tn * Dd];  // [bh][t][d]
__device__ __nv_bfloat16 g_ql[(size_t)Bb * Hh * Tn * Dd];
__device__ __nv_bfloat16 g_kh[(size_t)Bb * Hh * Tn * Dd];
__device__ __nv_bfloat16 g_kl[(size_t)Bb * Hh * Tn * Dd];
__device__ __half g_vh[(size_t)Bb * Hh * Tn * Dd];         // V fp16 hi/lo
__device__ __half g_vl[(size_t)Bb * Hh * Tn * Dd];

// ================= helpers =================
__device__ __forceinline__ uint32_t smem_to_u32(const void* p) {
    uint32_t a;
    asm("{ .reg .u64 t; cvta.to.shared.u64 t, %1; cvt.u32.u64 %0, t; }" : "=r"(a) : "l"(p));
    return a;
}
#define CP16(dst, src) \
    asm volatile("cp.async.cg.shared.global [%0], [%1], 16;" :: "r"(dst), "l"(src) : "memory")
#define CP_COMMIT() asm volatile("cp.async.commit_group;" ::: "memory")
#define CP_WAIT0() asm volatile("cp.async.wait_group 0;" ::: "memory")
#define CP_WAIT1() asm volatile("cp.async.wait_group 1;" ::: "memory")

__device__ __forceinline__ void ldsm4(uint32_t* r, uint32_t addr) {
    asm volatile("ldmatrix.sync.aligned.m8n8.x4.shared.b16 {%0,%1,%2,%3}, [%4];"
                 : "=r"(r[0]), "=r"(r[1]), "=r"(r[2]), "=r"(r[3]) : "r"(addr));
}
__device__ __forceinline__ void ldsm2(uint32_t* r, uint32_t addr) {
    asm volatile("ldmatrix.sync.aligned.m8n8.x2.shared.b16 {%0,%1}, [%2];"
                 : "=r"(r[0]), "=r"(r[1]) : "r"(addr));
}
__device__ __forceinline__ void ldsm2t(uint32_t* r, uint32_t addr) {
    asm volatile("ldmatrix.sync.aligned.m8n8.x2.trans.shared.b16 {%0,%1}, [%2];"
                 : "=r"(r[0]), "=r"(r[1]) : "r"(addr));
}
__device__ __forceinline__ void mma16816(float* c, const uint32_t* a, const uint32_t* b) {
    asm volatile("mma.sync.aligned.m16n8k16.row.col.f32.bf16.bf16.f32 "
                 "{%0,%1,%2,%3}, {%4,%5,%6,%7}, {%8,%9}, {%0,%1,%2,%3};"
                 : "+f"(c[0]), "+f"(c[1]), "+f"(c[2]), "+f"(c[3])
                 : "r"(a[0]), "r"(a[1]), "r"(a[2]), "r"(a[3]), "r"(b[0]), "r"(b[1]));
}
__device__ __forceinline__ void mma16816h(float* c, const uint32_t* a, const uint32_t* b) {
    asm volatile("mma.sync.aligned.m16n8k16.row.col.f32.f16.f16.f32 "
                 "{%0,%1,%2,%3}, {%4,%5,%6,%7}, {%8,%9}, {%0,%1,%2,%3};"
                 : "+f"(c[0]), "+f"(c[1]), "+f"(c[2]), "+f"(c[3])
                 : "r"(a[0]), "r"(a[1]), "r"(a[2]), "r"(a[3]), "r"(b[0]), "r"(b[1]));
}
__device__ __forceinline__ void split_store(__nv_bfloat16* ph, __nv_bfloat16* pl, size_t idx, float v) {
    __nv_bfloat16 h = __float2bfloat16_rn(v);
    ph[idx] = h;
    pl[idx] = __float2bfloat16_rn(v - __bfloat162float(h));
}
__device__ __forceinline__ void split_store_h(__half* ph, __half* pl, size_t idx, float v) {
    __half h = __float2half_rn(v);
    ph[idx] = h;
    pl[idx] = __float2half_rn(v - __half2float(h));
}

// ---------------- 1) time shift -> bf16 hi/lo ----------------
__global__ __launch_bounds__(256) void timeshift_kernel(const float* __restrict__ x) {
    int idx = blockIdx.x * blockDim.x + threadIdx.x;
    int c = idx & (Cc - 1);
    int t = (idx >> 10) & (Tn - 1);
    int b = idx >> 20;
    float val;
    if (c < Cc / 2) {
        val = (t == 0) ? 0.f : x[((size_t)b * Tn + (t - 1)) * Cc + c];
    } else {
        val = x[((size_t)b * Tn + t) * Cc + c];
    }
    split_store(g_xs_h, g_xs_l, idx, val);
}

// ---------------- 1b) weight conversion -> bf16 hi/lo ----------------
__global__ __launch_bounds__(256) void convert_w_kernel(const float* __restrict__ Wq,
                                                        const float* __restrict__ Wk,
                                                        const float* __restrict__ Wv,
                                                        const float* __restrict__ Wp) {
    size_t idx = (size_t)blockIdx.x * blockDim.x + threadIdx.x;
    int which = (int)(idx >> 20);
    size_t off = idx & ((size_t)Cc * Cc - 1);
    const float* W = (which == 0) ? Wq : (which == 1) ? Wk : (which == 2) ? Wv : Wp;
    split_store(g_wh, g_wl, idx, W[off]);
}

// ================= 2/7) bf16-split mma.sync projection GEMM, 2-stage pipeline =================
#define STAGE_BYTES 32768
#define PROJ_SMEM (2 * STAGE_BYTES)

__global__ __launch_bounds__(256) void proj_gemm_mma(const float* __restrict__ bias,
                                                     float* __restrict__ outflat, int which) {
    extern __shared__ char smem[];
    uint32_t sbase = smem_to_u32(smem);
    const __nv_bfloat16* gAh = (which == 3) ? g_y_h : g_xs_h;
    const __nv_bfloat16* gAl = (which == 3) ? g_y_l : g_xs_l;
    const __nv_bfloat16* gWh = g_wh + (size_t)which * Cc * Cc;
    const __nv_bfloat16* gWl = g_wl + (size_t)which * Cc * Cc;

    int tid = threadIdx.x, lane = tid & 31, wid = tid >> 5;
    int warp_m = wid & 1, warp_n = wid >> 1;
    int m0 = blockIdx.y * 128, n0 = blockIdx.x * 128;

    int rtid = tid >> 2;
    int ctid = tid & 3;

    int a_row_off = (lane & 7) + ((lane >> 3) & 1) * 8;
    int a_chunk = lane >> 4;
    int b_row_off = lane & 7;
    int b_chunk = (lane >> 3) & 1;

    uint32_t aBase[4], aSw[4], bBase[4], bSw[4];
#pragma unroll
    for (int mi = 0; mi < 4; mi++) {
        int r = warp_m * 64 + mi * 16 + a_row_off;
        aBase[mi] = (uint32_t)(r * 64);
        aSw[mi] = (uint32_t)((r >> 1) & 3);
    }
#pragma unroll
    for (int ni = 0; ni < 4; ni++) {
        int r = warp_n * 32 + ni * 8 + b_row_off;
        bBase[ni] = (uint32_t)(r * 64);
        bSw[ni] = (uint32_t)((r >> 1) & 3);
    }

    float acc[4][4][4];
#pragma unroll
    for (int mi = 0; mi < 4; mi++)
#pragma unroll
        for (int ni = 0; ni < 4; ni++)
#pragma unroll
            for (int j = 0; j < 4; j++) acc[mi][ni][j] = 0.f;

    auto issue = [&](int chunk, int stage) {
        int k0 = chunk * 32;
        uint32_t sb = sbase + (uint32_t)stage * STAGE_BYTES;
#pragma unroll
        for (int j = 0; j < 2; j++) {
            int row = rtid + j * 64;
            uint32_t dof = (uint32_t)(row * 64 + ((ctid ^ ((row >> 1) & 3)) << 4));
            size_t ga = (size_t)(m0 + row) * Cc + k0 + ctid * 8;
            size_t gw = (size_t)(n0 + row) * Cc + k0 + ctid * 8;
            CP16(sb + dof,         gAh + ga);
            CP16(sb + 8192 + dof,  gAl + ga);
            CP16(sb + 16384 + dof, gWh + gw);
            CP16(sb + 24576 + dof, gWl + gw);
        }
    };

    auto compute = [&](int stage) {
        uint32_t sb = sbase + (uint32_t)stage * STAGE_BYTES;
#pragma unroll
        for (int ks = 0; ks < 2; ks++) {
            uint32_t aH[4][4], aL[4][4], bH[4][2], bL[4][2];
#pragma unroll
            for (int mi = 0; mi < 4; mi++) {
                uint32_t off = aBase[mi] + ((((uint32_t)(ks * 2) + a_chunk) ^ aSw[mi]) << 4);
                ldsm4(aH[mi], sb + off);
                ldsm4(aL[mi], sb + 8192 + off);
            }
#pragma unroll
            for (int ni = 0; ni < 4; ni++) {
                uint32_t off = bBase[ni] + ((((uint32_t)(ks * 2) + b_chunk) ^ bSw[ni]) << 4);
                ldsm2(bH[ni], sb + 16384 + off);
                ldsm2(bL[ni], sb + 24576 + off);
            }
#pragma unroll
            for (int mi = 0; mi < 4; mi++)
#pragma unroll
                for (int ni = 0; ni < 4; ni++) {
                    mma16816(acc[mi][ni], aH[mi], bH[ni]);
                    mma16816(acc[mi][ni], aH[mi], bL[ni]);
                    mma16816(acc[mi][ni], aL[mi], bH[ni]);
                }
        }
    };

    const int NCH = Cc / 32;
    issue(0, 0);
    CP_COMMIT();
#pragma unroll 1
    for (int c = 0; c < NCH; c++) {
        if (c + 1 < NCH) {
            issue(c + 1, (c + 1) & 1);
            CP_COMMIT();
            CP_WAIT1();
        } else {
            CP_WAIT0();
        }
        __syncthreads();
        compute(c & 1);
        __syncthreads();
    }

    // epilogue
    int r4 = lane >> 2;
    int cp2 = (lane & 3) * 2;
#pragma unroll
    for (int ni = 0; ni < 4; ni++) {
        int n = n0 + warp_n * 32 + ni * 8 + cp2;
        float b0 = bias[n], b1 = bias[n + 1];
#pragma unroll
        for (int mi = 0; mi < 4; mi++) {
            int mA = m0 + warp_m * 64 + mi * 16 + r4;
            float v00 = acc[mi][ni][0] + b0, v01 = acc[mi][ni][1] + b1;
            float v10 = acc[mi][ni][2] + b0, v11 = acc[mi][ni][3] + b1;
            if (which == 3) {
                *reinterpret_cast<float2*>(&outflat[(size_t)mA * Cc + n]) = make_float2(v00, v01);
                *reinterpret_cast<float2*>(&outflat[(size_t)(mA + 8) * Cc + n]) = make_float2(v10, v11);
            } else {
                int h = n >> 6, d = n & 63;
                int b_ = mA >> 10, t = mA & 1023;
                size_t i0 = (((size_t)(b_ * Hh + h)) * Tn + t) * Dd + d;
                int m2 = mA + 8;
                int b2 = m2 >> 10, t2 = m2 & 1023;
                size_t i1 = (((size_t)(b2 * Hh + h)) * Tn + t2) * Dd + d;
                if (which == 2) {
                    split_store_h(g_vh, g_vl, i0,     v00);
                    split_store_h(g_vh, g_vl, i0 + 1, v01);
                    split_store_h(g_vh, g_vl, i1,     v10);
                    split_store_h(g_vh, g_vl, i1 + 1, v11);
                } else {
                    __nv_bfloat16* ph = (which == 0) ? g_qh : g_kh;
                    __nv_bfloat16* pl = (which == 0) ? g_ql : g_kl;
                    split_store(ph, pl, i0,     v00);
                    split_store(ph, pl, i0 + 1, v01);
                    split_store(ph, pl, i1,     v10);
                    split_store(ph, pl, i1 + 1, v11);
                }
            }
        }
    }
}

// ================= 3) scores via bf16-split MMA: S = QK^T / 8, + masked exp partial sums =================
__global__ __launch_bounds__(128) void scores_mma() {
    int sblk = blockIdx.x, tblk = blockIdx.y, bh = blockIdx.z;
    if (sblk > tblk) return;
    __shared__ char smem[4 * 8192];   // Qh Ql Kh Kl (64 rows x 128B each)
    __shared__ float rowsum[64][2];
    uint32_t sb = smem_to_u32(smem);

    int tid = threadIdx.x, lane = tid & 31, wid = tid >> 5;
    int warp_m = wid & 1, warp_n = wid >> 1;
    int t0 = tblk * 64, s0 = sblk * 64;

    const __nv_bfloat16* srcs[4] = {
        g_qh + ((size_t)bh * Tn + t0) * Dd,
        g_ql + ((size_t)bh * Tn + t0) * Dd,
        g_kh + ((size_t)bh * Tn + s0) * Dd,
        g_kl + ((size_t)bh * Tn + s0) * Dd };
#pragma unroll
    for (int a = 0; a < 4; a++) {
        const __nv_bfloat16* s = srcs[a];
        for (int i = tid; i < 512; i += 128) {
            int row = i >> 3, ch = i & 7;
            uint32_t off = (uint32_t)(row * 128 + ((ch ^ (row & 7)) << 4));
            *reinterpret_cast<uint4*>(smem + a * 8192 + off) =
                *reinterpret_cast<const uint4*>(s + row * 64 + ch * 8);
        }
    }
    __syncthreads();

    int a_row = warp_m * 32 + ((lane >> 3) & 1) * 8 + (lane & 7);
    int a_ch  = lane >> 4;
    int b_row = warp_n * 32 + (lane & 7);
    int b_ch  = (lane >> 3) & 1;

    float acc[2][4][4];
#pragma unroll
    for (int mi = 0; mi < 2; mi++)
#pragma unroll
        for (int ni = 0; ni < 4; ni++)
#pragma unroll
            for (int j = 0; j < 4; j++) acc[mi][ni][j] = 0.f;

#pragma unroll
    for (int ks = 0; ks < 4; ks++) {
        uint32_t aH[2][4], aL[2][4], bH[4][2], bL[4][2];
#pragma unroll
        for (int mi = 0; mi < 2; mi++) {
            int r = a_row + mi * 16;
            uint32_t off = (uint32_t)(r * 128 + (((ks * 2 + a_ch) ^ (r & 7)) << 4));
            ldsm4(aH[mi], sb + off);
            ldsm4(aL[mi], sb + 8192 + off);
        }
#pragma unroll
        for (int ni = 0; ni < 4; ni++) {
            int r = b_row + ni * 8;
            uint32_t off = (uint32_t)(r * 128 + (((ks * 2 + b_ch) ^ (r & 7)) << 4));
            ldsm2(bH[ni], sb + 16384 + off);
            ldsm2(bL[ni], sb + 24576 + off);
        }
#pragma unroll
        for (int mi = 0; mi < 2; mi++)
#pragma unroll
            for (int ni = 0; ni < 4; ni++) {
                mma16816(acc[mi][ni], aH[mi], bH[ni]);
                mma16816(acc[mi][ni], aH[mi], bL[ni]);
                mma16816(acc[mi][ni], aL[mi], bH[ni]);
            }
    }

    float* S = g_att + (size_t)bh * Tn * Tn;
    int r4 = lane >> 2, cp2 = (lane & 3) * 2;
    float esum[2][2] = {};
#pragma unroll
    for (int mi = 0; mi < 2; mi++) {
        int t = t0 + warp_m * 32 + mi * 16 + r4;
#pragma unroll
        for (int ni = 0; ni < 4; ni++) {
            int s = s0 + warp_n * 32 + ni * 8 + cp2;
            float v0 = acc[mi][ni][0] * 0.125f, v1 = acc[mi][ni][1] * 0.125f;
            float v2 = acc[mi][ni][2] * 0.125f, v3 = acc[mi][ni][3] * 0.125f;
            *reinterpret_cast<float2*>(&S[(size_t)t * Tn + s]) = make_float2(v0, v1);
            *reinterpret_cast<float2*>(&S[(size_t)(t + 8) * Tn + s]) = make_float2(v2, v3);
            esum[mi][0] += (s     <= t    ? __expf(v0) : 0.f) + (s + 1 <= t     ? __expf(v1) : 0.f);
            esum[mi][1] += (s     <= t + 8 ? __expf(v2) : 0.f) + (s + 1 <= t + 8 ? __expf(v3) : 0.f);
        }
    }
#pragma unroll
    for (int mi = 0; mi < 2; mi++)
#pragma unroll
        for (int hf = 0; hf < 2; hf++) {
            float v = esum[mi][hf];
            v += __shfl_xor_sync(0xffffffffu, v, 1);
            v += __shfl_xor_sync(0xffffffffu, v, 2);
            esum[mi][hf] = v;
        }
    if ((lane & 3) == 0) {
#pragma unroll
        for (int mi = 0; mi < 2; mi++)
#pragma unroll
            for (int hf = 0; hf < 2; hf++)
                rowsum[warp_m * 32 + mi * 16 + hf * 8 + r4][warp_n] = esum[mi][hf];
    }
    __syncthreads();
    if (tid < 64)
        g_psum[(((size_t)bh * Tn) + t0 + tid) * 16 + sblk] = rowsum[tid][0] + rowsum[tid][1];
}

// ---------------- 4) reduce partials -> 1/sum per row ----------------
__global__ __launch_bounds__(256) void reduce_inv_kernel() {
    int idx = blockIdx.x * blockDim.x + threadIdx.x;   // bh*Tn + t
    int t = idx & (Tn - 1);
    int nblk = (t >> 6) + 1;
    const float* p = g_psum + (size_t)idx * 16;
    float S = 0.f;
    for (int i = 0; i < nblk; i++) S += p[i];
    g_inv[idx] = 1.0f / S;
}

// ---------------- 5) apply exp*inv*tw + head mix -> fp16, causal-zeroed ----------------
__global__ __launch_bounds__(256) void mixapply_kernel(const float* __restrict__ tw,
                                                       const float* __restrict__ Mx) {
    int chunk = blockIdx.x, t = blockIdx.y, b = blockIdx.z;
    int s0 = chunk * 256;
    if (s0 > t) return;            // beyond causal: g_am stays 0 (never written)
    __shared__ float Ms[256];
    __shared__ float st[16];
    int tid = threadIdx.x;
    Ms[tid] = Mx[tid];
    if (tid < 16) st[tid] = g_inv[((size_t)(b * Hh + tid)) * Tn + t];
    __syncthreads();

    int s = s0 + tid;
    bool valid = s <= t;
    float vals[16];
#pragma unroll
    for (int h = 0; h < Hh; h++) {
        float x = g_att[(((size_t)(b * Hh + h)) * Tn + t) * Tn + s];
        float w = tw[(((size_t)h * Tn) + t) * Tn + s];
        vals[h] = valid ? __expf(x) * st[h] * w : 0.f;
    }
#pragma unroll
    for (int o = 0; o < Hh; o++) {
        float a = 0.f;
#pragma unroll
        for (int h = 0; h < Hh; h++) a = fmaf(Ms[o * 16 + h], vals[h], a);
        g_am[(((size_t)(b * Hh + o)) * Tn + t) * Tn + s] = __float2half_rn(a);
    }
}

// ================= 6) AV via fp16 MMA (att single, V hi/lo), 3-stage cp.async =================
#define AV_STAGE 24576
#define AV_SMEM (3 * AV_STAGE)
__global__ __launch_bounds__(256) void av_mma() {
    int tblk = blockIdx.x, bo = blockIdx.y;
    int b = bo >> 4, o = bo & 15;
    int t0 = tblk * 64;
    extern __shared__ char smem[];
    uint32_t sbase = smem_to_u32(smem);

    int tid = threadIdx.x, lane = tid & 31, wid = tid >> 5;
    int warp_m = wid & 3, warp_n = wid >> 2;   // 4 x 2 warp grid, warp tile 16(t) x 32(d)

    int a_row = warp_m * 16 + ((lane >> 3) & 1) * 8 + (lane & 7);
    int a_ch  = lane >> 4;
    int v_lrow = ((lane >> 3) & 1) * 8 + (lane & 7);

    float acc[4][4];
#pragma unroll
    for (int ni = 0; ni < 4; ni++)
#pragma unroll
        for (int j = 0; j < 4; j++) acc[ni][j] = 0.f;

    const __half* Am = g_am + ((size_t)bo * Tn + t0) * Tn;
    const __half* Vh = g_vh + (size_t)bo * Tn * Dd;
    const __half* Vl = g_vl + (size_t)bo * Tn * Dd;

    auto issue = [&](int st, int stage) {
        int s0 = st * 64;
        uint32_t sb = sbase + (uint32_t)stage * AV_STAGE;
#pragma unroll
        for (int j = 0; j < 2; j++) {
            int i = tid + j * 256;
            int row = i >> 3, ch = i & 7;
            uint32_t off = (uint32_t)(row * 128 + ((ch ^ (row & 7)) << 4));
            CP16(sb + off,         Am + (size_t)row * Tn + s0 + ch * 8);
            CP16(sb + 8192 + off,  Vh + (size_t)(s0 + row) * Dd + ch * 8);
            CP16(sb + 16384 + off, Vl + (size_t)(s0 + row) * Dd + ch * 8);
        }
    };

    auto compute = [&](int stage) {
        uint32_t sb = sbase + (uint32_t)stage * AV_STAGE;
#pragma unroll
        for (int ks = 0; ks < 4; ks++) {
            uint32_t aF[4], bH[4][2], bL[4][2];
            {
                int r = a_row;
                uint32_t off = (uint32_t)(r * 128 + (((ks * 2 + a_ch) ^ (r & 7)) << 4));
                ldsm4(aF, sb + off);
            }
            int vrow = ks * 16 + v_lrow;
#pragma unroll
            for (int ni = 0; ni < 4; ni++) {
                int dch = warp_n * 4 + ni;
                uint32_t off = (uint32_t)(vrow * 128 + ((dch ^ (vrow & 7)) << 4));
                ldsm2t(bH[ni], sb + 8192 + off);
                ldsm2t(bL[ni], sb + 16384 + off);
            }
#pragma unroll
            for (int ni = 0; ni < 4; ni++) {
                mma16816h(acc[ni], aF, bH[ni]);
                mma16816h(acc[ni], aF, bL[ni]);
            }
        }
    };

    int nStages = tblk + 1;
    issue(0, 0);
    CP_COMMIT();
    if (nStages > 1) issue(1, 1);
    CP_COMMIT();
#pragma unroll 1
    for (int st = 0; st < nStages; st++) {
        CP_WAIT1();
        __syncthreads();
        compute(st % 3);
        if (st + 2 < nStages) issue(st + 2, (st + 2) % 3);
        CP_COMMIT();
    }

    int r4 = lane >> 2, cp2 = (lane & 3) * 2;
#pragma unroll
    for (int ni = 0; ni < 4; ni++) {
        int d = warp_n * 32 + ni * 8 + cp2;
        int t = t0 + warp_m * 16 + r4;
        size_t i0 = ((size_t)(b * Tn + t)) * Cc + o * 64 + d;
        split_store(g_y_h, g_y_l, i0,     acc[ni][0]);
        split_store(g_y_h, g_y_l, i0 + 1, acc[ni][1]);
        size_t i1 = ((size_t)(b * Tn + t + 8)) * Cc + o * 64 + d;
        split_store(g_y_h, g_y_l, i1,     acc[ni][2]);
        split_store(g_y_h, g_y_l, i1 + 1, acc[ni][3]);
    }
}

// ---------------- host launch ----------------
extern "C" void kernel_launch(void* const* d_in, const int* in_sizes, int n_in,
                              void* d_out, int out_size) {
    const float* x  = (const float*)d_in[0];
    const float* Wq = (const float*)d_in[1];
    const float* bq = (const float*)d_in[2];
    const float* Wk = (const float*)d_in[3];
    const float* bk = (const float*)d_in[4];
    const float* Wv = (const float*)d_in[5];
    const float* bv = (const float*)d_in[6];
    const float* tw = (const float*)d_in[7];
    const float* hm = (const float*)d_in[8];
    const float* Wp = (const float*)d_in[9];
    const float* bp = (const float*)d_in[10];
    float* out = (float*)d_out;

    static cudaStream_t s2 = nullptr, s3 = nullptr;
    static cudaEvent_t evFork = nullptr, evTS = nullptr, evCW = nullptr, evK = nullptr, evV = nullptr;
    if (!s2) {
        cudaFuncSetAttribute(proj_gemm_mma, cudaFuncAttributeMaxDynamicSharedMemorySize, PROJ_SMEM);
        cudaFuncSetAttribute(av_mma, cudaFuncAttributeMaxDynamicSharedMemorySize, AV_SMEM);
        cudaStreamCreateWithFlags(&s2, cudaStreamNonBlocking);
        cudaStreamCreateWithFlags(&s3, cudaStreamNonBlocking);
        cudaEventCreateWithFlags(&evFork, cudaEventDisableTiming);
        cudaEventCreateWithFlags(&evTS, cudaEventDisableTiming);
        cudaEventCreateWithFlags(&evCW, cudaEventDisableTiming);
        cudaEventCreateWithFlags(&evK, cudaEventDisableTiming);
        cudaEventCreateWithFlags(&evV, cudaEventDisableTiming);
    }

    dim3 gproj(Cc / 128, (Bb * Tn) / 128);

    // FORK: non-origin streams must join the capture via an origin-stream event
    // BEFORE their first launch (R13 lesson).
    cudaEventRecord(evFork, 0);
    cudaStreamWaitEvent(s2, evFork, 0);
    cudaStreamWaitEvent(s3, evFork, 0);

    // s0: timeshift ; s2: weight conversion (independent)
    timeshift_kernel<<<(Bb * Tn * Cc) / 256, 256>>>(x);
    cudaEventRecord(evTS, 0);
    convert_w_kernel<<<(4 * Cc * Cc) / 256, 256, 0, s2>>>(Wq, Wk, Wv, Wp);
    cudaEventRecord(evCW, s2);

    // q on s0, k on s3, v on s2 — all concurrent
    cudaStreamWaitEvent(0, evCW, 0);
    proj_gemm_mma<<<gproj, 256, PROJ_SMEM>>>(bq, nullptr, 0);

    cudaStreamWaitEvent(s3, evTS, 0);
    cudaStreamWaitEvent(s3, evCW, 0);
    proj_gemm_mma<<<gproj, 256, PROJ_SMEM, s3>>>(bk, nullptr, 1);
    cudaEventRecord(evK, s3);

    cudaStreamWaitEvent(s2, evTS, 0);
    proj_gemm_mma<<<gproj, 256, PROJ_SMEM, s2>>>(bv, nullptr, 2);
    cudaEventRecord(evV, s2);

    // scores chain on s0 (needs q [program order] + k [event])
    cudaStreamWaitEvent(0, evK, 0);
    dim3 gs(Tn / 64, Tn / 64, Bb * Hh);
    scores_mma<<<gs, 128>>>();

    reduce_inv_kernel<<<(Bb * Hh * Tn) / 256, 256>>>();

    dim3 gmx(Tn / 256, Tn, Bb);
    mixapply_kernel<<<gmx, 256>>>(tw, hm);

    cudaStreamWaitEvent(0, evV, 0);
    dim3 gav(Tn / 64, Bb * Hh);
    av_mma<<<gav, 256, AV_SMEM>>>();

    proj_gemm_mma<<<gproj, 256, PROJ_SMEM>>>(bp, out, 3);
}

// round 15
// speedup vs baseline: 3.5549x; 1.1514x over previous
#include <cuda_runtime.h>
#include <cuda_bf16.h>
#include <cuda_fp16.h>
#include <math.h>
#include <cstdint>

#define Bb 4
#define Tn 1024
#define Cc 1024
#define Hh 16
#define Dd 64
#define NELEM ((size_t)Bb * Tn * Cc)   // 4M

// ---------------- scratch (device globals) ----------------
__device__ float g_att[(size_t)Bb * Hh * Tn * Tn];   // fp32 raw scores (causal blocks)
__device__ float g_psum[(size_t)Bb * Hh * Tn * 16];  // per-(row, sblk) exp partial sums
__device__ float g_inv[(size_t)Bb * Hh * Tn];        // per-row 1/sum
__device__ __half g_am[(size_t)Bb * Hh * Tn * Tn];   // mixed att fp16 (causal-zeroed)

__device__ __nv_bfloat16 g_xs_h[NELEM];              // time-shifted input bf16 hi/lo (q/k path)
__device__ __nv_bfloat16 g_xs_l[NELEM];
__device__ __half g_xs_f[NELEM];                     // time-shifted input fp16 (v path)
__device__ __half g_y_f[NELEM];                      // AV output [B,T,C] fp16
__device__ __nv_bfloat16 g_wh[2 * (size_t)Cc * Cc];  // weights q,k bf16 hi
__device__ __nv_bfloat16 g_wl[2 * (size_t)Cc * Cc];  // weights q,k bf16 lo
__device__ __half g_wfh[2 * (size_t)Cc * Cc];        // weights v,p fp16 hi
__device__ __half g_wfl[2 * (size_t)Cc * Cc];        // weights v,p fp16 lo

__device__ __nv_bfloat16 g_qh[(size_t)Bb * Hh * Tn * Dd];  // [bh][t][d]
__device__ __nv_bfloat16 g_ql[(size_t)Bb * Hh * Tn * Dd];
__device__ __nv_bfloat16 g_kh[(size_t)Bb * Hh * Tn * Dd];
__device__ __nv_bfloat16 g_kl[(size_t)Bb * Hh * Tn * Dd];
__device__ __half g_vf[(size_t)Bb * Hh * Tn * Dd];         // V fp16 single

// ================= helpers =================
__device__ __forceinline__ uint32_t smem_to_u32(const void* p) {
    uint32_t a;
    asm("{ .reg .u64 t; cvta.to.shared.u64 t, %1; cvt.u32.u64 %0, t; }" : "=r"(a) : "l"(p));
    return a;
}
#define CP16(dst, src) \
    asm volatile("cp.async.cg.shared.global [%0], [%1], 16;" :: "r"(dst), "l"(src) : "memory")
#define CP_COMMIT() asm volatile("cp.async.commit_group;" ::: "memory")
#define CP_WAIT0() asm volatile("cp.async.wait_group 0;" ::: "memory")
#define CP_WAIT1() asm volatile("cp.async.wait_group 1;" ::: "memory")

__device__ __forceinline__ void ldsm4(uint32_t* r, uint32_t addr) {
    asm volatile("ldmatrix.sync.aligned.m8n8.x4.shared.b16 {%0,%1,%2,%3}, [%4];"
                 : "=r"(r[0]), "=r"(r[1]), "=r"(r[2]), "=r"(r[3]) : "r"(addr));
}
__device__ __forceinline__ void ldsm2(uint32_t* r, uint32_t addr) {
    asm volatile("ldmatrix.sync.aligned.m8n8.x2.shared.b16 {%0,%1}, [%2];"
                 : "=r"(r[0]), "=r"(r[1]) : "r"(addr));
}
__device__ __forceinline__ void ldsm2t(uint32_t* r, uint32_t addr) {
    asm volatile("ldmatrix.sync.aligned.m8n8.x2.trans.shared.b16 {%0,%1}, [%2];"
                 : "=r"(r[0]), "=r"(r[1]) : "r"(addr));
}
__device__ __forceinline__ void mma16816(float* c, const uint32_t* a, const uint32_t* b) {
    asm volatile("mma.sync.aligned.m16n8k16.row.col.f32.bf16.bf16.f32 "
                 "{%0,%1,%2,%3}, {%4,%5,%6,%7}, {%8,%9}, {%0,%1,%2,%3};"
                 : "+f"(c[0]), "+f"(c[1]), "+f"(c[2]), "+f"(c[3])
                 : "r"(a[0]), "r"(a[1]), "r"(a[2]), "r"(a[3]), "r"(b[0]), "r"(b[1]));
}
__device__ __forceinline__ void mma16816h(float* c, const uint32_t* a, const uint32_t* b) {
    asm volatile("mma.sync.aligned.m16n8k16.row.col.f32.f16.f16.f32 "
                 "{%0,%1,%2,%3}, {%4,%5,%6,%7}, {%8,%9}, {%0,%1,%2,%3};"
                 : "+f"(c[0]), "+f"(c[1]), "+f"(c[2]), "+f"(c[3])
                 : "r"(a[0]), "r"(a[1]), "r"(a[2]), "r"(a[3]), "r"(b[0]), "r"(b[1]));
}
__device__ __forceinline__ void split_store(__nv_bfloat16* ph, __nv_bfloat16* pl, size_t idx, float v) {
    __nv_bfloat16 h = __float2bfloat16_rn(v);
    ph[idx] = h;
    pl[idx] = __float2bfloat16_rn(v - __bfloat162float(h));
}
__device__ __forceinline__ void split_store_h(__half* ph, __half* pl, size_t idx, float v) {
    __half h = __float2half_rn(v);
    ph[idx] = h;
    pl[idx] = __float2half_rn(v - __half2float(h));
}

// ---------------- 1) time shift -> bf16 hi/lo + fp16 ----------------
__global__ __launch_bounds__(256) void timeshift_kernel(const float* __restrict__ x) {
    int idx = blockIdx.x * blockDim.x + threadIdx.x;
    int c = idx & (Cc - 1);
    int t = (idx >> 10) & (Tn - 1);
    int b = idx >> 20;
    float val;
    if (c < Cc / 2) {
        val = (t == 0) ? 0.f : x[((size_t)b * Tn + (t - 1)) * Cc + c];
    } else {
        val = x[((size_t)b * Tn + t) * Cc + c];
    }
    split_store(g_xs_h, g_xs_l, idx, val);
    g_xs_f[idx] = __float2half_rn(val);
}

// ---------------- 1b) weight conversion: q,k -> bf16 hi/lo ----------------
__global__ __launch_bounds__(256) void convert_w_kernel(const float* __restrict__ Wq,
                                                        const float* __restrict__ Wk) {
    size_t idx = (size_t)blockIdx.x * blockDim.x + threadIdx.x;
    int which = (int)(idx >> 20);
    size_t off = idx & ((size_t)Cc * Cc - 1);
    const float* W = (which == 0) ? Wq : Wk;
    split_store(g_wh, g_wl, idx, W[off]);
}

// ---------------- 1c) weight conversion: v,p -> fp16 hi/lo ----------------
__global__ __launch_bounds__(256) void convert_wf_kernel(const float* __restrict__ Wv,
                                                         const float* __restrict__ Wp) {
    size_t idx = (size_t)blockIdx.x * blockDim.x + threadIdx.x;
    int which = (int)(idx >> 20);
    size_t off = idx & ((size_t)Cc * Cc - 1);
    const float* W = (which == 0) ? Wv : Wp;
    split_store_h(g_wfh, g_wfl, idx, W[off]);
}

// ================= 2) bf16-split mma.sync projection GEMM (q/k), 2-stage pipeline =================
#define STAGE_BYTES 32768
#define PROJ_SMEM (2 * STAGE_BYTES)

__global__ __launch_bounds__(256) void proj_gemm_mma(const float* __restrict__ bias, int which) {
    extern __shared__ char smem[];
    uint32_t sbase = smem_to_u32(smem);
    const __nv_bfloat16* gAh = g_xs_h;
    const __nv_bfloat16* gAl = g_xs_l;
    const __nv_bfloat16* gWh = g_wh + (size_t)which * Cc * Cc;
    const __nv_bfloat16* gWl = g_wl + (size_t)which * Cc * Cc;

    int tid = threadIdx.x, lane = tid & 31, wid = tid >> 5;
    int warp_m = wid & 1, warp_n = wid >> 1;
    int m0 = blockIdx.y * 128, n0 = blockIdx.x * 128;

    int rtid = tid >> 2;
    int ctid = tid & 3;

    int a_row_off = (lane & 7) + ((lane >> 3) & 1) * 8;
    int a_chunk = lane >> 4;
    int b_row_off = lane & 7;
    int b_chunk = (lane >> 3) & 1;

    uint32_t aBase[4], aSw[4], bBase[4], bSw[4];
#pragma unroll
    for (int mi = 0; mi < 4; mi++) {
        int r = warp_m * 64 + mi * 16 + a_row_off;
        aBase[mi] = (uint32_t)(r * 64);
        aSw[mi] = (uint32_t)((r >> 1) & 3);
    }
#pragma unroll
    for (int ni = 0; ni < 4; ni++) {
        int r = warp_n * 32 + ni * 8 + b_row_off;
        bBase[ni] = (uint32_t)(r * 64);
        bSw[ni] = (uint32_t)((r >> 1) & 3);
    }

    float acc[4][4][4];
#pragma unroll
    for (int mi = 0; mi < 4; mi++)
#pragma unroll
        for (int ni = 0; ni < 4; ni++)
#pragma unroll
            for (int j = 0; j < 4; j++) acc[mi][ni][j] = 0.f;

    auto issue = [&](int chunk, int stage) {
        int k0 = chunk * 32;
        uint32_t sb = sbase + (uint32_t)stage * STAGE_BYTES;
#pragma unroll
        for (int j = 0; j < 2; j++) {
            int row = rtid + j * 64;
            uint32_t dof = (uint32_t)(row * 64 + ((ctid ^ ((row >> 1) & 3)) << 4));
            size_t ga = (size_t)(m0 + row) * Cc + k0 + ctid * 8;
            size_t gw = (size_t)(n0 + row) * Cc + k0 + ctid * 8;
            CP16(sb + dof,         gAh + ga);
            CP16(sb + 8192 + dof,  gAl + ga);
            CP16(sb + 16384 + dof, gWh + gw);
            CP16(sb + 24576 + dof, gWl + gw);
        }
    };

    auto compute = [&](int stage) {
        uint32_t sb = sbase + (uint32_t)stage * STAGE_BYTES;
#pragma unroll
        for (int ks = 0; ks < 2; ks++) {
            uint32_t aH[4][4], aL[4][4], bH[4][2], bL[4][2];
#pragma unroll
            for (int mi = 0; mi < 4; mi++) {
                uint32_t off = aBase[mi] + ((((uint32_t)(ks * 2) + a_chunk) ^ aSw[mi]) << 4);
                ldsm4(aH[mi], sb + off);
                ldsm4(aL[mi], sb + 8192 + off);
            }
#pragma unroll
            for (int ni = 0; ni < 4; ni++) {
                uint32_t off = bBase[ni] + ((((uint32_t)(ks * 2) + b_chunk) ^ bSw[ni]) << 4);
                ldsm2(bH[ni], sb + 16384 + off);
                ldsm2(bL[ni], sb + 24576 + off);
            }
#pragma unroll
            for (int mi = 0; mi < 4; mi++)
#pragma unroll
                for (int ni = 0; ni < 4; ni++) {
                    mma16816(acc[mi][ni], aH[mi], bH[ni]);
                    mma16816(acc[mi][ni], aH[mi], bL[ni]);
                    mma16816(acc[mi][ni], aL[mi], bH[ni]);
                }
        }
    };

    const int NCH = Cc / 32;
    issue(0, 0);
    CP_COMMIT();
#pragma unroll 1
    for (int c = 0; c < NCH; c++) {
        if (c + 1 < NCH) {
            issue(c + 1, (c + 1) & 1);
            CP_COMMIT();
            CP_WAIT1();
        } else {
            CP_WAIT0();
        }
        __syncthreads();
        compute(c & 1);
        __syncthreads();
    }

    // epilogue -> q/k bf16 hi/lo
    int r4 = lane >> 2;
    int cp2 = (lane & 3) * 2;
    __nv_bfloat16* ph = (which == 0) ? g_qh : g_kh;
    __nv_bfloat16* pl = (which == 0) ? g_ql : g_kl;
#pragma unroll
    for (int ni = 0; ni < 4; ni++) {
        int n = n0 + warp_n * 32 + ni * 8 + cp2;
        float b0 = bias[n], b1 = bias[n + 1];
        int h = n >> 6, d = n & 63;
#pragma unroll
        for (int mi = 0; mi < 4; mi++) {
            int mA = m0 + warp_m * 64 + mi * 16 + r4;
            int b_ = mA >> 10, t = mA & 1023;
            size_t i0 = (((size_t)(b_ * Hh + h)) * Tn + t) * Dd + d;
            split_store(ph, pl, i0,     acc[mi][ni][0] + b0);
            split_store(ph, pl, i0 + 1, acc[mi][ni][1] + b1);
            int m2 = mA + 8;
            int b2 = m2 >> 10, t2 = m2 & 1023;
            size_t i1 = (((size_t)(b2 * Hh + h)) * Tn + t2) * Dd + d;
            split_store(ph, pl, i1,     acc[mi][ni][2] + b0);
            split_store(ph, pl, i1 + 1, acc[mi][ni][3] + b1);
        }
    }
}

// ================= 2b) fp16 projection GEMM (v / out): A fp16 x W fp16-hi/lo, 2 products =================
#define STAGE_F16 24576
#define PROJF_SMEM (2 * STAGE_F16)

__global__ __launch_bounds__(256) void proj_gemm_f16(const float* __restrict__ bias,
                                                     float* __restrict__ outflat, int which) {
    extern __shared__ char smem[];
    uint32_t sbase = smem_to_u32(smem);
    const __half* gA  = (which == 0) ? g_xs_f : g_y_f;
    const __half* gWh = g_wfh + (size_t)which * Cc * Cc;
    const __half* gWl = g_wfl + (size_t)which * Cc * Cc;

    int tid = threadIdx.x, lane = tid & 31, wid = tid >> 5;
    int warp_m = wid & 1, warp_n = wid >> 1;
    int m0 = blockIdx.y * 128, n0 = blockIdx.x * 128;

    int rtid = tid >> 2;
    int ctid = tid & 3;

    int a_row_off = (lane & 7) + ((lane >> 3) & 1) * 8;
    int a_chunk = lane >> 4;
    int b_row_off = lane & 7;
    int b_chunk = (lane >> 3) & 1;

    uint32_t aBase[4], aSw[4], bBase[4], bSw[4];
#pragma unroll
    for (int mi = 0; mi < 4; mi++) {
        int r = warp_m * 64 + mi * 16 + a_row_off;
        aBase[mi] = (uint32_t)(r * 64);
        aSw[mi] = (uint32_t)((r >> 1) & 3);
    }
#pragma unroll
    for (int ni = 0; ni < 4; ni++) {
        int r = warp_n * 32 + ni * 8 + b_row_off;
        bBase[ni] = (uint32_t)(r * 64);
        bSw[ni] = (uint32_t)((r >> 1) & 3);
    }

    float acc[4][4][4];
#pragma unroll
    for (int mi = 0; mi < 4; mi++)
#pragma unroll
        for (int ni = 0; ni < 4; ni++)
#pragma unroll
            for (int j = 0; j < 4; j++) acc[mi][ni][j] = 0.f;

    auto issue = [&](int chunk, int stage) {
        int k0 = chunk * 32;
        uint32_t sb = sbase + (uint32_t)stage * STAGE_F16;
#pragma unroll
        for (int j = 0; j < 2; j++) {
            int row = rtid + j * 64;
            uint32_t dof = (uint32_t)(row * 64 + ((ctid ^ ((row >> 1) & 3)) << 4));
            size_t ga = (size_t)(m0 + row) * Cc + k0 + ctid * 8;
            size_t gw = (size_t)(n0 + row) * Cc + k0 + ctid * 8;
            CP16(sb + dof,         gA  + ga);
            CP16(sb + 8192 + dof,  gWh + gw);
            CP16(sb + 16384 + dof, gWl + gw);
        }
    };

    auto compute = [&](int stage) {
        uint32_t sb = sbase + (uint32_t)stage * STAGE_F16;
#pragma unroll
        for (int ks = 0; ks < 2; ks++) {
            uint32_t aF[4][4], bH[4][2], bL[4][2];
#pragma unroll
            for (int mi = 0; mi < 4; mi++) {
                uint32_t off = aBase[mi] + ((((uint32_t)(ks * 2) + a_chunk) ^ aSw[mi]) << 4);
                ldsm4(aF[mi], sb + off);
            }
#pragma unroll
            for (int ni = 0; ni < 4; ni++) {
                uint32_t off = bBase[ni] + ((((uint32_t)(ks * 2) + b_chunk) ^ bSw[ni]) << 4);
                ldsm2(bH[ni], sb + 8192 + off);
                ldsm2(bL[ni], sb + 16384 + off);
            }
#pragma unroll
            for (int mi = 0; mi < 4; mi++)
#pragma unroll
                for (int ni = 0; ni < 4; ni++) {
                    mma16816h(acc[mi][ni], aF[mi], bH[ni]);
                    mma16816h(acc[mi][ni], aF[mi], bL[ni]);
                }
        }
    };

    const int NCH = Cc / 32;
    issue(0, 0);
    CP_COMMIT();
#pragma unroll 1
    for (int c = 0; c < NCH; c++) {
        if (c + 1 < NCH) {
            issue(c + 1, (c + 1) & 1);
            CP_COMMIT();
            CP_WAIT1();
        } else {
            CP_WAIT0();
        }
        __syncthreads();
        compute(c & 1);
        __syncthreads();
    }

    // epilogue
    int r4 = lane >> 2;
    int cp2 = (lane & 3) * 2;
#pragma unroll
    for (int ni = 0; ni < 4; ni++) {
        int n = n0 + warp_n * 32 + ni * 8 + cp2;
        float b0 = bias[n], b1 = bias[n + 1];
#pragma unroll
        for (int mi = 0; mi < 4; mi++) {
            int mA = m0 + warp_m * 64 + mi * 16 + r4;
            float v00 = acc[mi][ni][0] + b0, v01 = acc[mi][ni][1] + b1;
            float v10 = acc[mi][ni][2] + b0, v11 = acc[mi][ni][3] + b1;
            if (which == 1) {
                *reinterpret_cast<float2*>(&outflat[(size_t)mA * Cc + n]) = make_float2(v00, v01);
                *reinterpret_cast<float2*>(&outflat[(size_t)(mA + 8) * Cc + n]) = make_float2(v10, v11);
            } else {
                int h = n >> 6, d = n & 63;
                int b_ = mA >> 10, t = mA & 1023;
                size_t i0 = (((size_t)(b_ * Hh + h)) * Tn + t) * Dd + d;
                *reinterpret_cast<__half2*>(&g_vf[i0]) = __floats2half2_rn(v00, v01);
                int m2 = mA + 8;
                int b2 = m2 >> 10, t2 = m2 & 1023;
                size_t i1 = (((size_t)(b2 * Hh + h)) * Tn + t2) * Dd + d;
                *reinterpret_cast<__half2*>(&g_vf[i1]) = __floats2half2_rn(v10, v11);
            }
        }
    }
}

// ================= 3) scores via bf16-split MMA: S = QK^T / 8, + masked exp partial sums =================
__global__ __launch_bounds__(128) void scores_mma() {
    int sblk = blockIdx.x, tblk = blockIdx.y, bh = blockIdx.z;
    if (sblk > tblk) return;
    __shared__ char smem[4 * 8192];   // Qh Ql Kh Kl (64 rows x 128B each)
    __shared__ float rowsum[64][2];
    uint32_t sb = smem_to_u32(smem);

    int tid = threadIdx.x, lane = tid & 31, wid = tid >> 5;
    int warp_m = wid & 1, warp_n = wid >> 1;
    int t0 = tblk * 64, s0 = sblk * 64;

    const __nv_bfloat16* srcs[4] = {
        g_qh + ((size_t)bh * Tn + t0) * Dd,
        g_ql + ((size_t)bh * Tn + t0) * Dd,
        g_kh + ((size_t)bh * Tn + s0) * Dd,
        g_kl + ((size_t)bh * Tn + s0) * Dd };
#pragma unroll
    for (int a = 0; a < 4; a++) {
        const __nv_bfloat16* s = srcs[a];
        for (int i = tid; i < 512; i += 128) {
            int row = i >> 3, ch = i & 7;
            uint32_t off = (uint32_t)(row * 128 + ((ch ^ (row & 7)) << 4));
            *reinterpret_cast<uint4*>(smem + a * 8192 + off) =
                *reinterpret_cast<const uint4*>(s + row * 64 + ch * 8);
        }
    }
    __syncthreads();

    int a_row = warp_m * 32 + ((lane >> 3) & 1) * 8 + (lane & 7);
    int a_ch  = lane >> 4;
    int b_row = warp_n * 32 + (lane & 7);
    int b_ch  = (lane >> 3) & 1;

    float acc[2][4][4];
#pragma unroll
    for (int mi = 0; mi < 2; mi++)
#pragma unroll
        for (int ni = 0; ni < 4; ni++)
#pragma unroll
            for (int j = 0; j < 4; j++) acc[mi][ni][j] = 0.f;

#pragma unroll
    for (int ks = 0; ks < 4; ks++) {
        uint32_t aH[2][4], aL[2][4], bH[4][2], bL[4][2];
#pragma unroll
        for (int mi = 0; mi < 2; mi++) {
            int r = a_row + mi * 16;
            uint32_t off = (uint32_t)(r * 128 + (((ks * 2 + a_ch) ^ (r & 7)) << 4));
            ldsm4(aH[mi], sb + off);
            ldsm4(aL[mi], sb + 8192 + off);
        }
#pragma unroll
        for (int ni = 0; ni < 4; ni++) {
            int r = b_row + ni * 8;
            uint32_t off = (uint32_t)(r * 128 + (((ks * 2 + b_ch) ^ (r & 7)) << 4));
            ldsm2(bH[ni], sb + 16384 + off);
            ldsm2(bL[ni], sb + 24576 + off);
        }
#pragma unroll
        for (int mi = 0; mi < 2; mi++)
#pragma unroll
            for (int ni = 0; ni < 4; ni++) {
                mma16816(acc[mi][ni], aH[mi], bH[ni]);
                mma16816(acc[mi][ni], aH[mi], bL[ni]);
                mma16816(acc[mi][ni], aL[mi], bH[ni]);
            }
    }

    float* S = g_att + (size_t)bh * Tn * Tn;
    int r4 = lane >> 2, cp2 = (lane & 3) * 2;
    float esum[2][2] = {};
#pragma unroll
    for (int mi = 0; mi < 2; mi++) {
        int t = t0 + warp_m * 32 + mi * 16 + r4;
#pragma unroll
        for (int ni = 0; ni < 4; ni++) {
            int s = s0 + warp_n * 32 + ni * 8 + cp2;
            float v0 = acc[mi][ni][0] * 0.125f, v1 = acc[mi][ni][1] * 0.125f;
            float v2 = acc[mi][ni][2] * 0.125f, v3 = acc[mi][ni][3] * 0.125f;
            *reinterpret_cast<float2*>(&S[(size_t)t * Tn + s]) = make_float2(v0, v1);
            *reinterpret_cast<float2*>(&S[(size_t)(t + 8) * Tn + s]) = make_float2(v2, v3);
            esum[mi][0] += (s     <= t    ? __expf(v0) : 0.f) + (s + 1 <= t     ? __expf(v1) : 0.f);
            esum[mi][1] += (s     <= t + 8 ? __expf(v2) : 0.f) + (s + 1 <= t + 8 ? __expf(v3) : 0.f);
        }
    }
#pragma unroll
    for (int mi = 0; mi < 2; mi++)
#pragma unroll
        for (int hf = 0; hf < 2; hf++) {
            float v = esum[mi][hf];
            v += __shfl_xor_sync(0xffffffffu, v, 1);
            v += __shfl_xor_sync(0xffffffffu, v, 2);
            esum[mi][hf] = v;
        }
    if ((lane & 3) == 0) {
#pragma unroll
        for (int mi = 0; mi < 2; mi++)
#pragma unroll
            for (int hf = 0; hf < 2; hf++)
                rowsum[warp_m * 32 + mi * 16 + hf * 8 + r4][warp_n] = esum[mi][hf];
    }
    __syncthreads();
    if (tid < 64)
        g_psum[(((size_t)bh * Tn) + t0 + tid) * 16 + sblk] = rowsum[tid][0] + rowsum[tid][1];
}

// ---------------- 4) reduce partials -> 1/sum per row ----------------
__global__ __launch_bounds__(256) void reduce_inv_kernel() {
    int idx = blockIdx.x * blockDim.x + threadIdx.x;   // bh*Tn + t
    int t = idx & (Tn - 1);
    int nblk = (t >> 6) + 1;
    const float* p = g_psum + (size_t)idx * 16;
    float S = 0.f;
    for (int i = 0; i < nblk; i++) S += p[i];
    g_inv[idx] = 1.0f / S;
}

// ---------------- 5) apply exp*inv*tw + head mix -> fp16, causal-zeroed ----------------
__global__ __launch_bounds__(256) void mixapply_kernel(const float* __restrict__ tw,
                                                       const float* __restrict__ Mx) {
    int chunk = blockIdx.x, t = blockIdx.y, b = blockIdx.z;
    int s0 = chunk * 256;
    if (s0 > t) return;            // beyond causal: g_am stays 0 (never written)
    __shared__ float Ms[256];
    __shared__ float st[16];
    int tid = threadIdx.x;
    Ms[tid] = Mx[tid];
    if (tid < 16) st[tid] = g_inv[((size_t)(b * Hh + tid)) * Tn + t];
    __syncthreads();

    int s = s0 + tid;
    bool valid = s <= t;
    float vals[16];
#pragma unroll
    for (int h = 0; h < Hh; h++) {
        float x = g_att[(((size_t)(b * Hh + h)) * Tn + t) * Tn + s];
        float w = tw[(((size_t)h * Tn) + t) * Tn + s];
        vals[h] = valid ? __expf(x) * st[h] * w : 0.f;
    }
#pragma unroll
    for (int o = 0; o < Hh; o++) {
        float a = 0.f;
#pragma unroll
        for (int h = 0; h < Hh; h++) a = fmaf(Ms[o * 16 + h], vals[h], a);
        g_am[(((size_t)(b * Hh + o)) * Tn + t) * Tn + s] = __float2half_rn(a);
    }
}

// ================= 6) AV via fp16 MMA (att x V, 1 product), 3-stage cp.async =================
#define AV_STAGE 16384
#define AV_SMEM (3 * AV_STAGE)
__global__ __launch_bounds__(256) void av_mma() {
    int tblk = blockIdx.x, bo = blockIdx.y;
    int b = bo >> 4, o = bo & 15;
    int t0 = tblk * 64;
    extern __shared__ char smem[];
    uint32_t sbase = smem_to_u32(smem);

    int tid = threadIdx.x, lane = tid & 31, wid = tid >> 5;
    int warp_m = wid & 3, warp_n = wid >> 2;   // 4 x 2 warp grid, warp tile 16(t) x 32(d)

    int a_row = warp_m * 16 + ((lane >> 3) & 1) * 8 + (lane & 7);
    int a_ch  = lane >> 4;
    int v_lrow = ((lane >> 3) & 1) * 8 + (lane & 7);

    float acc[4][4];
#pragma unroll
    for (int ni = 0; ni < 4; ni++)
#pragma unroll
        for (int j = 0; j < 4; j++) acc[ni][j] = 0.f;

    const __half* Am = g_am + ((size_t)bo * Tn + t0) * Tn;
    const __half* Vf = g_vf + (size_t)bo * Tn * Dd;

    auto issue = [&](int st, int stage) {
        int s0 = st * 64;
        uint32_t sb = sbase + (uint32_t)stage * AV_STAGE;
#pragma unroll
        for (int j = 0; j < 2; j++) {
            int i = tid + j * 256;
            int row = i >> 3, ch = i & 7;
            uint32_t off = (uint32_t)(row * 128 + ((ch ^ (row & 7)) << 4));
            CP16(sb + off,        Am + (size_t)row * Tn + s0 + ch * 8);
            CP16(sb + 8192 + off, Vf + (size_t)(s0 + row) * Dd + ch * 8);
        }
    };

    auto compute = [&](int stage) {
        uint32_t sb = sbase + (uint32_t)stage * AV_STAGE;
#pragma unroll
        for (int ks = 0; ks < 4; ks++) {
            uint32_t aF[4], bF[4][2];
            {
                int r = a_row;
                uint32_t off = (uint32_t)(r * 128 + (((ks * 2 + a_ch) ^ (r & 7)) << 4));
                ldsm4(aF, sb + off);
            }
            int vrow = ks * 16 + v_lrow;
#pragma unroll
            for (int ni = 0; ni < 4; ni++) {
                int dch = warp_n * 4 + ni;
                uint32_t off = (uint32_t)(vrow * 128 + ((dch ^ (vrow & 7)) << 4));
                ldsm2t(bF[ni], sb + 8192 + off);
            }
#pragma unroll
            for (int ni = 0; ni < 4; ni++) {
                mma16816h(acc[ni], aF, bF[ni]);
            }
        }
    };

    int nStages = tblk + 1;
    issue(0, 0);
    CP_COMMIT();
    if (nStages > 1) issue(1, 1);
    CP_COMMIT();
#pragma unroll 1
    for (int st = 0; st < nStages; st++) {
        CP_WAIT1();
        __syncthreads();
        compute(st % 3);
        if (st + 2 < nStages) issue(st + 2, (st + 2) % 3);
        CP_COMMIT();
    }

    int r4 = lane >> 2, cp2 = (lane & 3) * 2;
#pragma unroll
    for (int ni = 0; ni < 4; ni++) {
        int d = warp_n * 32 + ni * 8 + cp2;
        int t = t0 + warp_m * 16 + r4;
        size_t i0 = ((size_t)(b * Tn + t)) * Cc + o * 64 + d;
        *reinterpret_cast<__half2*>(&g_y_f[i0]) = __floats2half2_rn(acc[ni][0], acc[ni][1]);
        size_t i1 = ((size_t)(b * Tn + t + 8)) * Cc + o * 64 + d;
        *reinterpret_cast<__half2*>(&g_y_f[i1]) = __floats2half2_rn(acc[ni][2], acc[ni][3]);
    }
}

// ---------------- host launch ----------------
extern "C" void kernel_launch(void* const* d_in, const int* in_sizes, int n_in,
                              void* d_out, int out_size) {
    const float* x  = (const float*)d_in[0];
    const float* Wq = (const float*)d_in[1];
    const float* bq = (const float*)d_in[2];
    const float* Wk = (const float*)d_in[3];
    const float* bk = (const float*)d_in[4];
    const float* Wv = (const float*)d_in[5];
    const float* bv = (const float*)d_in[6];
    const float* tw = (const float*)d_in[7];
    const float* hm = (const float*)d_in[8];
    const float* Wp = (const float*)d_in[9];
    const float* bp = (const float*)d_in[10];
    float* out = (float*)d_out;

    static cudaStream_t s2 = nullptr, s3 = nullptr;
    static cudaEvent_t evFork = nullptr, evTS = nullptr, evCW = nullptr,
                       evCWF = nullptr, evK = nullptr, evV = nullptr;
    if (!s2) {
        cudaFuncSetAttribute(proj_gemm_mma, cudaFuncAttributeMaxDynamicSharedMemorySize, PROJ_SMEM);
        cudaFuncSetAttribute(proj_gemm_f16, cudaFuncAttributeMaxDynamicSharedMemorySize, PROJF_SMEM);
        cudaFuncSetAttribute(av_mma, cudaFuncAttributeMaxDynamicSharedMemorySize, AV_SMEM);
        cudaStreamCreateWithFlags(&s2, cudaStreamNonBlocking);
        cudaStreamCreateWithFlags(&s3, cudaStreamNonBlocking);
        cudaEventCreateWithFlags(&evFork, cudaEventDisableTiming);
        cudaEventCreateWithFlags(&evTS, cudaEventDisableTiming);
        cudaEventCreateWithFlags(&evCW, cudaEventDisableTiming);
        cudaEventCreateWithFlags(&evCWF, cudaEventDisableTiming);
        cudaEventCreateWithFlags(&evK, cudaEventDisableTiming);
        cudaEventCreateWithFlags(&evV, cudaEventDisableTiming);
    }

    dim3 gproj(Cc / 128, (Bb * Tn) / 128);

    // FORK: non-origin streams join the capture via an origin-stream event first.
    cudaEventRecord(evFork, 0);
    cudaStreamWaitEvent(s2, evFork, 0);
    cudaStreamWaitEvent(s3, evFork, 0);

    // s0: timeshift ; s2: q/k weight conversion ; s3: v/p weight conversion
    timeshift_kernel<<<(Bb * Tn * Cc) / 256, 256>>>(x);
    cudaEventRecord(evTS, 0);
    convert_w_kernel<<<(2 * Cc * Cc) / 256, 256, 0, s2>>>(Wq, Wk);
    cudaEventRecord(evCW, s2);
    convert_wf_kernel<<<(2 * Cc * Cc) / 256, 256, 0, s3>>>(Wv, Wp);
    cudaEventRecord(evCWF, s3);

    // q on s0
    cudaStreamWaitEvent(0, evCW, 0);
    proj_gemm_mma<<<gproj, 256, PROJ_SMEM>>>(bq, 0);

    // k on s3 (after its cwf, needs ts + cw)
    cudaStreamWaitEvent(s3, evTS, 0);
    cudaStreamWaitEvent(s3, evCW, 0);
    proj_gemm_mma<<<gproj, 256, PROJ_SMEM, s3>>>(bk, 1);
    cudaEventRecord(evK, s3);

    // v on s2 (needs ts + cwf)
    cudaStreamWaitEvent(s2, evTS, 0);
    cudaStreamWaitEvent(s2, evCWF, 0);
    proj_gemm_f16<<<gproj, 256, PROJF_SMEM, s2>>>(bv, nullptr, 0);
    cudaEventRecord(evV, s2);

    // scores chain on s0 (needs q [program order] + k [event])
    cudaStreamWaitEvent(0, evK, 0);
    dim3 gs(Tn / 64, Tn / 64, Bb * Hh);
    scores_mma<<<gs, 128>>>();

    reduce_inv_kernel<<<(Bb * Hh * Tn) / 256, 256>>>();

    dim3 gmx(Tn / 256, Tn, Bb);
    mixapply_kernel<<<gmx, 256>>>(tw, hm);

    cudaStreamWaitEvent(0, evV, 0);
    dim3 gav(Tn / 64, Bb * Hh);
    av_mma<<<gav, 256, AV_SMEM>>>();

    proj_gemm_f16<<<gproj, 256, PROJF_SMEM>>>(bp, out, 1);
}

// round 16
// speedup vs baseline: 4.5993x; 1.2938x over previous
#include <cuda_runtime.h>
#include <cuda_fp16.h>
#include <math.h>
#include <cstdint>

#define Bb 4
#define Tn 1024
#define Cc 1024
#define Hh 16
#define Dd 64
#define NELEM ((size_t)Bb * Tn * Cc)   // 4M

// ---------------- scratch (device globals) ----------------
__device__ float g_att[(size_t)Bb * Hh * Tn * Tn];   // fp32 raw scores (causal blocks)
__device__ float g_psum[(size_t)Bb * Hh * Tn * 16];  // per-(row, sblk) exp partial sums
__device__ float g_inv[(size_t)Bb * Hh * Tn];        // per-row 1/sum
__device__ __half g_am[(size_t)Bb * Hh * Tn * Tn];   // mixed att fp16 (causal-zeroed)

__device__ __half g_xs_f[NELEM];                     // time-shifted input fp16
__device__ __half g_y_f[NELEM];                      // AV output [B,T,C] fp16
__device__ __half g_wfh[4 * (size_t)Cc * Cc];        // weights q,k,v,p fp16 hi
__device__ __half g_wfl[4 * (size_t)Cc * Cc];        // weights q,k,v,p fp16 lo

__device__ __half g_qf[(size_t)Bb * Hh * Tn * Dd];   // [bh][t][d] fp16
__device__ __half g_kf[(size_t)Bb * Hh * Tn * Dd];
__device__ __half g_vf[(size_t)Bb * Hh * Tn * Dd];

// ================= helpers =================
__device__ __forceinline__ uint32_t smem_to_u32(const void* p) {
    uint32_t a;
    asm("{ .reg .u64 t; cvta.to.shared.u64 t, %1; cvt.u32.u64 %0, t; }" : "=r"(a) : "l"(p));
    return a;
}
#define CP16(dst, src) \
    asm volatile("cp.async.cg.shared.global [%0], [%1], 16;" :: "r"(dst), "l"(src) : "memory")
#define CP_COMMIT() asm volatile("cp.async.commit_group;" ::: "memory")
#define CP_WAIT0() asm volatile("cp.async.wait_group 0;" ::: "memory")
#define CP_WAIT1() asm volatile("cp.async.wait_group 1;" ::: "memory")

__device__ __forceinline__ void ldsm4(uint32_t* r, uint32_t addr) {
    asm volatile("ldmatrix.sync.aligned.m8n8.x4.shared.b16 {%0,%1,%2,%3}, [%4];"
                 : "=r"(r[0]), "=r"(r[1]), "=r"(r[2]), "=r"(r[3]) : "r"(addr));
}
__device__ __forceinline__ void ldsm2(uint32_t* r, uint32_t addr) {
    asm volatile("ldmatrix.sync.aligned.m8n8.x2.shared.b16 {%0,%1}, [%2];"
                 : "=r"(r[0]), "=r"(r[1]) : "r"(addr));
}
__device__ __forceinline__ void ldsm2t(uint32_t* r, uint32_t addr) {
    asm volatile("ldmatrix.sync.aligned.m8n8.x2.trans.shared.b16 {%0,%1}, [%2];"
                 : "=r"(r[0]), "=r"(r[1]) : "r"(addr));
}
__device__ __forceinline__ void mma16816h(float* c, const uint32_t* a, const uint32_t* b) {
    asm volatile("mma.sync.aligned.m16n8k16.row.col.f32.f16.f16.f32 "
                 "{%0,%1,%2,%3}, {%4,%5,%6,%7}, {%8,%9}, {%0,%1,%2,%3};"
                 : "+f"(c[0]), "+f"(c[1]), "+f"(c[2]), "+f"(c[3])
                 : "r"(a[0]), "r"(a[1]), "r"(a[2]), "r"(a[3]), "r"(b[0]), "r"(b[1]));
}
__device__ __forceinline__ void split_store_h(__half* ph, __half* pl, size_t idx, float v) {
    __half h = __float2half_rn(v);
    ph[idx] = h;
    pl[idx] = __float2half_rn(v - __half2float(h));
}

// ---------------- 1) time shift -> fp16 ----------------
__global__ __launch_bounds__(256) void timeshift_kernel(const float* __restrict__ x) {
    int idx = blockIdx.x * blockDim.x + threadIdx.x;
    int c = idx & (Cc - 1);
    int t = (idx >> 10) & (Tn - 1);
    int b = idx >> 20;
    float val;
    if (c < Cc / 2) {
        val = (t == 0) ? 0.f : x[((size_t)b * Tn + (t - 1)) * Cc + c];
    } else {
        val = x[((size_t)b * Tn + t) * Cc + c];
    }
    g_xs_f[idx] = __float2half_rn(val);
}

// ---------------- 1b) weight conversion: q,k,v,p -> fp16 hi/lo ----------------
__global__ __launch_bounds__(256) void convert_wf_kernel(const float* __restrict__ Wq,
                                                         const float* __restrict__ Wk,
                                                         const float* __restrict__ Wv,
                                                         const float* __restrict__ Wp) {
    size_t idx = (size_t)blockIdx.x * blockDim.x + threadIdx.x;
    int which = (int)(idx >> 20);
    size_t off = idx & ((size_t)Cc * Cc - 1);
    const float* W = (which == 0) ? Wq : (which == 1) ? Wk : (which == 2) ? Wv : Wp;
    split_store_h(g_wfh, g_wfl, idx, W[off]);
}

// ================= 2) fp16 projection GEMM: A fp16 x W fp16-hi/lo, 2 products =================
// which: 0=q, 1=k, 2=v, 3=out
#define STAGE_F16 24576
#define PROJF_SMEM (2 * STAGE_F16)

__global__ __launch_bounds__(256) void proj_gemm_f16(const float* __restrict__ bias,
                                                     float* __restrict__ outflat, int which) {
    extern __shared__ char smem[];
    uint32_t sbase = smem_to_u32(smem);
    const __half* gA  = (which == 3) ? g_y_f : g_xs_f;
    const __half* gWh = g_wfh + (size_t)which * Cc * Cc;
    const __half* gWl = g_wfl + (size_t)which * Cc * Cc;

    int tid = threadIdx.x, lane = tid & 31, wid = tid >> 5;
    int warp_m = wid & 1, warp_n = wid >> 1;
    int m0 = blockIdx.y * 128, n0 = blockIdx.x * 128;

    int rtid = tid >> 2;
    int ctid = tid & 3;

    int a_row_off = (lane & 7) + ((lane >> 3) & 1) * 8;
    int a_chunk = lane >> 4;
    int b_row_off = lane & 7;
    int b_chunk = (lane >> 3) & 1;

    uint32_t aBase[4], aSw[4], bBase[4], bSw[4];
#pragma unroll
    for (int mi = 0; mi < 4; mi++) {
        int r = warp_m * 64 + mi * 16 + a_row_off;
        aBase[mi] = (uint32_t)(r * 64);
        aSw[mi] = (uint32_t)((r >> 1) & 3);
    }
#pragma unroll
    for (int ni = 0; ni < 4; ni++) {
        int r = warp_n * 32 + ni * 8 + b_row_off;
        bBase[ni] = (uint32_t)(r * 64);
        bSw[ni] = (uint32_t)((r >> 1) & 3);
    }

    float acc[4][4][4];
#pragma unroll
    for (int mi = 0; mi < 4; mi++)
#pragma unroll
        for (int ni = 0; ni < 4; ni++)
#pragma unroll
            for (int j = 0; j < 4; j++) acc[mi][ni][j] = 0.f;

    auto issue = [&](int chunk, int stage) {
        int k0 = chunk * 32;
        uint32_t sb = sbase + (uint32_t)stage * STAGE_F16;
#pragma unroll
        for (int j = 0; j < 2; j++) {
            int row = rtid + j * 64;
            uint32_t dof = (uint32_t)(row * 64 + ((ctid ^ ((row >> 1) & 3)) << 4));
            size_t ga = (size_t)(m0 + row) * Cc + k0 + ctid * 8;
            size_t gw = (size_t)(n0 + row) * Cc + k0 + ctid * 8;
            CP16(sb + dof,         gA  + ga);
            CP16(sb + 8192 + dof,  gWh + gw);
            CP16(sb + 16384 + dof, gWl + gw);
        }
    };

    auto compute = [&](int stage) {
        uint32_t sb = sbase + (uint32_t)stage * STAGE_F16;
#pragma unroll
        for (int ks = 0; ks < 2; ks++) {
            uint32_t aF[4][4], bH[4][2], bL[4][2];
#pragma unroll
            for (int mi = 0; mi < 4; mi++) {
                uint32_t off = aBase[mi] + ((((uint32_t)(ks * 2) + a_chunk) ^ aSw[mi]) << 4);
                ldsm4(aF[mi], sb + off);
            }
#pragma unroll
            for (int ni = 0; ni < 4; ni++) {
                uint32_t off = bBase[ni] + ((((uint32_t)(ks * 2) + b_chunk) ^ bSw[ni]) << 4);
                ldsm2(bH[ni], sb + 8192 + off);
                ldsm2(bL[ni], sb + 16384 + off);
            }
#pragma unroll
            for (int mi = 0; mi < 4; mi++)
#pragma unroll
                for (int ni = 0; ni < 4; ni++) {
                    mma16816h(acc[mi][ni], aF[mi], bH[ni]);
                    mma16816h(acc[mi][ni], aF[mi], bL[ni]);
                }
        }
    };

    const int NCH = Cc / 32;
    issue(0, 0);
    CP_COMMIT();
#pragma unroll 1
    for (int c = 0; c < NCH; c++) {
        if (c + 1 < NCH) {
            issue(c + 1, (c + 1) & 1);
            CP_COMMIT();
            CP_WAIT1();
        } else {
            CP_WAIT0();
        }
        __syncthreads();
        compute(c & 1);
        __syncthreads();
    }

    // epilogue
    int r4 = lane >> 2;
    int cp2 = (lane & 3) * 2;
    __half* dsth = (which == 0) ? g_qf : (which == 1) ? g_kf : g_vf;
#pragma unroll
    for (int ni = 0; ni < 4; ni++) {
        int n = n0 + warp_n * 32 + ni * 8 + cp2;
        float b0 = bias[n], b1 = bias[n + 1];
#pragma unroll
        for (int mi = 0; mi < 4; mi++) {
            int mA = m0 + warp_m * 64 + mi * 16 + r4;
            float v00 = acc[mi][ni][0] + b0, v01 = acc[mi][ni][1] + b1;
            float v10 = acc[mi][ni][2] + b0, v11 = acc[mi][ni][3] + b1;
            if (which == 3) {
                *reinterpret_cast<float2*>(&outflat[(size_t)mA * Cc + n]) = make_float2(v00, v01);
                *reinterpret_cast<float2*>(&outflat[(size_t)(mA + 8) * Cc + n]) = make_float2(v10, v11);
            } else {
                int h = n >> 6, d = n & 63;
                int b_ = mA >> 10, t = mA & 1023;
                size_t i0 = (((size_t)(b_ * Hh + h)) * Tn + t) * Dd + d;
                *reinterpret_cast<__half2*>(&dsth[i0]) = __floats2half2_rn(v00, v01);
                int m2 = mA + 8;
                int b2 = m2 >> 10, t2 = m2 & 1023;
                size_t i1 = (((size_t)(b2 * Hh + h)) * Tn + t2) * Dd + d;
                *reinterpret_cast<__half2*>(&dsth[i1]) = __floats2half2_rn(v10, v11);
            }
        }
    }
}

// ================= 3) scores via fp16 MMA (1 product): S = QK^T / 8, + masked exp partial sums =================
__global__ __launch_bounds__(128) void scores_mma() {
    int sblk = blockIdx.x, tblk = blockIdx.y, bh = blockIdx.z;
    if (sblk > tblk) return;
    __shared__ char smem[2 * 8192];   // Qf Kf (64 rows x 128B each)
    __shared__ float rowsum[64][2];
    uint32_t sb = smem_to_u32(smem);

    int tid = threadIdx.x, lane = tid & 31, wid = tid >> 5;
    int warp_m = wid & 1, warp_n = wid >> 1;
    int t0 = tblk * 64, s0 = sblk * 64;

    const __half* srcs[2] = {
        g_qf + ((size_t)bh * Tn + t0) * Dd,
        g_kf + ((size_t)bh * Tn + s0) * Dd };
#pragma unroll
    for (int a = 0; a < 2; a++) {
        const __half* s = srcs[a];
        for (int i = tid; i < 512; i += 128) {
            int row = i >> 3, ch = i & 7;
            uint32_t off = (uint32_t)(row * 128 + ((ch ^ (row & 7)) << 4));
            *reinterpret_cast<uint4*>(smem + a * 8192 + off) =
                *reinterpret_cast<const uint4*>(s + row * 64 + ch * 8);
        }
    }
    __syncthreads();

    int a_row = warp_m * 32 + ((lane >> 3) & 1) * 8 + (lane & 7);
    int a_ch  = lane >> 4;
    int b_row = warp_n * 32 + (lane & 7);
    int b_ch  = (lane >> 3) & 1;

    float acc[2][4][4];
#pragma unroll
    for (int mi = 0; mi < 2; mi++)
#pragma unroll
        for (int ni = 0; ni < 4; ni++)
#pragma unroll
            for (int j = 0; j < 4; j++) acc[mi][ni][j] = 0.f;

#pragma unroll
    for (int ks = 0; ks < 4; ks++) {
        uint32_t aF[2][4], bF[4][2];
#pragma unroll
        for (int mi = 0; mi < 2; mi++) {
            int r = a_row + mi * 16;
            uint32_t off = (uint32_t)(r * 128 + (((ks * 2 + a_ch) ^ (r & 7)) << 4));
            ldsm4(aF[mi], sb + off);
        }
#pragma unroll
        for (int ni = 0; ni < 4; ni++) {
            int r = b_row + ni * 8;
            uint32_t off = (uint32_t)(r * 128 + (((ks * 2 + b_ch) ^ (r & 7)) << 4));
            ldsm2(bF[ni], sb + 8192 + off);
        }
#pragma unroll
        for (int mi = 0; mi < 2; mi++)
#pragma unroll
            for (int ni = 0; ni < 4; ni++)
                mma16816h(acc[mi][ni], aF[mi], bF[ni]);
    }

    float* S = g_att + (size_t)bh * Tn * Tn;
    int r4 = lane >> 2, cp2 = (lane & 3) * 2;
    float esum[2][2] = {};
#pragma unroll
    for (int mi = 0; mi < 2; mi++) {
        int t = t0 + warp_m * 32 + mi * 16 + r4;
#pragma unroll
        for (int ni = 0; ni < 4; ni++) {
            int s = s0 + warp_n * 32 + ni * 8 + cp2;
            float v0 = acc[mi][ni][0] * 0.125f, v1 = acc[mi][ni][1] * 0.125f;
            float v2 = acc[mi][ni][2] * 0.125f, v3 = acc[mi][ni][3] * 0.125f;
            *reinterpret_cast<float2*>(&S[(size_t)t * Tn + s]) = make_float2(v0, v1);
            *reinterpret_cast<float2*>(&S[(size_t)(t + 8) * Tn + s]) = make_float2(v2, v3);
            esum[mi][0] += (s     <= t    ? __expf(v0) : 0.f) + (s + 1 <= t     ? __expf(v1) : 0.f);
            esum[mi][1] += (s     <= t + 8 ? __expf(v2) : 0.f) + (s + 1 <= t + 8 ? __expf(v3) : 0.f);
        }
    }
#pragma unroll
    for (int mi = 0; mi < 2; mi++)
#pragma unroll
        for (int hf = 0; hf < 2; hf++) {
            float v = esum[mi][hf];
            v += __shfl_xor_sync(0xffffffffu, v, 1);
            v += __shfl_xor_sync(0xffffffffu, v, 2);
            esum[mi][hf] = v;
        }
    if ((lane & 3) == 0) {
#pragma unroll
        for (int mi = 0; mi < 2; mi++)
#pragma unroll
            for (int hf = 0; hf < 2; hf++)
                rowsum[warp_m * 32 + mi * 16 + hf * 8 + r4][warp_n] = esum[mi][hf];
    }
    __syncthreads();
    if (tid < 64)
        g_psum[(((size_t)bh * Tn) + t0 + tid) * 16 + sblk] = rowsum[tid][0] + rowsum[tid][1];
}

// ---------------- 4) reduce partials -> 1/sum per row ----------------
__global__ __launch_bounds__(256) void reduce_inv_kernel() {
    int idx = blockIdx.x * blockDim.x + threadIdx.x;   // bh*Tn + t
    int t = idx & (Tn - 1);
    int nblk = (t >> 6) + 1;
    const float* p = g_psum + (size_t)idx * 16;
    float S = 0.f;
    for (int i = 0; i < nblk; i++) S += p[i];
    g_inv[idx] = 1.0f / S;
}

// ---------------- 5) apply exp*inv*tw + head mix -> fp16, causal-zeroed ----------------
__global__ __launch_bounds__(256) void mixapply_kernel(const float* __restrict__ tw,
                                                       const float* __restrict__ Mx) {
    int chunk = blockIdx.x, t = blockIdx.y, b = blockIdx.z;
    int s0 = chunk * 256;
    if (s0 > t) return;            // beyond causal: g_am stays 0 (never written)
    __shared__ float Ms[256];
    __shared__ float st[16];
    int tid = threadIdx.x;
    Ms[tid] = Mx[tid];
    if (tid < 16) st[tid] = g_inv[((size_t)(b * Hh + tid)) * Tn + t];
    __syncthreads();

    int s = s0 + tid;
    bool valid = s <= t;
    float vals[16];
#pragma unroll
    for (int h = 0; h < Hh; h++) {
        float x = g_att[(((size_t)(b * Hh + h)) * Tn + t) * Tn + s];
        float w = tw[(((size_t)h * Tn) + t) * Tn + s];
        vals[h] = valid ? __expf(x) * st[h] * w : 0.f;
    }
#pragma unroll
    for (int o = 0; o < Hh; o++) {
        float a = 0.f;
#pragma unroll
        for (int h = 0; h < Hh; h++) a = fmaf(Ms[o * 16 + h], vals[h], a);
        g_am[(((size_t)(b * Hh + o)) * Tn + t) * Tn + s] = __float2half_rn(a);
    }
}

// ================= 6) AV via fp16 MMA (att x V, 1 product), 3-stage cp.async =================
#define AV_STAGE 16384
#define AV_SMEM (3 * AV_STAGE)
__global__ __launch_bounds__(256) void av_mma() {
    int tblk = blockIdx.x, bo = blockIdx.y;
    int b = bo >> 4, o = bo & 15;
    int t0 = tblk * 64;
    extern __shared__ char smem[];
    uint32_t sbase = smem_to_u32(smem);

    int tid = threadIdx.x, lane = tid & 31, wid = tid >> 5;
    int warp_m = wid & 3, warp_n = wid >> 2;   // 4 x 2 warp grid, warp tile 16(t) x 32(d)

    int a_row = warp_m * 16 + ((lane >> 3) & 1) * 8 + (lane & 7);
    int a_ch  = lane >> 4;
    int v_lrow = ((lane >> 3) & 1) * 8 + (lane & 7);

    float acc[4][4];
#pragma unroll
    for (int ni = 0; ni < 4; ni++)
#pragma unroll
        for (int j = 0; j < 4; j++) acc[ni][j] = 0.f;

    const __half* Am = g_am + ((size_t)bo * Tn + t0) * Tn;
    const __half* Vf = g_vf + (size_t)bo * Tn * Dd;

    auto issue = [&](int st, int stage) {
        int s0 = st * 64;
        uint32_t sb = sbase + (uint32_t)stage * AV_STAGE;
#pragma unroll
        for (int j = 0; j < 2; j++) {
            int i = tid + j * 256;
            int row = i >> 3, ch = i & 7;
            uint32_t off = (uint32_t)(row * 128 + ((ch ^ (row & 7)) << 4));
            CP16(sb + off,        Am + (size_t)row * Tn + s0 + ch * 8);
            CP16(sb + 8192 + off, Vf + (size_t)(s0 + row) * Dd + ch * 8);
        }
    };

    auto compute = [&](int stage) {
        uint32_t sb = sbase + (uint32_t)stage * AV_STAGE;
#pragma unroll
        for (int ks = 0; ks < 4; ks++) {
            uint32_t aF[4], bF[4][2];
            {
                int r = a_row;
                uint32_t off = (uint32_t)(r * 128 + (((ks * 2 + a_ch) ^ (r & 7)) << 4));
                ldsm4(aF, sb + off);
            }
            int vrow = ks * 16 + v_lrow;
#pragma unroll
            for (int ni = 0; ni < 4; ni++) {
                int dch = warp_n * 4 + ni;
                uint32_t off = (uint32_t)(vrow * 128 + ((dch ^ (vrow & 7)) << 4));
                ldsm2t(bF[ni], sb + 8192 + off);
            }
#pragma unroll
            for (int ni = 0; ni < 4; ni++)
                mma16816h(acc[ni], aF, bF[ni]);
        }
    };

    int nStages = tblk + 1;
    issue(0, 0);
    CP_COMMIT();
    if (nStages > 1) issue(1, 1);
    CP_COMMIT();
#pragma unroll 1
    for (int st = 0; st < nStages; st++) {
        CP_WAIT1();
        __syncthreads();
        compute(st % 3);
        if (st + 2 < nStages) issue(st + 2, (st + 2) % 3);
        CP_COMMIT();
    }

    int r4 = lane >> 2, cp2 = (lane & 3) * 2;
#pragma unroll
    for (int ni = 0; ni < 4; ni++) {
        int d = warp_n * 32 + ni * 8 + cp2;
        int t = t0 + warp_m * 16 + r4;
        size_t i0 = ((size_t)(b * Tn + t)) * Cc + o * 64 + d;
        *reinterpret_cast<__half2*>(&g_y_f[i0]) = __floats2half2_rn(acc[ni][0], acc[ni][1]);
        size_t i1 = ((size_t)(b * Tn + t + 8)) * Cc + o * 64 + d;
        *reinterpret_cast<__half2*>(&g_y_f[i1]) = __floats2half2_rn(acc[ni][2], acc[ni][3]);
    }
}

// ---------------- host launch ----------------
extern "C" void kernel_launch(void* const* d_in, const int* in_sizes, int n_in,
                              void* d_out, int out_size) {
    const float* x  = (const float*)d_in[0];
    const float* Wq = (const float*)d_in[1];
    const float* bq = (const float*)d_in[2];
    const float* Wk = (const float*)d_in[3];
    const float* bk = (const float*)d_in[4];
    const float* Wv = (const float*)d_in[5];
    const float* bv = (const float*)d_in[6];
    const float* tw = (const float*)d_in[7];
    const float* hm = (const float*)d_in[8];
    const float* Wp = (const float*)d_in[9];
    const float* bp = (const float*)d_in[10];
    float* out = (float*)d_out;

    static cudaStream_t s2 = nullptr, s3 = nullptr;
    static cudaEvent_t evFork = nullptr, evTS = nullptr, evCW = nullptr,
                       evK = nullptr, evV = nullptr;
    if (!s2) {
        cudaFuncSetAttribute(proj_gemm_f16, cudaFuncAttributeMaxDynamicSharedMemorySize, PROJF_SMEM);
        cudaFuncSetAttribute(av_mma, cudaFuncAttributeMaxDynamicSharedMemorySize, AV_SMEM);
        cudaStreamCreateWithFlags(&s2, cudaStreamNonBlocking);
        cudaStreamCreateWithFlags(&s3, cudaStreamNonBlocking);
        cudaEventCreateWithFlags(&evFork, cudaEventDisableTiming);
        cudaEventCreateWithFlags(&evTS, cudaEventDisableTiming);
        cudaEventCreateWithFlags(&evCW, cudaEventDisableTiming);
        cudaEventCreateWithFlags(&evK, cudaEventDisableTiming);
        cudaEventCreateWithFlags(&evV, cudaEventDisableTiming);
    }

    dim3 gproj(Cc / 128, (Bb * Tn) / 128);

    // FORK: non-origin streams join the capture via an origin-stream event first.
    cudaEventRecord(evFork, 0);
    cudaStreamWaitEvent(s2, evFork, 0);
    cudaStreamWaitEvent(s3, evFork, 0);

    // s0: timeshift ; s2: weight conversion (all four, fp16 hi/lo)
    timeshift_kernel<<<(Bb * Tn * Cc) / 256, 256>>>(x);
    cudaEventRecord(evTS, 0);
    convert_wf_kernel<<<(4 * Cc * Cc) / 256, 256, 0, s2>>>(Wq, Wk, Wv, Wp);
    cudaEventRecord(evCW, s2);

    // q on s0
    cudaStreamWaitEvent(0, evCW, 0);
    proj_gemm_f16<<<gproj, 256, PROJF_SMEM>>>(bq, nullptr, 0);

    // k on s3 (needs ts + cw)
    cudaStreamWaitEvent(s3, evTS, 0);
    cudaStreamWaitEvent(s3, evCW, 0);
    proj_gemm_f16<<<gproj, 256, PROJF_SMEM, s3>>>(bk, nullptr, 1);
    cudaEventRecord(evK, s3);

    // v on s2 (needs ts; cw in program order on s2)
    cudaStreamWaitEvent(s2, evTS, 0);
    proj_gemm_f16<<<gproj, 256, PROJF_SMEM, s2>>>(bv, nullptr, 2);
    cudaEventRecord(evV, s2);

    // scores chain on s0 (needs q [program order] + k [event])
    cudaStreamWaitEvent(0, evK, 0);
    dim3 gs(Tn / 64, Tn / 64, Bb * Hh);
    scores_mma<<<gs, 128>>>();

    reduce_inv_kernel<<<(Bb * Hh * Tn) / 256, 256>>>();

    dim3 gmx(Tn / 256, Tn, Bb);
    mixapply_kernel<<<gmx, 256>>>(tw, hm);

    cudaStreamWaitEvent(0, evV, 0);
    dim3 gav(Tn / 64, Bb * Hh);
    av_mma<<<gav, 256, AV_SMEM>>>();

    proj_gemm_f16<<<gproj, 256, PROJF_SMEM>>>(bp, out, 3);
}

// round 17
// speedup vs baseline: 4.8754x; 1.0600x over previous
#include <cuda_runtime.h>
#include <cuda_fp16.h>
#include <math.h>
#include <cstdint>

#define Bb 4
#define Tn 1024
#define Cc 1024
#define Hh 16
#define Dd 64
#define NELEM ((size_t)Bb * Tn * Cc)   // 4M
#define EXPSCALE 0.00390625f           // 2^-8
#define EXPUNSCALE 256.0f

// ---------------- scratch (device globals) ----------------
__device__ __half g_ex[(size_t)Bb * Hh * Tn * Tn];   // exp(S)*2^-8 fp16 (causal blocks)
__device__ float g_psum[(size_t)Bb * Hh * Tn * 16];  // per-(row, sblk) exp partial sums (fp32 exact)
__device__ float g_inv[(size_t)Bb * Hh * Tn];        // per-row 1/sum
__device__ __half g_am[(size_t)Bb * Hh * Tn * Tn];   // mixed att fp16 (causal-zeroed)

__device__ __half g_xs_f[NELEM];                     // time-shifted input fp16
__device__ __half g_y_f[NELEM];                      // AV output [B,T,C] fp16
__device__ __half g_wfh[4 * (size_t)Cc * Cc];        // weights q,k,v,p fp16 hi
__device__ __half g_wfl[4 * (size_t)Cc * Cc];        // weights q,k,v,p fp16 lo

__device__ __half g_qf[(size_t)Bb * Hh * Tn * Dd];   // [bh][t][d] fp16
__device__ __half g_kf[(size_t)Bb * Hh * Tn * Dd];
__device__ __half g_vf[(size_t)Bb * Hh * Tn * Dd];

// ================= helpers =================
__device__ __forceinline__ uint32_t smem_to_u32(const void* p) {
    uint32_t a;
    asm("{ .reg .u64 t; cvta.to.shared.u64 t, %1; cvt.u32.u64 %0, t; }" : "=r"(a) : "l"(p));
    return a;
}
#define CP16(dst, src) \
    asm volatile("cp.async.cg.shared.global [%0], [%1], 16;" :: "r"(dst), "l"(src) : "memory")
#define CP_COMMIT() asm volatile("cp.async.commit_group;" ::: "memory")
#define CP_WAIT0() asm volatile("cp.async.wait_group 0;" ::: "memory")
#define CP_WAIT1() asm volatile("cp.async.wait_group 1;" ::: "memory")

__device__ __forceinline__ void ldsm4(uint32_t* r, uint32_t addr) {
    asm volatile("ldmatrix.sync.aligned.m8n8.x4.shared.b16 {%0,%1,%2,%3}, [%4];"
                 : "=r"(r[0]), "=r"(r[1]), "=r"(r[2]), "=r"(r[3]) : "r"(addr));
}
__device__ __forceinline__ void ldsm2(uint32_t* r, uint32_t addr) {
    asm volatile("ldmatrix.sync.aligned.m8n8.x2.shared.b16 {%0,%1}, [%2];"
                 : "=r"(r[0]), "=r"(r[1]) : "r"(addr));
}
__device__ __forceinline__ void ldsm2t(uint32_t* r, uint32_t addr) {
    asm volatile("ldmatrix.sync.aligned.m8n8.x2.trans.shared.b16 {%0,%1}, [%2];"
                 : "=r"(r[0]), "=r"(r[1]) : "r"(addr));
}
__device__ __forceinline__ void mma16816h(float* c, const uint32_t* a, const uint32_t* b) {
    asm volatile("mma.sync.aligned.m16n8k16.row.col.f32.f16.f16.f32 "
                 "{%0,%1,%2,%3}, {%4,%5,%6,%7}, {%8,%9}, {%0,%1,%2,%3};"
                 : "+f"(c[0]), "+f"(c[1]), "+f"(c[2]), "+f"(c[3])
                 : "r"(a[0]), "r"(a[1]), "r"(a[2]), "r"(a[3]), "r"(b[0]), "r"(b[1]));
}
__device__ __forceinline__ void split_store_h(__half* ph, __half* pl, size_t idx, float v) {
    __half h = __float2half_rn(v);
    ph[idx] = h;
    pl[idx] = __float2half_rn(v - __half2float(h));
}

// ---------------- 1) time shift -> fp16 ----------------
__global__ __launch_bounds__(256) void timeshift_kernel(const float* __restrict__ x) {
    int idx = blockIdx.x * blockDim.x + threadIdx.x;
    int c = idx & (Cc - 1);
    int t = (idx >> 10) & (Tn - 1);
    int b = idx >> 20;
    float val;
    if (c < Cc / 2) {
        val = (t == 0) ? 0.f : x[((size_t)b * Tn + (t - 1)) * Cc + c];
    } else {
        val = x[((size_t)b * Tn + t) * Cc + c];
    }
    g_xs_f[idx] = __float2half_rn(val);
}

// ---------------- 1b) weight conversion: q,k,v,p -> fp16 hi/lo ----------------
__global__ __launch_bounds__(256) void convert_wf_kernel(const float* __restrict__ Wq,
                                                         const float* __restrict__ Wk,
                                                         const float* __restrict__ Wv,
                                                         const float* __restrict__ Wp) {
    size_t idx = (size_t)blockIdx.x * blockDim.x + threadIdx.x;
    int which = (int)(idx >> 20);
    size_t off = idx & ((size_t)Cc * Cc - 1);
    const float* W = (which == 0) ? Wq : (which == 1) ? Wk : (which == 2) ? Wv : Wp;
    split_store_h(g_wfh, g_wfl, idx, W[off]);
}

// ================= 2) fp16 projection GEMM: A fp16 x W fp16-hi/lo, 2 products, 3-stage =================
// which: 0=q, 1=k, 2=v, 3=out
#define STAGE_F16 24576
#define PROJF_SMEM (3 * STAGE_F16)   // 72KB: still 2 CTAs/SM

__global__ __launch_bounds__(256) void proj_gemm_f16(const float* __restrict__ bias,
                                                     float* __restrict__ outflat, int which) {
    extern __shared__ char smem[];
    uint32_t sbase = smem_to_u32(smem);
    const __half* gA  = (which == 3) ? g_y_f : g_xs_f;
    const __half* gWh = g_wfh + (size_t)which * Cc * Cc;
    const __half* gWl = g_wfl + (size_t)which * Cc * Cc;

    int tid = threadIdx.x, lane = tid & 31, wid = tid >> 5;
    int warp_m = wid & 1, warp_n = wid >> 1;
    int m0 = blockIdx.y * 128, n0 = blockIdx.x * 128;

    int rtid = tid >> 2;
    int ctid = tid & 3;

    int a_row_off = (lane & 7) + ((lane >> 3) & 1) * 8;
    int a_chunk = lane >> 4;
    int b_row_off = lane & 7;
    int b_chunk = (lane >> 3) & 1;

    uint32_t aBase[4], aSw[4], bBase[4], bSw[4];
#pragma unroll
    for (int mi = 0; mi < 4; mi++) {
        int r = warp_m * 64 + mi * 16 + a_row_off;
        aBase[mi] = (uint32_t)(r * 64);
        aSw[mi] = (uint32_t)((r >> 1) & 3);
    }
#pragma unroll
    for (int ni = 0; ni < 4; ni++) {
        int r = warp_n * 32 + ni * 8 + b_row_off;
        bBase[ni] = (uint32_t)(r * 64);
        bSw[ni] = (uint32_t)((r >> 1) & 3);
    }

    float acc[4][4][4];
#pragma unroll
    for (int mi = 0; mi < 4; mi++)
#pragma unroll
        for (int ni = 0; ni < 4; ni++)
#pragma unroll
            for (int j = 0; j < 4; j++) acc[mi][ni][j] = 0.f;

    auto issue = [&](int chunk, int stage) {
        int k0 = chunk * 32;
        uint32_t sb = sbase + (uint32_t)stage * STAGE_F16;
#pragma unroll
        for (int j = 0; j < 2; j++) {
            int row = rtid + j * 64;
            uint32_t dof = (uint32_t)(row * 64 + ((ctid ^ ((row >> 1) & 3)) << 4));
            size_t ga = (size_t)(m0 + row) * Cc + k0 + ctid * 8;
            size_t gw = (size_t)(n0 + row) * Cc + k0 + ctid * 8;
            CP16(sb + dof,         gA  + ga);
            CP16(sb + 8192 + dof,  gWh + gw);
            CP16(sb + 16384 + dof, gWl + gw);
        }
    };

    auto compute = [&](int stage) {
        uint32_t sb = sbase + (uint32_t)stage * STAGE_F16;
#pragma unroll
        for (int ks = 0; ks < 2; ks++) {
            uint32_t aF[4][4], bH[4][2], bL[4][2];
#pragma unroll
            for (int mi = 0; mi < 4; mi++) {
                uint32_t off = aBase[mi] + ((((uint32_t)(ks * 2) + a_chunk) ^ aSw[mi]) << 4);
                ldsm4(aF[mi], sb + off);
            }
#pragma unroll
            for (int ni = 0; ni < 4; ni++) {
                uint32_t off = bBase[ni] + ((((uint32_t)(ks * 2) + b_chunk) ^ bSw[ni]) << 4);
                ldsm2(bH[ni], sb + 8192 + off);
                ldsm2(bL[ni], sb + 16384 + off);
            }
#pragma unroll
            for (int mi = 0; mi < 4; mi++)
#pragma unroll
                for (int ni = 0; ni < 4; ni++) {
                    mma16816h(acc[mi][ni], aF[mi], bH[ni]);
                    mma16816h(acc[mi][ni], aF[mi], bL[ni]);
                }
        }
    };

    const int NCH = Cc / 32;
    issue(0, 0);
    CP_COMMIT();
    issue(1, 1);
    CP_COMMIT();
#pragma unroll 1
    for (int c = 0; c < NCH; c++) {
        CP_WAIT1();                 // oldest of the 2 pending groups done -> stage c ready
        __syncthreads();
        compute(c % 3);
        if (c + 2 < NCH) issue(c + 2, (c + 2) % 3);
        CP_COMMIT();                // unconditional: keeps group indexing positional
    }

    // epilogue
    int r4 = lane >> 2;
    int cp2 = (lane & 3) * 2;
    __half* dsth = (which == 0) ? g_qf : (which == 1) ? g_kf : g_vf;
#pragma unroll
    for (int ni = 0; ni < 4; ni++) {
        int n = n0 + warp_n * 32 + ni * 8 + cp2;
        float b0 = bias[n], b1 = bias[n + 1];
#pragma unroll
        for (int mi = 0; mi < 4; mi++) {
            int mA = m0 + warp_m * 64 + mi * 16 + r4;
            float v00 = acc[mi][ni][0] + b0, v01 = acc[mi][ni][1] + b1;
            float v10 = acc[mi][ni][2] + b0, v11 = acc[mi][ni][3] + b1;
            if (which == 3) {
                *reinterpret_cast<float2*>(&outflat[(size_t)mA * Cc + n]) = make_float2(v00, v01);
                *reinterpret_cast<float2*>(&outflat[(size_t)(mA + 8) * Cc + n]) = make_float2(v10, v11);
            } else {
                int h = n >> 6, d = n & 63;
                int b_ = mA >> 10, t = mA & 1023;
                size_t i0 = (((size_t)(b_ * Hh + h)) * Tn + t) * Dd + d;
                *reinterpret_cast<__half2*>(&dsth[i0]) = __floats2half2_rn(v00, v01);
                int m2 = mA + 8;
                int b2 = m2 >> 10, t2 = m2 & 1023;
                size_t i1 = (((size_t)(b2 * Hh + h)) * Tn + t2) * Dd + d;
                *reinterpret_cast<__half2*>(&dsth[i1]) = __floats2half2_rn(v10, v11);
            }
        }
    }
}

// ================= 3) scores via fp16 MMA: store exp(S)*2^-8 fp16, + masked fp32 exp partial sums =================
__global__ __launch_bounds__(128) void scores_mma() {
    int sblk = blockIdx.x, tblk = blockIdx.y, bh = blockIdx.z;
    if (sblk > tblk) return;
    __shared__ char smem[2 * 8192];   // Qf Kf (64 rows x 128B each)
    __shared__ float rowsum[64][2];
    uint32_t sb = smem_to_u32(smem);

    int tid = threadIdx.x, lane = tid & 31, wid = tid >> 5;
    int warp_m = wid & 1, warp_n = wid >> 1;
    int t0 = tblk * 64, s0 = sblk * 64;

    const __half* srcs[2] = {
        g_qf + ((size_t)bh * Tn + t0) * Dd,
        g_kf + ((size_t)bh * Tn + s0) * Dd };
#pragma unroll
    for (int a = 0; a < 2; a++) {
        const __half* s = srcs[a];
        for (int i = tid; i < 512; i += 128) {
            int row = i >> 3, ch = i & 7;
            uint32_t off = (uint32_t)(row * 128 + ((ch ^ (row & 7)) << 4));
            *reinterpret_cast<uint4*>(smem + a * 8192 + off) =
                *reinterpret_cast<const uint4*>(s + row * 64 + ch * 8);
        }
    }
    __syncthreads();

    int a_row = warp_m * 32 + ((lane >> 3) & 1) * 8 + (lane & 7);
    int a_ch  = lane >> 4;
    int b_row = warp_n * 32 + (lane & 7);
    int b_ch  = (lane >> 3) & 1;

    float acc[2][4][4];
#pragma unroll
    for (int mi = 0; mi < 2; mi++)
#pragma unroll
        for (int ni = 0; ni < 4; ni++)
#pragma unroll
            for (int j = 0; j < 4; j++) acc[mi][ni][j] = 0.f;

#pragma unroll
    for (int ks = 0; ks < 4; ks++) {
        uint32_t aF[2][4], bF[4][2];
#pragma unroll
        for (int mi = 0; mi < 2; mi++) {
            int r = a_row + mi * 16;
            uint32_t off = (uint32_t)(r * 128 + (((ks * 2 + a_ch) ^ (r & 7)) << 4));
            ldsm4(aF[mi], sb + off);
        }
#pragma unroll
        for (int ni = 0; ni < 4; ni++) {
            int r = b_row + ni * 8;
            uint32_t off = (uint32_t)(r * 128 + (((ks * 2 + b_ch) ^ (r & 7)) << 4));
            ldsm2(bF[ni], sb + 8192 + off);
        }
#pragma unroll
        for (int mi = 0; mi < 2; mi++)
#pragma unroll
            for (int ni = 0; ni < 4; ni++)
                mma16816h(acc[mi][ni], aF[mi], bF[ni]);
    }

    __half* E = g_ex + (size_t)bh * Tn * Tn;
    int r4 = lane >> 2, cp2 = (lane & 3) * 2;
    float esum[2][2] = {};
#pragma unroll
    for (int mi = 0; mi < 2; mi++) {
        int t = t0 + warp_m * 32 + mi * 16 + r4;
#pragma unroll
        for (int ni = 0; ni < 4; ni++) {
            int s = s0 + warp_n * 32 + ni * 8 + cp2;
            float e0 = __expf(acc[mi][ni][0] * 0.125f);
            float e1 = __expf(acc[mi][ni][1] * 0.125f);
            float e2 = __expf(acc[mi][ni][2] * 0.125f);
            float e3 = __expf(acc[mi][ni][3] * 0.125f);
            *reinterpret_cast<__half2*>(&E[(size_t)t * Tn + s]) =
                __floats2half2_rn(e0 * EXPSCALE, e1 * EXPSCALE);
            *reinterpret_cast<__half2*>(&E[(size_t)(t + 8) * Tn + s]) =
                __floats2half2_rn(e2 * EXPSCALE, e3 * EXPSCALE);
            esum[mi][0] += (s     <= t     ? e0 : 0.f) + (s + 1 <= t     ? e1 : 0.f);
            esum[mi][1] += (s     <= t + 8 ? e2 : 0.f) + (s + 1 <= t + 8 ? e3 : 0.f);
        }
    }
#pragma unroll
    for (int mi = 0; mi < 2; mi++)
#pragma unroll
        for (int hf = 0; hf < 2; hf++) {
            float v = esum[mi][hf];
            v += __shfl_xor_sync(0xffffffffu, v, 1);
            v += __shfl_xor_sync(0xffffffffu, v, 2);
            esum[mi][hf] = v;
        }
    if ((lane & 3) == 0) {
#pragma unroll
        for (int mi = 0; mi < 2; mi++)
#pragma unroll
            for (int hf = 0; hf < 2; hf++)
                rowsum[warp_m * 32 + mi * 16 + hf * 8 + r4][warp_n] = esum[mi][hf];
    }
    __syncthreads();
    if (tid < 64)
        g_psum[(((size_t)bh * Tn) + t0 + tid) * 16 + sblk] = rowsum[tid][0] + rowsum[tid][1];
}

// ---------------- 4) reduce partials -> 1/sum per row ----------------
__global__ __launch_bounds__(256) void reduce_inv_kernel() {
    int idx = blockIdx.x * blockDim.x + threadIdx.x;   // bh*Tn + t
    int t = idx & (Tn - 1);
    int nblk = (t >> 6) + 1;
    const float* p = g_psum + (size_t)idx * 16;
    float S = 0.f;
    for (int i = 0; i < nblk; i++) S += p[i];
    g_inv[idx] = 1.0f / S;
}

// ---------------- 5) apply scaled-exp * inv * tw + head mix -> fp16, causal-zeroed ----------------
__global__ __launch_bounds__(256) void mixapply_kernel(const float* __restrict__ tw,
                                                       const float* __restrict__ Mx) {
    int chunk = blockIdx.x, t = blockIdx.y, b = blockIdx.z;
    int s0 = chunk * 256;
    if (s0 > t) return;            // beyond causal: g_am stays 0 (never written)
    __shared__ float Ms[256];
    __shared__ float st[16];
    int tid = threadIdx.x;
    Ms[tid] = Mx[tid];
    if (tid < 16) st[tid] = g_inv[((size_t)(b * Hh + tid)) * Tn + t] * EXPUNSCALE;
    __syncthreads();

    int s = s0 + tid;
    bool valid = s <= t;
    float vals[16];
#pragma unroll
    for (int h = 0; h < Hh; h++) {
        float x = __half2float(g_ex[(((size_t)(b * Hh + h)) * Tn + t) * Tn + s]);
        float w = tw[(((size_t)h * Tn) + t) * Tn + s];
        vals[h] = valid ? x * st[h] * w : 0.f;
    }
#pragma unroll
    for (int o = 0; o < Hh; o++) {
        float a = 0.f;
#pragma unroll
        for (int h = 0; h < Hh; h++) a = fmaf(Ms[o * 16 + h], vals[h], a);
        g_am[(((size_t)(b * Hh + o)) * Tn + t) * Tn + s] = __float2half_rn(a);
    }
}

// ================= 6) AV via fp16 MMA (att x V, 1 product), 3-stage cp.async =================
#define AV_STAGE 16384
#define AV_SMEM (3 * AV_STAGE)
__global__ __launch_bounds__(256) void av_mma() {
    int tblk = blockIdx.x, bo = blockIdx.y;
    int b = bo >> 4, o = bo & 15;
    int t0 = tblk * 64;
    extern __shared__ char smem[];
    uint32_t sbase = smem_to_u32(smem);

    int tid = threadIdx.x, lane = tid & 31, wid = tid >> 5;
    int warp_m = wid & 3, warp_n = wid >> 2;   // 4 x 2 warp grid, warp tile 16(t) x 32(d)

    int a_row = warp_m * 16 + ((lane >> 3) & 1) * 8 + (lane & 7);
    int a_ch  = lane >> 4;
    int v_lrow = ((lane >> 3) & 1) * 8 + (lane & 7);

    float acc[4][4];
#pragma unroll
    for (int ni = 0; ni < 4; ni++)
#pragma unroll
        for (int j = 0; j < 4; j++) acc[ni][j] = 0.f;

    const __half* Am = g_am + ((size_t)bo * Tn + t0) * Tn;
    const __half* Vf = g_vf + (size_t)bo * Tn * Dd;

    auto issue = [&](int st, int stage) {
        int s0 = st * 64;
        uint32_t sb = sbase + (uint32_t)stage * AV_STAGE;
#pragma unroll
        for (int j = 0; j < 2; j++) {
            int i = tid + j * 256;
            int row = i >> 3, ch = i & 7;
            uint32_t off = (uint32_t)(row * 128 + ((ch ^ (row & 7)) << 4));
            CP16(sb + off,        Am + (size_t)row * Tn + s0 + ch * 8);
            CP16(sb + 8192 + off, Vf + (size_t)(s0 + row) * Dd + ch * 8);
        }
    };

    auto compute = [&](int stage) {
        uint32_t sb = sbase + (uint32_t)stage * AV_STAGE;
#pragma unroll
        for (int ks = 0; ks < 4; ks++) {
            uint32_t aF[4], bF[4][2];
            {
                int r = a_row;
                uint32_t off = (uint32_t)(r * 128 + (((ks * 2 + a_ch) ^ (r & 7)) << 4));
                ldsm4(aF, sb + off);
            }
            int vrow = ks * 16 + v_lrow;
#pragma unroll
            for (int ni = 0; ni < 4; ni++) {
                int dch = warp_n * 4 + ni;
                uint32_t off = (uint32_t)(vrow * 128 + ((dch ^ (vrow & 7)) << 4));
                ldsm2t(bF[ni], sb + 8192 + off);
            }
#pragma unroll
            for (int ni = 0; ni < 4; ni++)
                mma16816h(acc[ni], aF, bF[ni]);
        }
    };

    int nStages = tblk + 1;
    issue(0, 0);
    CP_COMMIT();
    if (nStages > 1) issue(1, 1);
    CP_COMMIT();
#pragma unroll 1
    for (int st = 0; st < nStages; st++) {
        CP_WAIT1();
        __syncthreads();
        compute(st % 3);
        if (st + 2 < nStages) issue(st + 2, (st + 2) % 3);
        CP_COMMIT();
    }

    int r4 = lane >> 2, cp2 = (lane & 3) * 2;
#pragma unroll
    for (int ni = 0; ni < 4; ni++) {
        int d = warp_n * 32 + ni * 8 + cp2;
        int t = t0 + warp_m * 16 + r4;
        size_t i0 = ((size_t)(b * Tn + t)) * Cc + o * 64 + d;
        *reinterpret_cast<__half2*>(&g_y_f[i0]) = __floats2half2_rn(acc[ni][0], acc[ni][1]);
        size_t i1 = ((size_t)(b * Tn + t + 8)) * Cc + o * 64 + d;
        *reinterpret_cast<__half2*>(&g_y_f[i1]) = __floats2half2_rn(acc[ni][2], acc[ni][3]);
    }
}

// ---------------- host launch ----------------
extern "C" void kernel_launch(void* const* d_in, const int* in_sizes, int n_in,
                              void* d_out, int out_size) {
    const float* x  = (const float*)d_in[0];
    const float* Wq = (const float*)d_in[1];
    const float* bq = (const float*)d_in[2];
    const float* Wk = (const float*)d_in[3];
    const float* bk = (const float*)d_in[4];
    const float* Wv = (const float*)d_in[5];
    const float* bv = (const float*)d_in[6];
    const float* tw = (const float*)d_in[7];
    const float* hm = (const float*)d_in[8];
    const float* Wp = (const float*)d_in[9];
    const float* bp = (const float*)d_in[10];
    float* out = (float*)d_out;

    static cudaStream_t s2 = nullptr, s3 = nullptr;
    static cudaEvent_t evFork = nullptr, evTS = nullptr, evCW = nullptr,
                       evK = nullptr, evV = nullptr;
    if (!s2) {
        cudaFuncSetAttribute(proj_gemm_f16, cudaFuncAttributeMaxDynamicSharedMemorySize, PROJF_SMEM);
        cudaFuncSetAttribute(av_mma, cudaFuncAttributeMaxDynamicSharedMemorySize, AV_SMEM);
        cudaStreamCreateWithFlags(&s2, cudaStreamNonBlocking);
        cudaStreamCreateWithFlags(&s3, cudaStreamNonBlocking);
        cudaEventCreateWithFlags(&evFork, cudaEventDisableTiming);
        cudaEventCreateWithFlags(&evTS, cudaEventDisableTiming);
        cudaEventCreateWithFlags(&evCW, cudaEventDisableTiming);
        cudaEventCreateWithFlags(&evK, cudaEventDisableTiming);
        cudaEventCreateWithFlags(&evV, cudaEventDisableTiming);
    }

    dim3 gproj(Cc / 128, (Bb * Tn) / 128);

    // FORK: non-origin streams join the capture via an origin-stream event first.
    cudaEventRecord(evFork, 0);
    cudaStreamWaitEvent(s2, evFork, 0);
    cudaStreamWaitEvent(s3, evFork, 0);

    // s0: timeshift ; s2: weight conversion (all four, fp16 hi/lo)
    timeshift_kernel<<<(Bb * Tn * Cc) / 256, 256>>>(x);
    cudaEventRecord(evTS, 0);
    convert_wf_kernel<<<(4 * Cc * Cc) / 256, 256, 0, s2>>>(Wq, Wk, Wv, Wp);
    cudaEventRecord(evCW, s2);

    // q on s0
    cudaStreamWaitEvent(0, evCW, 0);
    proj_gemm_f16<<<gproj, 256, PROJF_SMEM>>>(bq, nullptr, 0);

    // k on s3 (needs ts + cw)
    cudaStreamWaitEvent(s3, evTS, 0);
    cudaStreamWaitEvent(s3, evCW, 0);
    proj_gemm_f16<<<gproj, 256, PROJF_SMEM, s3>>>(bk, nullptr, 1);
    cudaEventRecord(evK, s3);

    // v on s2 (needs ts; cw in program order on s2)
    cudaStreamWaitEvent(s2, evTS, 0);
    proj_gemm_f16<<<gproj, 256, PROJF_SMEM, s2>>>(bv, nullptr, 2);
    cudaEventRecord(evV, s2);

    // scores chain on s0 (needs q [program order] + k [event])
    cudaStreamWaitEvent(0, evK, 0);
    dim3 gs(Tn / 64, Tn / 64, Bb * Hh);
    scores_mma<<<gs, 128>>>();

    reduce_inv_kernel<<<(Bb * Hh * Tn) / 256, 256>>>();

    dim3 gmx(Tn / 256, Tn, Bb);
    mixapply_kernel<<<gmx, 256>>>(tw, hm);

    cudaStreamWaitEvent(0, evV, 0);
    dim3 gav(Tn / 64, Bb * Hh);
    av_mma<<<gav, 256, AV_SMEM>>>();

    proj_gemm_f16<<<gproj, 256, PROJF_SMEM>>>(bp, out, 3);
}